// round 1
// baseline (speedup 1.0000x reference)
#include <cuda_runtime.h>

#define BB 4
#define CC 256
#define HH 64
#define WWID 64
#define OO 256
#define HWW 4096
#define NN 16384          // BB*HWW
#define CKK 2304          // CC*9
#define EPSB 1e-5f

// ---------------- scratch (device globals; no allocs allowed) ----------------
__device__ float g_offset[BB * 18 * HWW];              // 4.7 MB
__device__ float g_col[(size_t)CKK * NN];              // 151 MB
__device__ float g_out1[(size_t)OO * NN];              // 16.8 MB  [o][b*HW+hw]
__device__ float g_out2[(size_t)OO * NN];              // 16.8 MB
__device__ float g_scale1[OO], g_shift1[OO], g_scale2[OO], g_shift2[OO];

// ---------------- zero g_offset (atomicAdd accumulation target) -------------
__global__ void k_zero_offset() {
    int i = blockIdx.x * 256 + threadIdx.x;
    if (i < BB * 18 * HWW) g_offset[i] = 0.f;
}

// ---------------- offset conv: 3x3, dil=2, pad=2, 256->18 -------------------
// grid (64, 4): x = pixel blocks (16384 threads total), y = channel chunk of 64.
__global__ __launch_bounds__(256)
void k_offset_conv(const float* __restrict__ x, const float* __restrict__ off_w,
                   const float* __restrict__ off_b) {
    __shared__ float sw[18 * 64 * 9];          // 41.4 KB weight slice
    int c0 = blockIdx.y * 64;
    for (int idx = threadIdx.x; idx < 18 * 64 * 9; idx += 256) {
        int oc = idx / 576;
        int rem = idx - oc * 576;              // cc*9 + k
        sw[idx] = off_w[oc * CKK + c0 * 9 + rem];
    }
    __syncthreads();

    int n = blockIdx.x * 256 + threadIdx.x;
    int b = n >> 12, hw = n & 4095;
    int h = hw >> 6, w = hw & 63;

    float acc[18];
#pragma unroll
    for (int oc = 0; oc < 18; oc++) acc[oc] = 0.f;

    const float* xb = x + ((size_t)b * CC + c0) * HWW;
    for (int cc = 0; cc < 64; cc++) {
        const float* xc = xb + cc * HWW;
#pragma unroll
        for (int i = 0; i < 3; i++) {
            int y = h - 2 + 2 * i;
            if ((unsigned)y >= 64u) continue;
#pragma unroll
            for (int j = 0; j < 3; j++) {
                int xx = w - 2 + 2 * j;
                if ((unsigned)xx >= 64u) continue;
                float v = xc[(y << 6) + xx];
                const float* wp = &sw[cc * 9 + i * 3 + j];
#pragma unroll
                for (int oc = 0; oc < 18; oc++)
                    acc[oc] = fmaf(v, wp[oc * 576], acc[oc]);
            }
        }
    }
    float* op = g_offset + (size_t)b * 18 * HWW + hw;
    if (blockIdx.y == 0) {
#pragma unroll
        for (int oc = 0; oc < 18; oc++) atomicAdd(&op[oc * HWW], acc[oc] + off_b[oc]);
    } else {
#pragma unroll
        for (int oc = 0; oc < 18; oc++) atomicAdd(&op[oc * HWW], acc[oc]);
    }
}

// ---------------- deformable im2col: bilinear gather -> g_col ---------------
// grid (64, 9): x = pixel blocks, y = kernel point k. col[(c*9+k)][n]
__global__ __launch_bounds__(256)
void k_im2col_deform(const float* __restrict__ x) {
    int n = blockIdx.x * 256 + threadIdx.x;
    int k = blockIdx.y;
    int b = n >> 12, hw = n & 4095;
    int h = hw >> 6, w = hw & 63;
    int ki = k / 3, kj = k - ki * 3;

    float offy = g_offset[((size_t)b * 18 + 2 * k) * HWW + hw];
    float offx = g_offset[((size_t)b * 18 + 2 * k + 1) * HWW + hw];
    float py = (float)(h - 2 + 2 * ki) + offy;
    float px = (float)(w - 2 + 2 * kj) + offx;

    float fy0 = floorf(py), fx0 = floorf(px);
    int y0 = (int)fy0, x0 = (int)fx0;
    int y1 = y0 + 1, x1 = x0 + 1;
    float wy1 = py - fy0, wx1 = px - fx0;
    float wy0 = 1.f - wy1, wx0 = 1.f - wx1;

    bool vy0 = (unsigned)y0 < 64u, vy1 = (unsigned)y1 < 64u;
    bool vx0 = (unsigned)x0 < 64u, vx1 = (unsigned)x1 < 64u;
    float w00 = (vy0 && vx0) ? wy0 * wx0 : 0.f;
    float w01 = (vy0 && vx1) ? wy0 * wx1 : 0.f;
    float w10 = (vy1 && vx0) ? wy1 * wx0 : 0.f;
    float w11 = (vy1 && vx1) ? wy1 * wx1 : 0.f;

    int yc0 = min(max(y0, 0), 63), yc1 = min(max(y1, 0), 63);
    int xc0 = min(max(x0, 0), 63), xc1 = min(max(x1, 0), 63);
    int i00 = (yc0 << 6) + xc0, i01 = (yc0 << 6) + xc1;
    int i10 = (yc1 << 6) + xc0, i11 = (yc1 << 6) + xc1;

    const float* xb = x + (size_t)b * CC * HWW;
    float* col = g_col + (size_t)k * NN + n;
    for (int c = 0; c < CC; c++) {
        const float* xc = xb + (size_t)c * HWW;
        float v = w00 * xc[i00] + w01 * xc[i01] + w10 * xc[i10] + w11 * xc[i11];
        col[(size_t)c * 9 * NN] = v;
    }
}

// ---------------- SGEMM: C[m][n] = sum_k A[m][k] * g_col[k][n] (+bias) ------
// A: [256][2304] row-major. grid (NN/128, 2), 256 threads, 8x8 per thread.
__global__ __launch_bounds__(256, 2)
void k_gemm(const float* __restrict__ A, const float* __restrict__ bias, int outsel) {
    __shared__ float As[16][128];
    __shared__ float Bs[16][128];
    const float* Bc = g_col;
    float* Cm = outsel ? g_out2 : g_out1;

    int tid = threadIdx.x;
    int n0 = blockIdx.x * 128;
    int m0 = blockIdx.y * 128;

    int a_row = tid >> 1;              // 0..127
    int a_c4 = (tid & 1) * 2;          // {0,2}
    int b_row = tid >> 5;              // 0..7
    int b_c4 = tid & 31;               // 0..31

    int tm = (tid >> 4) << 3;
    int tn = (tid & 15) << 3;

    float acc[8][8];
#pragma unroll
    for (int i = 0; i < 8; i++)
#pragma unroll
        for (int j = 0; j < 8; j++) acc[i][j] = 0.f;

    for (int kt = 0; kt < CKK; kt += 16) {
#pragma unroll
        for (int u = 0; u < 2; u++) {
            float4 av = *(const float4*)(A + (size_t)(m0 + a_row) * CKK + kt + (a_c4 + u) * 4);
            As[(a_c4 + u) * 4 + 0][a_row] = av.x;
            As[(a_c4 + u) * 4 + 1][a_row] = av.y;
            As[(a_c4 + u) * 4 + 2][a_row] = av.z;
            As[(a_c4 + u) * 4 + 3][a_row] = av.w;
        }
#pragma unroll
        for (int u = 0; u < 2; u++) {
            float4 bv = *(const float4*)(Bc + (size_t)(kt + b_row + u * 8) * NN + n0 + b_c4 * 4);
            *(float4*)(&Bs[b_row + u * 8][b_c4 * 4]) = bv;
        }
        __syncthreads();
#pragma unroll
        for (int kk = 0; kk < 16; kk++) {
            float a[8], bf[8];
            *(float4*)(a) = *(const float4*)(&As[kk][tm]);
            *(float4*)(a + 4) = *(const float4*)(&As[kk][tm + 4]);
            *(float4*)(bf) = *(const float4*)(&Bs[kk][tn]);
            *(float4*)(bf + 4) = *(const float4*)(&Bs[kk][tn + 4]);
#pragma unroll
            for (int i = 0; i < 8; i++)
#pragma unroll
                for (int j = 0; j < 8; j++)
                    acc[i][j] = fmaf(a[i], bf[j], acc[i][j]);
        }
        __syncthreads();
    }

#pragma unroll
    for (int i = 0; i < 8; i++) {
        int row = m0 + tm + i;
        float bv = bias ? bias[row] : 0.f;
        float* cp = Cm + (size_t)row * NN + n0 + tn;
        float4 v0 = make_float4(acc[i][0] + bv, acc[i][1] + bv, acc[i][2] + bv, acc[i][3] + bv);
        float4 v1 = make_float4(acc[i][4] + bv, acc[i][5] + bv, acc[i][6] + bv, acc[i][7] + bv);
        *(float4*)(cp) = v0;
        *(float4*)(cp + 4) = v1;
    }
}

// ---------------- BN stats -> per-channel scale/shift ------------------------
__global__ __launch_bounds__(256)
void k_bnstats(const float* __restrict__ gamma, const float* __restrict__ beta, int sel) {
    const float* src = sel ? g_out2 : g_out1;
    float* scale = sel ? g_scale2 : g_scale1;
    float* shift = sel ? g_shift2 : g_shift1;
    int ch = blockIdx.x;
    const float* p = src + (size_t)ch * NN;
    float s = 0.f, sq = 0.f;
    for (int i = threadIdx.x; i < NN; i += 256) {
        float v = p[i];
        s += v;
        sq = fmaf(v, v, sq);
    }
    __shared__ float rs[256], rq[256];
    int t = threadIdx.x;
    rs[t] = s; rq[t] = sq;
    __syncthreads();
    for (int off = 128; off > 0; off >>= 1) {
        if (t < off) { rs[t] += rs[t + off]; rq[t] += rq[t + off]; }
        __syncthreads();
    }
    if (t == 0) {
        float mean = rs[0] * (1.f / NN);
        float var = fmaxf(rq[0] * (1.f / NN) - mean * mean, 0.f);
        float inv = rsqrtf(var + EPSB);
        float sc = inv * gamma[ch];
        scale[ch] = sc;
        shift[ch] = beta[ch] - mean * sc;
    }
}

// ---------------- im2col for conv2 (pad1 dil1), BN1+ReLU fused --------------
// grid (64, 9)
__global__ __launch_bounds__(256)
void k_im2col2() {
    int n = blockIdx.x * 256 + threadIdx.x;
    int k = blockIdx.y;
    int b = n >> 12, hw = n & 4095;
    int h = hw >> 6, w = hw & 63;
    int ki = k / 3, kj = k - ki * 3;
    int y = h - 1 + ki, xx = w - 1 + kj;
    bool valid = (unsigned)y < 64u && (unsigned)xx < 64u;
    float* col = g_col + (size_t)k * NN + n;
    if (valid) {
        int src_off = b * HWW + (y << 6) + xx;
        for (int c = 0; c < CC; c++) {
            float v = fmaf(g_out1[(size_t)c * NN + src_off], g_scale1[c], g_shift1[c]);
            col[(size_t)c * 9 * NN] = fmaxf(v, 0.f);
        }
    } else {
        for (int c = 0; c < CC; c++) col[(size_t)c * 9 * NN] = 0.f;
    }
}

// ---------------- final: relu(bn2(out2) + x) in NCHW ------------------------
__global__ __launch_bounds__(256)
void k_final(const float* __restrict__ x, float* __restrict__ out) {
    int i = blockIdx.x * 256 + threadIdx.x;   // over B*O*HW = 4.19M
    int hw = i & 4095;
    int o = (i >> 12) & 255;
    int b = i >> 20;
    float v = fmaf(g_out2[(size_t)o * NN + b * HWW + hw], g_scale2[o], g_shift2[o]) + x[i];
    out[i] = fmaxf(v, 0.f);
}

// ---------------- launch -----------------------------------------------------
extern "C" void kernel_launch(void* const* d_in, const int* in_sizes, int n_in,
                              void* d_out, int out_size) {
    const float* x     = (const float*)d_in[0];
    const float* off_w = (const float*)d_in[1];
    const float* off_b = (const float*)d_in[2];
    const float* dw    = (const float*)d_in[3];
    const float* db    = (const float*)d_in[4];
    const float* bn1_g = (const float*)d_in[5];
    const float* bn1_b = (const float*)d_in[6];
    const float* w2    = (const float*)d_in[7];
    const float* bn2_g = (const float*)d_in[8];
    const float* bn2_b = (const float*)d_in[9];
    float* out = (float*)d_out;

    k_zero_offset<<<(BB * 18 * HWW + 255) / 256, 256>>>();
    k_offset_conv<<<dim3(64, 4), 256>>>(x, off_w, off_b);
    k_im2col_deform<<<dim3(64, 9), 256>>>(x);
    k_gemm<<<dim3(NN / 128, 2), 256>>>(dw, db, 0);
    k_bnstats<<<256, 256>>>(bn1_g, bn1_b, 0);
    k_im2col2<<<dim3(64, 9), 256>>>();
    k_gemm<<<dim3(NN / 128, 2), 256>>>(w2, nullptr, 1);
    k_bnstats<<<256, 256>>>(bn2_g, bn2_b, 1);
    k_final<<<(BB * OO * HWW + 255) / 256, 256>>>(x, out);
}

// round 3
// speedup vs baseline: 1.4051x; 1.4051x over previous
#include <cuda_runtime.h>
#include <cuda_bf16.h>
#include <cstdint>

#define BB 4
#define CC 256
#define OO 256
#define HWW 4096
#define NN 16384          // BB*HWW
#define CKK 2304          // CC*9
#define K3 6912           // 3*CKK (bf16 split-triple K)
#define EPSB 1e-5f

#define NSTAGE 3
#define STAGE_SZ 32768      // A 16KB + B 16KB per stage (128 rows x 128B each)
#define GEMM_SMEM (NSTAGE * STAGE_SZ)
#define NUM_KCH 108         // K3*2 bytes / 128B per chunk = 13824/128

// ---------------- scratch (device globals; no allocs allowed) ----------------
__device__ float g_offset[BB * 18 * HWW];                       // 4.7 MB
__device__ __nv_bfloat16 g_colb[(size_t)NN * K3];               // 226 MB [n][k']
__device__ __nv_bfloat16 g_wA1[(size_t)OO * K3];                // 3.5 MB [m][k']
__device__ __nv_bfloat16 g_wA2[(size_t)OO * K3];
__device__ float g_out1[(size_t)OO * NN];                       // 16.8 MB [o][n]
__device__ float g_out2[(size_t)OO * NN];
__device__ float g_scale1[OO], g_shift1[OO], g_scale2[OO], g_shift2[OO];

// ---------------- helpers ----------------------------------------------------
__device__ __forceinline__ uint32_t smem_u32(const void* p) {
    uint32_t a;
    asm("{ .reg .u64 t; cvta.to.shared.u64 t, %1; cvt.u32.u64 %0, t; }" : "=r"(a) : "l"(p));
    return a;
}
#define SWZ128(o) ((o) ^ (((o) >> 3) & 0x70))
#define CP_ASYNC16(dst, src) \
    asm volatile("cp.async.cg.shared.global [%0], [%1], 16;" :: "r"(dst), "l"(src))
#define CP_COMMIT() asm volatile("cp.async.commit_group;" ::: "memory")
#define CP_WAIT2()  asm volatile("cp.async.wait_group 2;" ::: "memory")

#define LDSM4(r0, r1, r2, r3, addr) \
    asm volatile("ldmatrix.sync.aligned.m8n8.x4.shared.b16 {%0,%1,%2,%3}, [%4];" \
                 : "=r"(r0), "=r"(r1), "=r"(r2), "=r"(r3) : "r"(addr))

#define MMA16816(d, a0, a1, a2, a3, b0, b1) \
    asm volatile("mma.sync.aligned.m16n8k16.row.col.f32.bf16.bf16.f32 " \
                 "{%0,%1,%2,%3},{%4,%5,%6,%7},{%8,%9},{%0,%1,%2,%3};" \
                 : "+f"((d)[0]), "+f"((d)[1]), "+f"((d)[2]), "+f"((d)[3]) \
                 : "r"(a0), "r"(a1), "r"(a2), "r"(a3), "r"(b0), "r"(b1))

__device__ __forceinline__ unsigned short f2bf(float v) {
    __nv_bfloat16 h = __float2bfloat16_rn(v);
    return *reinterpret_cast<unsigned short*>(&h);
}

// ---------------- zero offset ------------------------------------------------
__global__ void k_zero_offset() {
    int i = blockIdx.x * 256 + threadIdx.x;
    if (i < BB * 18 * HWW) g_offset[i] = 0.f;
}

// ---------------- offset conv: 3x3, dil=2, pad=2, 256->18 -------------------
__global__ __launch_bounds__(256)
void k_offset_conv(const float* __restrict__ x, const float* __restrict__ off_w,
                   const float* __restrict__ off_b) {
    __shared__ float sw[18 * 64 * 9];
    int c0 = blockIdx.y * 64;
    for (int idx = threadIdx.x; idx < 18 * 64 * 9; idx += 256) {
        int oc = idx / 576;
        int rem = idx - oc * 576;
        sw[idx] = off_w[oc * CKK + c0 * 9 + rem];
    }
    __syncthreads();

    int n = blockIdx.x * 256 + threadIdx.x;
    int b = n >> 12, hw = n & 4095;
    int h = hw >> 6, w = hw & 63;

    float acc[18];
#pragma unroll
    for (int oc = 0; oc < 18; oc++) acc[oc] = 0.f;

    const float* xb = x + ((size_t)b * CC + c0) * HWW;
    for (int cc = 0; cc < 64; cc++) {
        const float* xc = xb + cc * HWW;
#pragma unroll
        for (int i = 0; i < 3; i++) {
            int y = h - 2 + 2 * i;
            if ((unsigned)y >= 64u) continue;
#pragma unroll
            for (int j = 0; j < 3; j++) {
                int xx = w - 2 + 2 * j;
                if ((unsigned)xx >= 64u) continue;
                float v = xc[(y << 6) + xx];
                const float* wp = &sw[cc * 9 + i * 3 + j];
#pragma unroll
                for (int oc = 0; oc < 18; oc++)
                    acc[oc] = fmaf(v, wp[oc * 576], acc[oc]);
            }
        }
    }
    float* op = g_offset + (size_t)b * 18 * HWW + hw;
    if (blockIdx.y == 0) {
#pragma unroll
        for (int oc = 0; oc < 18; oc++) atomicAdd(&op[oc * HWW], acc[oc] + off_b[oc]);
    } else {
#pragma unroll
        for (int oc = 0; oc < 18; oc++) atomicAdd(&op[oc * HWW], acc[oc]);
    }
}

// ---------------- weight prep: fp32 W -> split-triple bf16 A' ---------------
// A'[m][3*(kpt*256+c)+{0,1,2}] = {hi, lo, hi}
__global__ __launch_bounds__(256)
void k_wprep(const float* __restrict__ dw, const float* __restrict__ w2) {
    int idx = blockIdx.x * 256 + threadIdx.x;     // over 256*2304
    if (idx >= OO * CKK) return;
    int m = idx / CKK;
    int ck = idx - m * CKK;
    int c = ck / 9, kpt = ck - c * 9;
    const float* w = blockIdx.y ? w2 : dw;
    __nv_bfloat16* dst = blockIdx.y ? g_wA2 : g_wA1;
    float v = w[idx];
    unsigned short hi = f2bf(v);
    float hf = __bfloat162float(*reinterpret_cast<__nv_bfloat16*>(&hi));
    unsigned short lo = f2bf(v - hf);
    size_t p = (size_t)m * K3 + 3 * (kpt * 256 + c);
    unsigned short* d = reinterpret_cast<unsigned short*>(dst);
    d[p] = hi; d[p + 1] = lo; d[p + 2] = hi;
}

// ---------------- deformable im2col -> B' triple bf16 [n][k'] ---------------
// B'[n][3*(kpt*256+c)+{0,1,2}] = {hi, hi, lo}
__global__ __launch_bounds__(256)
void k_im2col_deform(const float* __restrict__ x) {
    int t = blockIdx.x * 256 + threadIdx.x;    // over NN*9
    int n = t / 9, kpt = t - n * 9;
    int b = n >> 12, hw = n & 4095;
    int h = hw >> 6, w = hw & 63;
    int ki = kpt / 3, kj = kpt - ki * 3;

    float offy = g_offset[((size_t)b * 18 + 2 * kpt) * HWW + hw];
    float offx = g_offset[((size_t)b * 18 + 2 * kpt + 1) * HWW + hw];
    float py = (float)(h - 2 + 2 * ki) + offy;
    float px = (float)(w - 2 + 2 * kj) + offx;

    float fy0 = floorf(py), fx0 = floorf(px);
    int y0 = (int)fy0, x0 = (int)fx0;
    int y1 = y0 + 1, x1 = x0 + 1;
    float wy1 = py - fy0, wx1 = px - fx0;
    float wy0 = 1.f - wy1, wx0 = 1.f - wx1;

    bool vy0 = (unsigned)y0 < 64u, vy1 = (unsigned)y1 < 64u;
    bool vx0 = (unsigned)x0 < 64u, vx1 = (unsigned)x1 < 64u;
    float w00 = (vy0 && vx0) ? wy0 * wx0 : 0.f;
    float w01 = (vy0 && vx1) ? wy0 * wx1 : 0.f;
    float w10 = (vy1 && vx0) ? wy1 * wx0 : 0.f;
    float w11 = (vy1 && vx1) ? wy1 * wx1 : 0.f;

    int yc0 = min(max(y0, 0), 63), yc1 = min(max(y1, 0), 63);
    int xc0 = min(max(x0, 0), 63), xc1 = min(max(x1, 0), 63);
    int i00 = (yc0 << 6) + xc0, i01 = (yc0 << 6) + xc1;
    int i10 = (yc1 << 6) + xc0, i11 = (yc1 << 6) + xc1;

    const float* xb = x + (size_t)b * CC * HWW;
    unsigned short* colp = reinterpret_cast<unsigned short*>(g_colb) +
                           (size_t)n * K3 + 3 * (kpt * 256);
    for (int c0 = 0; c0 < 256; c0 += 8) {
        __align__(16) unsigned short buf[24];
#pragma unroll
        for (int cc = 0; cc < 8; cc++) {
            const float* xc = xb + (size_t)(c0 + cc) * HWW;
            float v = w00 * xc[i00] + w01 * xc[i01] + w10 * xc[i10] + w11 * xc[i11];
            unsigned short hi = f2bf(v);
            float hf = __bfloat162float(*reinterpret_cast<__nv_bfloat16*>(&hi));
            unsigned short lo = f2bf(v - hf);
            buf[cc * 3] = hi; buf[cc * 3 + 1] = hi; buf[cc * 3 + 2] = lo;
        }
        uint4* dst = reinterpret_cast<uint4*>(colp + 3 * c0);
        const uint4* s = reinterpret_cast<const uint4*>(buf);
        dst[0] = s[0]; dst[1] = s[1]; dst[2] = s[2];
    }
}

// ---------------- im2col for conv2 (pad1 dil1), BN1+ReLU fused --------------
__global__ __launch_bounds__(256)
void k_im2col2() {
    __shared__ float sS[256], sH[256];
    for (int i = threadIdx.x; i < 256; i += 256) { sS[i] = g_scale1[i]; sH[i] = g_shift1[i]; }
    __syncthreads();

    int t = blockIdx.x * 256 + threadIdx.x;    // over NN*9
    int n = t / 9, kpt = t - n * 9;
    int b = n >> 12, hw = n & 4095;
    int h = hw >> 6, w = hw & 63;
    int ki = kpt / 3, kj = kpt - ki * 3;
    int y = h - 1 + ki, xx = w - 1 + kj;
    bool valid = (unsigned)y < 64u && (unsigned)xx < 64u;
    int src = b * HWW + (y << 6) + xx;

    unsigned short* colp = reinterpret_cast<unsigned short*>(g_colb) +
                           (size_t)n * K3 + 3 * (kpt * 256);
    for (int c0 = 0; c0 < 256; c0 += 8) {
        __align__(16) unsigned short buf[24];
#pragma unroll
        for (int cc = 0; cc < 8; cc++) {
            int c = c0 + cc;
            float v = 0.f;
            if (valid) v = fmaxf(fmaf(g_out1[(size_t)c * NN + src], sS[c], sH[c]), 0.f);
            unsigned short hi = f2bf(v);
            float hf = __bfloat162float(*reinterpret_cast<__nv_bfloat16*>(&hi));
            unsigned short lo = f2bf(v - hf);
            buf[cc * 3] = hi; buf[cc * 3 + 1] = hi; buf[cc * 3 + 2] = lo;
        }
        uint4* dst = reinterpret_cast<uint4*>(colp + 3 * c0);
        const uint4* s = reinterpret_cast<const uint4*>(buf);
        dst[0] = s[0]; dst[1] = s[1]; dst[2] = s[2];
    }
}

// ---------------- mma.sync bf16 GEMM: C[m][n] = sum A'[m][k']*B'[n][k'] -----
// grid (2, 128): x = m-tile (128 rows), y = n-tile (128 pixels). 256 threads.
// 3-stage cp.async pipeline, BK=64 bf16 (128B rows, SW128).
__global__ __launch_bounds__(256, 2)
void k_gemm_mma(int wsel, const float* __restrict__ bias, int outsel) {
    extern __shared__ char smem[];
    uint32_t sb = smem_u32(smem);
    int tid = threadIdx.x;
    int m0 = blockIdx.x * 128;
    int n0 = blockIdx.y * 128;

    const __nv_bfloat16* Ag = wsel ? g_wA2 : g_wA1;
    float* Cg = outsel ? g_out2 : g_out1;
    const char* Abase = reinterpret_cast<const char*>(Ag) + (size_t)m0 * (K3 * 2);
    const char* Bbase = reinterpret_cast<const char*>(g_colb) + (size_t)n0 * (K3 * 2);

    // producer: 2048 16B chunks per stage (A 1024 + B 1024), 8 per thread
    auto load_stage = [&](int kc, int s) {
        uint32_t st = sb + s * STAGE_SZ;
        size_t kb = (size_t)kc * 128;
#pragma unroll
        for (int i = 0; i < 8; i++) {
            int idx = tid + i * 256;
            if (idx < 1024) {
                int r = idx >> 3, c = idx & 7;
                uint32_t off = SWZ128(r * 128 + c * 16);
                CP_ASYNC16(st + off, Abase + (size_t)r * (K3 * 2) + kb + c * 16);
            } else {
                int j = idx - 1024;
                int r = j >> 3, c = j & 7;
                uint32_t off = SWZ128(r * 128 + c * 16);
                CP_ASYNC16(st + 16384 + off, Bbase + (size_t)r * (K3 * 2) + kb + c * 16);
            }
        }
        CP_COMMIT();
    };

    int lane = tid & 31, w = tid >> 5;
    int wm = w >> 1, wn = w & 1;       // warp grid 4x2
    int mW = wm * 32, nW = wn * 64;
    int gq = lane >> 3, rr = lane & 7;
    int rowin = (gq & 1) * 8 + rr;     // row within a 16-row tile
    int kboff = (gq >> 1) * 16;        // byte offset within k16 (0 or 16)

    float acc[2][8][4];
#pragma unroll
    for (int mt = 0; mt < 2; mt++)
#pragma unroll
        for (int j = 0; j < 8; j++)
#pragma unroll
            for (int q = 0; q < 4; q++) acc[mt][j][q] = 0.f;

    // precompute smem row offsets + swizzle xors for ldmatrix addressing
    uint32_t aOff[2], aXor[2], bOff[4], bXor[4];
#pragma unroll
    for (int mt = 0; mt < 2; mt++) {
        int row = mW + mt * 16 + rowin;
        aOff[mt] = row * 128;
        aXor[mt] = (row & 7) << 4;
    }
#pragma unroll
    for (int nt = 0; nt < 4; nt++) {
        int row = nW + nt * 16 + rowin;
        bOff[nt] = row * 128;
        bXor[nt] = (row & 7) << 4;
    }

    load_stage(0, 0);
    load_stage(1, 1);
    load_stage(2, 2);

    for (int k = 0; k < NUM_KCH; k++) {
        int s = k % NSTAGE;
        uint32_t stA = sb + s * STAGE_SZ;
        uint32_t stB = stA + 16384;
        CP_WAIT2();
        __syncthreads();

#pragma unroll
        for (int ks = 0; ks < 4; ks++) {
            uint32_t kb = ks * 32 + kboff;
            uint32_t af[2][4], bf[4][4];
#pragma unroll
            for (int mt = 0; mt < 2; mt++)
                LDSM4(af[mt][0], af[mt][1], af[mt][2], af[mt][3],
                      stA + aOff[mt] + (kb ^ aXor[mt]));
#pragma unroll
            for (int nt = 0; nt < 4; nt++)
                LDSM4(bf[nt][0], bf[nt][1], bf[nt][2], bf[nt][3],
                      stB + bOff[nt] + (kb ^ bXor[nt]));
#pragma unroll
            for (int mt = 0; mt < 2; mt++)
#pragma unroll
                for (int j = 0; j < 8; j++) {
                    int q = j >> 1, hh = j & 1;
                    MMA16816(acc[mt][j], af[mt][0], af[mt][1], af[mt][2], af[mt][3],
                             bf[q][hh ? 1 : 0], bf[q][hh ? 3 : 2]);
                }
        }
        __syncthreads();
        if (k + 3 < NUM_KCH) load_stage(k + 3, s);
        else CP_COMMIT();
    }

    // epilogue: acc -> Cg (+bias)
    int qr = lane >> 2;
    int qc = (lane & 3) * 2;
#pragma unroll
    for (int mt = 0; mt < 2; mt++) {
        int row0 = m0 + mW + mt * 16 + qr;
        float bv0 = bias ? bias[row0] : 0.f;
        float bv1 = bias ? bias[row0 + 8] : 0.f;
#pragma unroll
        for (int j = 0; j < 8; j++) {
            int col = n0 + nW + j * 8 + qc;
            float2 v0 = make_float2(acc[mt][j][0] + bv0, acc[mt][j][1] + bv0);
            float2 v1 = make_float2(acc[mt][j][2] + bv1, acc[mt][j][3] + bv1);
            *reinterpret_cast<float2*>(Cg + (size_t)row0 * NN + col) = v0;
            *reinterpret_cast<float2*>(Cg + (size_t)(row0 + 8) * NN + col) = v1;
        }
    }
}

// ---------------- BN stats -> per-channel scale/shift ------------------------
__global__ __launch_bounds__(256)
void k_bnstats(const float* __restrict__ gamma, const float* __restrict__ beta, int sel) {
    const float* src = sel ? g_out2 : g_out1;
    float* scale = sel ? g_scale2 : g_scale1;
    float* shift = sel ? g_shift2 : g_shift1;
    int ch = blockIdx.x;
    const float* p = src + (size_t)ch * NN;
    float s = 0.f, sq = 0.f;
    for (int i = threadIdx.x; i < NN; i += 256) {
        float v = p[i];
        s += v;
        sq = fmaf(v, v, sq);
    }
    __shared__ float rs[256], rq[256];
    int t = threadIdx.x;
    rs[t] = s; rq[t] = sq;
    __syncthreads();
    for (int off = 128; off > 0; off >>= 1) {
        if (t < off) { rs[t] += rs[t + off]; rq[t] += rq[t + off]; }
        __syncthreads();
    }
    if (t == 0) {
        float mean = rs[0] * (1.f / NN);
        float var = fmaxf(rq[0] * (1.f / NN) - mean * mean, 0.f);
        float inv = rsqrtf(var + EPSB);
        float sc = inv * gamma[ch];
        scale[ch] = sc;
        shift[ch] = beta[ch] - mean * sc;
    }
}

// ---------------- final: relu(bn2(out2) + x) in NCHW ------------------------
__global__ __launch_bounds__(256)
void k_final(const float* __restrict__ x, float* __restrict__ out) {
    int i = blockIdx.x * 256 + threadIdx.x;
    int hw = i & 4095;
    int o = (i >> 12) & 255;
    int b = i >> 20;
    float v = fmaf(g_out2[(size_t)o * NN + b * HWW + hw], g_scale2[o], g_shift2[o]) + x[i];
    out[i] = fmaxf(v, 0.f);
}

// ---------------- launch -----------------------------------------------------
extern "C" void kernel_launch(void* const* d_in, const int* in_sizes, int n_in,
                              void* d_out, int out_size) {
    const float* x     = (const float*)d_in[0];
    const float* off_w = (const float*)d_in[1];
    const float* off_b = (const float*)d_in[2];
    const float* dw    = (const float*)d_in[3];
    const float* db    = (const float*)d_in[4];
    const float* bn1_g = (const float*)d_in[5];
    const float* bn1_b = (const float*)d_in[6];
    const float* w2    = (const float*)d_in[7];
    const float* bn2_g = (const float*)d_in[8];
    const float* bn2_b = (const float*)d_in[9];
    float* out = (float*)d_out;

    cudaFuncSetAttribute(k_gemm_mma, cudaFuncAttributeMaxDynamicSharedMemorySize, GEMM_SMEM);

    k_zero_offset<<<(BB * 18 * HWW + 255) / 256, 256>>>();
    k_offset_conv<<<dim3(64, 4), 256>>>(x, off_w, off_b);
    k_wprep<<<dim3((OO * CKK + 255) / 256, 2), 256>>>(dw, w2);
    k_im2col_deform<<<(NN * 9 + 255) / 256, 256>>>(x);
    k_gemm_mma<<<dim3(2, 128), 256, GEMM_SMEM>>>(0, db, 0);
    k_bnstats<<<256, 256>>>(bn1_g, bn1_b, 0);
    k_im2col2<<<(NN * 9 + 255) / 256, 256>>>();
    k_gemm_mma<<<dim3(2, 128), 256, GEMM_SMEM>>>(1, nullptr, 1);
    k_bnstats<<<256, 256>>>(bn2_g, bn2_b, 1);
    k_final<<<(BB * OO * HWW + 255) / 256, 256>>>(x, out);
}

// round 4
// speedup vs baseline: 1.6013x; 1.1396x over previous
#include <cuda_runtime.h>
#include <cuda_bf16.h>
#include <cstdint>

#define BB 4
#define CC 256
#define OO 256
#define HWW 4096
#define NN 16384          // BB*HWW
#define CKK 2304          // CC*9
#define K3 6912           // 3*CKK (bf16 split-triple K)
#define EPSB 1e-5f

#define NSTAGE 3
#define STAGE_SZ 32768      // A 16KB + B 16KB per stage (128 rows x 128B each)
#define GEMM_SMEM (NSTAGE * STAGE_SZ)
#define NUM_KCH 108         // K3*2 bytes / 128B per chunk

// ---------------- scratch (device globals; no allocs allowed) ----------------
__device__ float g_offset[BB * 18 * HWW];                       // 4.7 MB
__device__ __nv_bfloat16 g_colb[(size_t)NN * K3];               // 226 MB [n][k']
__device__ __nv_bfloat16 g_wA1[(size_t)OO * K3];                // 3.5 MB [m][k']
__device__ __nv_bfloat16 g_wA2[(size_t)OO * K3];
__device__ float g_out1[(size_t)OO * NN];                       // 16.8 MB [o][n]
__device__ float g_out2[(size_t)OO * NN];
__device__ float g_scale1[OO], g_shift1[OO], g_scale2[OO], g_shift2[OO];

// ---------------- helpers ----------------------------------------------------
__device__ __forceinline__ uint32_t smem_u32(const void* p) {
    uint32_t a;
    asm("{ .reg .u64 t; cvta.to.shared.u64 t, %1; cvt.u32.u64 %0, t; }" : "=r"(a) : "l"(p));
    return a;
}
#define SWZ128(o) ((o) ^ (((o) >> 3) & 0x70))
#define CP_ASYNC16(dst, src) \
    asm volatile("cp.async.cg.shared.global [%0], [%1], 16;" :: "r"(dst), "l"(src))
#define CP_COMMIT() asm volatile("cp.async.commit_group;" ::: "memory")
#define CP_WAIT2()  asm volatile("cp.async.wait_group 2;" ::: "memory")

#define LDSM4(r0, r1, r2, r3, addr) \
    asm volatile("ldmatrix.sync.aligned.m8n8.x4.shared.b16 {%0,%1,%2,%3}, [%4];" \
                 : "=r"(r0), "=r"(r1), "=r"(r2), "=r"(r3) : "r"(addr))

#define MMA16816(d, a0, a1, a2, a3, b0, b1) \
    asm volatile("mma.sync.aligned.m16n8k16.row.col.f32.bf16.bf16.f32 " \
                 "{%0,%1,%2,%3},{%4,%5,%6,%7},{%8,%9},{%0,%1,%2,%3};" \
                 : "+f"((d)[0]), "+f"((d)[1]), "+f"((d)[2]), "+f"((d)[3]) \
                 : "r"(a0), "r"(a1), "r"(a2), "r"(a3), "r"(b0), "r"(b1))

__device__ __forceinline__ unsigned short f2bf(float v) {
    __nv_bfloat16 h = __float2bfloat16_rn(v);
    return *reinterpret_cast<unsigned short*>(&h);
}

// ---------------- zero offset ------------------------------------------------
__global__ void k_zero_offset() {
    int i = blockIdx.x * 256 + threadIdx.x;
    if (i < BB * 18 * HWW) g_offset[i] = 0.f;
}

// ---------------- offset conv: 3x3, dil=2, pad=2, 256->18 -------------------
__global__ __launch_bounds__(256)
void k_offset_conv(const float* __restrict__ x, const float* __restrict__ off_w,
                   const float* __restrict__ off_b) {
    __shared__ float sw[18 * 64 * 9];
    int c0 = blockIdx.y * 64;
    for (int idx = threadIdx.x; idx < 18 * 64 * 9; idx += 256) {
        int oc = idx / 576;
        int rem = idx - oc * 576;
        sw[idx] = off_w[oc * CKK + c0 * 9 + rem];
    }
    __syncthreads();

    int n = blockIdx.x * 256 + threadIdx.x;
    int b = n >> 12, hw = n & 4095;
    int h = hw >> 6, w = hw & 63;

    float acc[18];
#pragma unroll
    for (int oc = 0; oc < 18; oc++) acc[oc] = 0.f;

    const float* xb = x + ((size_t)b * CC + c0) * HWW;
    for (int cc = 0; cc < 64; cc++) {
        const float* xc = xb + cc * HWW;
#pragma unroll
        for (int i = 0; i < 3; i++) {
            int y = h - 2 + 2 * i;
            if ((unsigned)y >= 64u) continue;
#pragma unroll
            for (int j = 0; j < 3; j++) {
                int xx = w - 2 + 2 * j;
                if ((unsigned)xx >= 64u) continue;
                float v = xc[(y << 6) + xx];
                const float* wp = &sw[cc * 9 + i * 3 + j];
#pragma unroll
                for (int oc = 0; oc < 18; oc++)
                    acc[oc] = fmaf(v, wp[oc * 576], acc[oc]);
            }
        }
    }
    float* op = g_offset + (size_t)b * 18 * HWW + hw;
    if (blockIdx.y == 0) {
#pragma unroll
        for (int oc = 0; oc < 18; oc++) atomicAdd(&op[oc * HWW], acc[oc] + off_b[oc]);
    } else {
#pragma unroll
        for (int oc = 0; oc < 18; oc++) atomicAdd(&op[oc * HWW], acc[oc]);
    }
}

// ---------------- weight prep: fp32 W -> split-triple bf16 A' ---------------
__global__ __launch_bounds__(256)
void k_wprep(const float* __restrict__ dw, const float* __restrict__ w2) {
    int idx = blockIdx.x * 256 + threadIdx.x;
    if (idx >= OO * CKK) return;
    int m = idx / CKK;
    int ck = idx - m * CKK;
    int c = ck / 9, kpt = ck - c * 9;
    const float* w = blockIdx.y ? w2 : dw;
    __nv_bfloat16* dst = blockIdx.y ? g_wA2 : g_wA1;
    float v = w[idx];
    unsigned short hi = f2bf(v);
    float hf = __bfloat162float(*reinterpret_cast<__nv_bfloat16*>(&hi));
    unsigned short lo = f2bf(v - hf);
    size_t p = (size_t)m * K3 + 3 * (kpt * 256 + c);
    unsigned short* d = reinterpret_cast<unsigned short*>(dst);
    d[p] = hi; d[p + 1] = lo; d[p + 2] = hi;
}

// ---------------- deformable im2col v2: smem-transposed ----------------------
// block = 32 consecutive pixels x 9 kpt x 256 c (chunks of 32). grid NN/32.
__global__ __launch_bounds__(256)
void k_im2col_deform(const float* __restrict__ x) {
    __shared__ float st[9][32][33];     // [kpt][cc][px]
    __shared__ float4 wts[9][32];       // bilinear weights per (kpt,px)
    __shared__ int4 idxs[9][32];        // clamped gather indices per (kpt,px)

    int n0 = blockIdx.x * 32;
    int b = n0 >> 12;

    // phase 0: per (px,kpt) sampling geometry
    for (int t = threadIdx.x; t < 288; t += 256) {
        int kpt = t >> 5, px = t & 31;
        int n = n0 + px;
        int hw = n & 4095;
        int h = hw >> 6, w = hw & 63;
        int ki = kpt / 3, kj = kpt - ki * 3;
        float offy = g_offset[((size_t)b * 18 + 2 * kpt) * HWW + hw];
        float offx = g_offset[((size_t)b * 18 + 2 * kpt + 1) * HWW + hw];
        float py = (float)(h - 2 + 2 * ki) + offy;
        float pxx = (float)(w - 2 + 2 * kj) + offx;
        float fy0 = floorf(py), fx0 = floorf(pxx);
        int y0 = (int)fy0, x0 = (int)fx0;
        int y1 = y0 + 1, x1 = x0 + 1;
        float wy1 = py - fy0, wx1 = pxx - fx0;
        float wy0 = 1.f - wy1, wx0 = 1.f - wx1;
        bool vy0 = (unsigned)y0 < 64u, vy1 = (unsigned)y1 < 64u;
        bool vx0 = (unsigned)x0 < 64u, vx1 = (unsigned)x1 < 64u;
        float w00 = (vy0 && vx0) ? wy0 * wx0 : 0.f;
        float w01 = (vy0 && vx1) ? wy0 * wx1 : 0.f;
        float w10 = (vy1 && vx0) ? wy1 * wx0 : 0.f;
        float w11 = (vy1 && vx1) ? wy1 * wx1 : 0.f;
        int yc0 = min(max(y0, 0), 63), yc1 = min(max(y1, 0), 63);
        int xc0 = min(max(x0, 0), 63), xc1 = min(max(x1, 0), 63);
        wts[kpt][px] = make_float4(w00, w01, w10, w11);
        idxs[kpt][px] = make_int4((yc0 << 6) + xc0, (yc0 << 6) + xc1,
                                  (yc1 << 6) + xc0, (yc1 << 6) + xc1);
    }
    __syncthreads();

    const float* xb = x + (size_t)b * CC * HWW;
    unsigned short* colbase = reinterpret_cast<unsigned short*>(g_colb);
    int wid = threadIdx.x >> 5, lane = threadIdx.x & 31;

    for (int c0 = 0; c0 < 256; c0 += 32) {
        // phase A: gather, lane = pixel (coalesced-ish local reads)
        float4 wv; int4 iv;
        for (int pair = wid; pair < 288; pair += 8) {
            int kpt = pair >> 5, cc = pair & 31;
            wv = wts[kpt][lane];
            iv = idxs[kpt][lane];
            const float* xp = xb + (size_t)(c0 + cc) * HWW;
            float v = wv.x * xp[iv.x] + wv.y * xp[iv.y] + wv.z * xp[iv.z] + wv.w * xp[iv.w];
            st[kpt][cc][lane] = v;
        }
        __syncthreads();

        // phase B: split + coalesced writes. task = (px, kpt, q) -> 8 c's = 48B
        for (int task = threadIdx.x; task < 1152; task += 256) {
            int q = task & 3;
            int rem = task >> 2;
            int kpt = rem % 9;
            int px = rem / 9;
            __align__(16) unsigned short buf[24];
#pragma unroll
            for (int j = 0; j < 8; j++) {
                float v = st[kpt][q * 8 + j][px];
                unsigned short hi = f2bf(v);
                float hf = __bfloat162float(*reinterpret_cast<__nv_bfloat16*>(&hi));
                unsigned short lo = f2bf(v - hf);
                buf[j * 3] = hi; buf[j * 3 + 1] = hi; buf[j * 3 + 2] = lo;
            }
            uint4* dst = reinterpret_cast<uint4*>(
                colbase + (size_t)(n0 + px) * K3 + 3 * (kpt * 256 + c0 + q * 8));
            const uint4* s = reinterpret_cast<const uint4*>(buf);
            dst[0] = s[0]; dst[1] = s[1]; dst[2] = s[2];
        }
        __syncthreads();
    }
}

// ---------------- im2col2 v2: smem-transposed, BN1+ReLU fused ----------------
__global__ __launch_bounds__(256)
void k_im2col2() {
    __shared__ float st[9][32][33];
    __shared__ int sidx[9][32];          // src index or -1
    __shared__ float sS[256], sH[256];

    int n0 = blockIdx.x * 32;
    int b = n0 >> 12;

    for (int i = threadIdx.x; i < 256; i += 256) { sS[i] = g_scale1[i]; sH[i] = g_shift1[i]; }
    for (int t = threadIdx.x; t < 288; t += 256) {
        int kpt = t >> 5, px = t & 31;
        int n = n0 + px;
        int hw = n & 4095;
        int h = hw >> 6, w = hw & 63;
        int ki = kpt / 3, kj = kpt - ki * 3;
        int y = h - 1 + ki, xx = w - 1 + kj;
        bool valid = (unsigned)y < 64u && (unsigned)xx < 64u;
        sidx[kpt][px] = valid ? (b * HWW + (y << 6) + xx) : -1;
    }
    __syncthreads();

    unsigned short* colbase = reinterpret_cast<unsigned short*>(g_colb);
    int wid = threadIdx.x >> 5, lane = threadIdx.x & 31;

    for (int c0 = 0; c0 < 256; c0 += 32) {
        for (int pair = wid; pair < 288; pair += 8) {
            int kpt = pair >> 5, cc = pair & 31;
            int c = c0 + cc;
            int src = sidx[kpt][lane];
            float v = 0.f;
            if (src >= 0)
                v = fmaxf(fmaf(g_out1[(size_t)c * NN + src], sS[c], sH[c]), 0.f);
            st[kpt][cc][lane] = v;
        }
        __syncthreads();

        for (int task = threadIdx.x; task < 1152; task += 256) {
            int q = task & 3;
            int rem = task >> 2;
            int kpt = rem % 9;
            int px = rem / 9;
            __align__(16) unsigned short buf[24];
#pragma unroll
            for (int j = 0; j < 8; j++) {
                float v = st[kpt][q * 8 + j][px];
                unsigned short hi = f2bf(v);
                float hf = __bfloat162float(*reinterpret_cast<__nv_bfloat16*>(&hi));
                unsigned short lo = f2bf(v - hf);
                buf[j * 3] = hi; buf[j * 3 + 1] = hi; buf[j * 3 + 2] = lo;
            }
            uint4* dst = reinterpret_cast<uint4*>(
                colbase + (size_t)(n0 + px) * K3 + 3 * (kpt * 256 + c0 + q * 8));
            const uint4* s = reinterpret_cast<const uint4*>(buf);
            dst[0] = s[0]; dst[1] = s[1]; dst[2] = s[2];
        }
        __syncthreads();
    }
}

// ---------------- mma.sync bf16 GEMM (unchanged from passing R3) -------------
__global__ __launch_bounds__(256, 2)
void k_gemm_mma(int wsel, const float* __restrict__ bias, int outsel) {
    extern __shared__ char smem[];
    uint32_t sb = smem_u32(smem);
    int tid = threadIdx.x;
    int m0 = blockIdx.x * 128;
    int n0 = blockIdx.y * 128;

    const __nv_bfloat16* Ag = wsel ? g_wA2 : g_wA1;
    float* Cg = outsel ? g_out2 : g_out1;
    const char* Abase = reinterpret_cast<const char*>(Ag) + (size_t)m0 * (K3 * 2);
    const char* Bbase = reinterpret_cast<const char*>(g_colb) + (size_t)n0 * (K3 * 2);

    auto load_stage = [&](int kc, int s) {
        uint32_t st = sb + s * STAGE_SZ;
        size_t kb = (size_t)kc * 128;
#pragma unroll
        for (int i = 0; i < 8; i++) {
            int idx = tid + i * 256;
            if (idx < 1024) {
                int r = idx >> 3, c = idx & 7;
                uint32_t off = SWZ128(r * 128 + c * 16);
                CP_ASYNC16(st + off, Abase + (size_t)r * (K3 * 2) + kb + c * 16);
            } else {
                int j = idx - 1024;
                int r = j >> 3, c = j & 7;
                uint32_t off = SWZ128(r * 128 + c * 16);
                CP_ASYNC16(st + 16384 + off, Bbase + (size_t)r * (K3 * 2) + kb + c * 16);
            }
        }
        CP_COMMIT();
    };

    int lane = tid & 31, w = tid >> 5;
    int wm = w >> 1, wn = w & 1;
    int mW = wm * 32, nW = wn * 64;
    int gq = lane >> 3, rr = lane & 7;
    int rowin = (gq & 1) * 8 + rr;
    int kboff = (gq >> 1) * 16;

    float acc[2][8][4];
#pragma unroll
    for (int mt = 0; mt < 2; mt++)
#pragma unroll
        for (int j = 0; j < 8; j++)
#pragma unroll
            for (int q = 0; q < 4; q++) acc[mt][j][q] = 0.f;

    uint32_t aOff[2], aXor[2], bOff[4], bXor[4];
#pragma unroll
    for (int mt = 0; mt < 2; mt++) {
        int row = mW + mt * 16 + rowin;
        aOff[mt] = row * 128;
        aXor[mt] = (row & 7) << 4;
    }
#pragma unroll
    for (int nt = 0; nt < 4; nt++) {
        int row = nW + nt * 16 + rowin;
        bOff[nt] = row * 128;
        bXor[nt] = (row & 7) << 4;
    }

    load_stage(0, 0);
    load_stage(1, 1);
    load_stage(2, 2);

    for (int k = 0; k < NUM_KCH; k++) {
        int s = k % NSTAGE;
        uint32_t stA = sb + s * STAGE_SZ;
        uint32_t stB = stA + 16384;
        CP_WAIT2();
        __syncthreads();

#pragma unroll
        for (int ks = 0; ks < 4; ks++) {
            uint32_t kb = ks * 32 + kboff;
            uint32_t af[2][4], bf[4][4];
#pragma unroll
            for (int mt = 0; mt < 2; mt++)
                LDSM4(af[mt][0], af[mt][1], af[mt][2], af[mt][3],
                      stA + aOff[mt] + (kb ^ aXor[mt]));
#pragma unroll
            for (int nt = 0; nt < 4; nt++)
                LDSM4(bf[nt][0], bf[nt][1], bf[nt][2], bf[nt][3],
                      stB + bOff[nt] + (kb ^ bXor[nt]));
#pragma unroll
            for (int mt = 0; mt < 2; mt++)
#pragma unroll
                for (int j = 0; j < 8; j++) {
                    int q = j >> 1, hh = j & 1;
                    MMA16816(acc[mt][j], af[mt][0], af[mt][1], af[mt][2], af[mt][3],
                             bf[q][hh ? 1 : 0], bf[q][hh ? 3 : 2]);
                }
        }
        __syncthreads();
        if (k + 3 < NUM_KCH) load_stage(k + 3, s);
        else CP_COMMIT();
    }

    int qr = lane >> 2;
    int qc = (lane & 3) * 2;
#pragma unroll
    for (int mt = 0; mt < 2; mt++) {
        int row0 = m0 + mW + mt * 16 + qr;
        float bv0 = bias ? bias[row0] : 0.f;
        float bv1 = bias ? bias[row0 + 8] : 0.f;
#pragma unroll
        for (int j = 0; j < 8; j++) {
            int col = n0 + nW + j * 8 + qc;
            float2 v0 = make_float2(acc[mt][j][0] + bv0, acc[mt][j][1] + bv0);
            float2 v1 = make_float2(acc[mt][j][2] + bv1, acc[mt][j][3] + bv1);
            *reinterpret_cast<float2*>(Cg + (size_t)row0 * NN + col) = v0;
            *reinterpret_cast<float2*>(Cg + (size_t)(row0 + 8) * NN + col) = v1;
        }
    }
}

// ---------------- BN stats -> per-channel scale/shift ------------------------
__global__ __launch_bounds__(256)
void k_bnstats(const float* __restrict__ gamma, const float* __restrict__ beta, int sel) {
    const float* src = sel ? g_out2 : g_out1;
    float* scale = sel ? g_scale2 : g_scale1;
    float* shift = sel ? g_shift2 : g_shift1;
    int ch = blockIdx.x;
    const float* p = src + (size_t)ch * NN;
    float s = 0.f, sq = 0.f;
    for (int i = threadIdx.x; i < NN; i += 256) {
        float v = p[i];
        s += v;
        sq = fmaf(v, v, sq);
    }
    __shared__ float rs[256], rq[256];
    int t = threadIdx.x;
    rs[t] = s; rq[t] = sq;
    __syncthreads();
    for (int off = 128; off > 0; off >>= 1) {
        if (t < off) { rs[t] += rs[t + off]; rq[t] += rq[t + off]; }
        __syncthreads();
    }
    if (t == 0) {
        float mean = rs[0] * (1.f / NN);
        float var = fmaxf(rq[0] * (1.f / NN) - mean * mean, 0.f);
        float inv = rsqrtf(var + EPSB);
        float sc = inv * gamma[ch];
        scale[ch] = sc;
        shift[ch] = beta[ch] - mean * sc;
    }
}

// ---------------- final: relu(bn2(out2) + x) in NCHW ------------------------
__global__ __launch_bounds__(256)
void k_final(const float* __restrict__ x, float* __restrict__ out) {
    int i = blockIdx.x * 256 + threadIdx.x;
    int hw = i & 4095;
    int o = (i >> 12) & 255;
    int b = i >> 20;
    float v = fmaf(g_out2[(size_t)o * NN + b * HWW + hw], g_scale2[o], g_shift2[o]) + x[i];
    out[i] = fmaxf(v, 0.f);
}

// ---------------- launch -----------------------------------------------------
extern "C" void kernel_launch(void* const* d_in, const int* in_sizes, int n_in,
                              void* d_out, int out_size) {
    const float* x     = (const float*)d_in[0];
    const float* off_w = (const float*)d_in[1];
    const float* off_b = (const float*)d_in[2];
    const float* dw    = (const float*)d_in[3];
    const float* db    = (const float*)d_in[4];
    const float* bn1_g = (const float*)d_in[5];
    const float* bn1_b = (const float*)d_in[6];
    const float* w2    = (const float*)d_in[7];
    const float* bn2_g = (const float*)d_in[8];
    const float* bn2_b = (const float*)d_in[9];
    float* out = (float*)d_out;

    cudaFuncSetAttribute(k_gemm_mma, cudaFuncAttributeMaxDynamicSharedMemorySize, GEMM_SMEM);

    k_zero_offset<<<(BB * 18 * HWW + 255) / 256, 256>>>();
    k_offset_conv<<<dim3(64, 4), 256>>>(x, off_w, off_b);
    k_wprep<<<dim3((OO * CKK + 255) / 256, 2), 256>>>(dw, w2);
    k_im2col_deform<<<NN / 32, 256>>>(x);
    k_gemm_mma<<<dim3(2, 128), 256, GEMM_SMEM>>>(0, db, 0);
    k_bnstats<<<256, 256>>>(bn1_g, bn1_b, 0);
    k_im2col2<<<NN / 32, 256>>>();
    k_gemm_mma<<<dim3(2, 128), 256, GEMM_SMEM>>>(1, nullptr, 1);
    k_bnstats<<<256, 256>>>(bn2_g, bn2_b, 1);
    k_final<<<(BB * OO * HWW + 255) / 256, 256>>>(x, out);
}

// round 5
// speedup vs baseline: 1.8146x; 1.1332x over previous
#include <cuda_runtime.h>
#include <cuda_bf16.h>
#include <cstdint>

#define BB 4
#define CC 256
#define OO 256
#define HWW 4096
#define NN 16384          // BB*HWW
#define CKK 2304          // CC*9
#define K3 6912           // 3*CKK (bf16 split-triple K)
#define EPSB 1e-5f

#define NSTAGE 3
#define STAGE_SZ 32768      // A 16KB + B 16KB per stage (128 rows x 128B each)
#define GEMM_SMEM (NSTAGE * STAGE_SZ)
#define NUM_KCH 108         // K3*2 bytes / 128B per chunk

// ---------------- scratch (device globals; no allocs allowed) ----------------
__device__ float g_offset[BB * 18 * HWW];                       // 4.7 MB
__device__ __nv_bfloat16 g_colb[(size_t)NN * K3];               // 226 MB [n][k']
__device__ __nv_bfloat16 g_wA1[(size_t)OO * K3];                // 3.5 MB [m][k']
__device__ __nv_bfloat16 g_wA2[(size_t)OO * K3];
__device__ float g_out1[(size_t)OO * NN];                       // 16.8 MB [o][n]
__device__ float g_out2[(size_t)OO * NN];
__device__ __nv_bfloat16 g_out1b[(size_t)NN * 768];             // 25 MB [n][c*3+slot]
__device__ float g_scale1[OO], g_shift1[OO], g_scale2[OO], g_shift2[OO];

// ---------------- helpers ----------------------------------------------------
__device__ __forceinline__ uint32_t smem_u32(const void* p) {
    uint32_t a;
    asm("{ .reg .u64 t; cvta.to.shared.u64 t, %1; cvt.u32.u64 %0, t; }" : "=r"(a) : "l"(p));
    return a;
}
#define SWZ128(o) ((o) ^ (((o) >> 3) & 0x70))
#define CP_ASYNC16(dst, src) \
    asm volatile("cp.async.cg.shared.global [%0], [%1], 16;" :: "r"(dst), "l"(src))
#define CP_ASYNC16Z(dst, src, sz) \
    asm volatile("cp.async.cg.shared.global [%0], [%1], 16, %2;" :: "r"(dst), "l"(src), "r"(sz))
#define CP_COMMIT() asm volatile("cp.async.commit_group;" ::: "memory")
#define CP_WAIT2()  asm volatile("cp.async.wait_group 2;" ::: "memory")

#define LDSM4(r0, r1, r2, r3, addr) \
    asm volatile("ldmatrix.sync.aligned.m8n8.x4.shared.b16 {%0,%1,%2,%3}, [%4];" \
                 : "=r"(r0), "=r"(r1), "=r"(r2), "=r"(r3) : "r"(addr))

#define MMA16816(d, a0, a1, a2, a3, b0, b1) \
    asm volatile("mma.sync.aligned.m16n8k16.row.col.f32.bf16.bf16.f32 " \
                 "{%0,%1,%2,%3},{%4,%5,%6,%7},{%8,%9},{%0,%1,%2,%3};" \
                 : "+f"((d)[0]), "+f"((d)[1]), "+f"((d)[2]), "+f"((d)[3]) \
                 : "r"(a0), "r"(a1), "r"(a2), "r"(a3), "r"(b0), "r"(b1))

__device__ __forceinline__ unsigned short f2bf(float v) {
    __nv_bfloat16 h = __float2bfloat16_rn(v);
    return *reinterpret_cast<unsigned short*>(&h);
}

// ---------------- zero offset ------------------------------------------------
__global__ void k_zero_offset() {
    int i = blockIdx.x * 256 + threadIdx.x;
    if (i < BB * 18 * HWW) g_offset[i] = 0.f;
}

// ---------------- offset conv: 3x3, dil=2, pad=2, 256->18 -------------------
__global__ __launch_bounds__(256)
void k_offset_conv(const float* __restrict__ x, const float* __restrict__ off_w,
                   const float* __restrict__ off_b) {
    __shared__ float sw[18 * 64 * 9];
    int c0 = blockIdx.y * 64;
    for (int idx = threadIdx.x; idx < 18 * 64 * 9; idx += 256) {
        int oc = idx / 576;
        int rem = idx - oc * 576;
        sw[idx] = off_w[oc * CKK + c0 * 9 + rem];
    }
    __syncthreads();

    int n = blockIdx.x * 256 + threadIdx.x;
    int b = n >> 12, hw = n & 4095;
    int h = hw >> 6, w = hw & 63;

    float acc[18];
#pragma unroll
    for (int oc = 0; oc < 18; oc++) acc[oc] = 0.f;

    const float* xb = x + ((size_t)b * CC + c0) * HWW;
    for (int cc = 0; cc < 64; cc++) {
        const float* xc = xb + cc * HWW;
#pragma unroll
        for (int i = 0; i < 3; i++) {
            int y = h - 2 + 2 * i;
            if ((unsigned)y >= 64u) continue;
#pragma unroll
            for (int j = 0; j < 3; j++) {
                int xx = w - 2 + 2 * j;
                if ((unsigned)xx >= 64u) continue;
                float v = xc[(y << 6) + xx];
                const float* wp = &sw[cc * 9 + i * 3 + j];
#pragma unroll
                for (int oc = 0; oc < 18; oc++)
                    acc[oc] = fmaf(v, wp[oc * 576], acc[oc]);
            }
        }
    }
    float* op = g_offset + (size_t)b * 18 * HWW + hw;
    if (blockIdx.y == 0) {
#pragma unroll
        for (int oc = 0; oc < 18; oc++) atomicAdd(&op[oc * HWW], acc[oc] + off_b[oc]);
    } else {
#pragma unroll
        for (int oc = 0; oc < 18; oc++) atomicAdd(&op[oc * HWW], acc[oc]);
    }
}

// ---------------- weight prep: fp32 W -> split-triple bf16 A' ---------------
__global__ __launch_bounds__(256)
void k_wprep(const float* __restrict__ dw, const float* __restrict__ w2) {
    int idx = blockIdx.x * 256 + threadIdx.x;
    if (idx >= OO * CKK) return;
    int m = idx / CKK;
    int ck = idx - m * CKK;
    int c = ck / 9, kpt = ck - c * 9;
    const float* w = blockIdx.y ? w2 : dw;
    __nv_bfloat16* dst = blockIdx.y ? g_wA2 : g_wA1;
    float v = w[idx];
    unsigned short hi = f2bf(v);
    float hf = __bfloat162float(*reinterpret_cast<__nv_bfloat16*>(&hi));
    unsigned short lo = f2bf(v - hf);
    size_t p = (size_t)m * K3 + 3 * (kpt * 256 + c);
    unsigned short* d = reinterpret_cast<unsigned short*>(dst);
    d[p] = hi; d[p + 1] = lo; d[p + 2] = hi;
}

// ---------------- deformable im2col v3: conflict-free smem transpose --------
// grid (NN/32, 2): 32 pixels x 9 kpt x 128 channels per block.
#define STK 1057            // kpt stride: 1057 % 32 == 1 -> conflict-free
__global__ __launch_bounds__(256)
void k_im2col_deform(const float* __restrict__ x) {
    __shared__ float st[9 * STK + 1];   // [kpt*STK + cc*33 + px]
    __shared__ float4 wts[9][32];
    __shared__ int4 idxs[9][32];

    int n0 = blockIdx.x * 32;
    int b = n0 >> 12;
    int cbase = blockIdx.y * 128;

    for (int t = threadIdx.x; t < 288; t += 256) {
        int kpt = t >> 5, px = t & 31;
        int n = n0 + px;
        int hw = n & 4095;
        int h = hw >> 6, w = hw & 63;
        int ki = kpt / 3, kj = kpt - ki * 3;
        float offy = g_offset[((size_t)b * 18 + 2 * kpt) * HWW + hw];
        float offx = g_offset[((size_t)b * 18 + 2 * kpt + 1) * HWW + hw];
        float py = (float)(h - 2 + 2 * ki) + offy;
        float pxx = (float)(w - 2 + 2 * kj) + offx;
        float fy0 = floorf(py), fx0 = floorf(pxx);
        int y0 = (int)fy0, x0 = (int)fx0;
        int y1 = y0 + 1, x1 = x0 + 1;
        float wy1 = py - fy0, wx1 = pxx - fx0;
        float wy0 = 1.f - wy1, wx0 = 1.f - wx1;
        bool vy0 = (unsigned)y0 < 64u, vy1 = (unsigned)y1 < 64u;
        bool vx0 = (unsigned)x0 < 64u, vx1 = (unsigned)x1 < 64u;
        float w00 = (vy0 && vx0) ? wy0 * wx0 : 0.f;
        float w01 = (vy0 && vx1) ? wy0 * wx1 : 0.f;
        float w10 = (vy1 && vx0) ? wy1 * wx0 : 0.f;
        float w11 = (vy1 && vx1) ? wy1 * wx1 : 0.f;
        int yc0 = min(max(y0, 0), 63), yc1 = min(max(y1, 0), 63);
        int xc0 = min(max(x0, 0), 63), xc1 = min(max(x1, 0), 63);
        wts[kpt][px] = make_float4(w00, w01, w10, w11);
        idxs[kpt][px] = make_int4((yc0 << 6) + xc0, (yc0 << 6) + xc1,
                                  (yc1 << 6) + xc0, (yc1 << 6) + xc1);
    }
    __syncthreads();

    const float* xb = x + (size_t)b * CC * HWW;
    unsigned short* colbase = reinterpret_cast<unsigned short*>(g_colb);
    int wid = threadIdx.x >> 5, lane = threadIdx.x & 31;

    for (int cq = 0; cq < 4; cq++) {
        int c0 = cbase + cq * 32;
        // phase A: gather, lane = pixel
        for (int pair = wid; pair < 288; pair += 8) {
            int kpt = pair >> 5, cc = pair & 31;
            float4 wv = wts[kpt][lane];
            int4 iv = idxs[kpt][lane];
            const float* xp = xb + (size_t)(c0 + cc) * HWW;
            float v = wv.x * xp[iv.x] + wv.y * xp[iv.y] + wv.z * xp[iv.z] + wv.w * xp[iv.w];
            st[kpt * STK + cc * 33 + lane] = v;
        }
        __syncthreads();

        // phase B: split + coalesced writes. task = (px, kpt, q) -> 8 c = 48B
        for (int task = threadIdx.x; task < 1152; task += 256) {
            int q = task & 3;
            int rem = task >> 2;
            int kpt = rem % 9;
            int px = rem / 9;
            __align__(16) unsigned short buf[24];
#pragma unroll
            for (int j = 0; j < 8; j++) {
                float v = st[kpt * STK + (q * 8 + j) * 33 + px];
                unsigned short hi = f2bf(v);
                float hf = __bfloat162float(*reinterpret_cast<__nv_bfloat16*>(&hi));
                unsigned short lo = f2bf(v - hf);
                buf[j * 3] = hi; buf[j * 3 + 1] = hi; buf[j * 3 + 2] = lo;
            }
            uint4* dst = reinterpret_cast<uint4*>(
                colbase + (size_t)(n0 + px) * K3 + 3 * (kpt * 256 + c0 + q * 8));
            const uint4* s = reinterpret_cast<const uint4*>(buf);
            dst[0] = s[0]; dst[1] = s[1]; dst[2] = s[2];
        }
        __syncthreads();
    }
}

// ---------------- convert1: out1 -> pixel-major bf16 triples (BN1+ReLU) -----
// out1b[n][c*3+slot]; grid NN/32, 256 threads.
__global__ __launch_bounds__(256)
void k_convert1() {
    __shared__ float sv[64][33];
    __shared__ float sS[256], sH[256];
    int px0 = blockIdx.x * 32;
    int tid = threadIdx.x;
    for (int i = tid; i < 256; i += 256) { sS[i] = g_scale1[i]; sH[i] = g_shift1[i]; }
    __syncthreads();

    unsigned short* ob = reinterpret_cast<unsigned short*>(g_out1b);
    for (int c0 = 0; c0 < 256; c0 += 64) {
        for (int t = tid; t < 2048; t += 256) {
            int cc = t >> 5, lane = t & 31;
            float v = g_out1[(size_t)(c0 + cc) * NN + px0 + lane];
            sv[cc][lane] = fmaxf(fmaf(v, sS[c0 + cc], sH[c0 + cc]), 0.f);
        }
        __syncthreads();
        int px = tid >> 3, g = tid & 7;
        __align__(16) unsigned short buf[24];
#pragma unroll
        for (int j = 0; j < 8; j++) {
            float v = sv[g * 8 + j][px];
            unsigned short hi = f2bf(v);
            float hf = __bfloat162float(*reinterpret_cast<__nv_bfloat16*>(&hi));
            unsigned short lo = f2bf(v - hf);
            buf[j * 3] = hi; buf[j * 3 + 1] = hi; buf[j * 3 + 2] = lo;
        }
        uint4* dst = reinterpret_cast<uint4*>(ob + (size_t)(px0 + px) * 768 + (c0 + g * 8) * 3);
        const uint4* s = reinterpret_cast<const uint4*>(buf);
        dst[0] = s[0]; dst[1] = s[1]; dst[2] = s[2];
        __syncthreads();
    }
}

// ---------------- mma.sync bf16 GEMM; B explicit (col) or implicit (out1b) --
__global__ __launch_bounds__(256, 2)
void k_gemm_mma(int wsel, const float* __restrict__ bias, int outsel, int implicitB) {
    extern __shared__ char smem[];
    uint32_t sb = smem_u32(smem);
    int tid = threadIdx.x;
    int m0 = blockIdx.x * 128;
    int n0 = blockIdx.y * 128;

    const __nv_bfloat16* Ag = wsel ? g_wA2 : g_wA1;
    float* Cg = outsel ? g_out2 : g_out1;
    const char* Abase = reinterpret_cast<const char*>(Ag) + (size_t)m0 * (K3 * 2);
    const char* Bbase = reinterpret_cast<const char*>(g_colb) + (size_t)n0 * (K3 * 2);
    const char* Obase = reinterpret_cast<const char*>(g_out1b);

    auto load_stage = [&](int kc, int s) {
        uint32_t st = sb + s * STAGE_SZ;
        size_t kb = (size_t)kc * 128;
        if (!implicitB) {
#pragma unroll
            for (int i = 0; i < 8; i++) {
                int idx = tid + i * 256;
                if (idx < 1024) {
                    int r = idx >> 3, c = idx & 7;
                    uint32_t off = SWZ128(r * 128 + c * 16);
                    CP_ASYNC16(st + off, Abase + (size_t)r * (K3 * 2) + kb + c * 16);
                } else {
                    int j = idx - 1024;
                    int r = j >> 3, c = j & 7;
                    uint32_t off = SWZ128(r * 128 + c * 16);
                    CP_ASYNC16(st + 16384 + off, Bbase + (size_t)r * (K3 * 2) + kb + c * 16);
                }
            }
        } else {
            int kpt = kc / 12, part = kc - 12 * kpt;
            int ki = kpt / 3, kj = kpt - 3 * ki;
            int dn = (ki - 1) * 64 + (kj - 1);
#pragma unroll
            for (int i = 0; i < 8; i++) {
                int idx = tid + i * 256;
                if (idx < 1024) {
                    int r = idx >> 3, c = idx & 7;
                    uint32_t off = SWZ128(r * 128 + c * 16);
                    CP_ASYNC16(st + off, Abase + (size_t)r * (K3 * 2) + kb + c * 16);
                } else {
                    int j = idx - 1024;
                    int r = j >> 3, c = j & 7;
                    int n = n0 + r;
                    int h = (n >> 6) & 63, w = n & 63;
                    int y = h - 1 + ki, xw = w - 1 + kj;
                    bool valid = ((unsigned)y < 64u) && ((unsigned)xw < 64u);
                    int np = valid ? n + dn : 0;
                    uint32_t sz = valid ? 16u : 0u;
                    uint32_t off = SWZ128(r * 128 + c * 16);
                    CP_ASYNC16Z(st + 16384 + off,
                                Obase + (size_t)np * 1536 + part * 128 + c * 16, sz);
                }
            }
        }
        CP_COMMIT();
    };

    int lane = tid & 31, w = tid >> 5;
    int wm = w >> 1, wn = w & 1;
    int mW = wm * 32, nW = wn * 64;
    int gq = lane >> 3, rr = lane & 7;
    int rowin = (gq & 1) * 8 + rr;
    int kboff = (gq >> 1) * 16;

    float acc[2][8][4];
#pragma unroll
    for (int mt = 0; mt < 2; mt++)
#pragma unroll
        for (int j = 0; j < 8; j++)
#pragma unroll
            for (int q = 0; q < 4; q++) acc[mt][j][q] = 0.f;

    uint32_t aOff[2], aXor[2], bOff[4], bXor[4];
#pragma unroll
    for (int mt = 0; mt < 2; mt++) {
        int row = mW + mt * 16 + rowin;
        aOff[mt] = row * 128;
        aXor[mt] = (row & 7) << 4;
    }
#pragma unroll
    for (int nt = 0; nt < 4; nt++) {
        int row = nW + nt * 16 + rowin;
        bOff[nt] = row * 128;
        bXor[nt] = (row & 7) << 4;
    }

    load_stage(0, 0);
    load_stage(1, 1);
    load_stage(2, 2);

    for (int k = 0; k < NUM_KCH; k++) {
        int s = k % NSTAGE;
        uint32_t stA = sb + s * STAGE_SZ;
        uint32_t stB = stA + 16384;
        CP_WAIT2();
        __syncthreads();

#pragma unroll
        for (int ks = 0; ks < 4; ks++) {
            uint32_t kb = ks * 32 + kboff;
            uint32_t af[2][4], bf[4][4];
#pragma unroll
            for (int mt = 0; mt < 2; mt++)
                LDSM4(af[mt][0], af[mt][1], af[mt][2], af[mt][3],
                      stA + aOff[mt] + (kb ^ aXor[mt]));
#pragma unroll
            for (int nt = 0; nt < 4; nt++)
                LDSM4(bf[nt][0], bf[nt][1], bf[nt][2], bf[nt][3],
                      stB + bOff[nt] + (kb ^ bXor[nt]));
#pragma unroll
            for (int mt = 0; mt < 2; mt++)
#pragma unroll
                for (int j = 0; j < 8; j++) {
                    int q = j >> 1, hh = j & 1;
                    MMA16816(acc[mt][j], af[mt][0], af[mt][1], af[mt][2], af[mt][3],
                             bf[q][hh ? 1 : 0], bf[q][hh ? 3 : 2]);
                }
        }
        __syncthreads();
        if (k + 3 < NUM_KCH) load_stage(k + 3, s);
        else CP_COMMIT();
    }

    int qr = lane >> 2;
    int qc = (lane & 3) * 2;
#pragma unroll
    for (int mt = 0; mt < 2; mt++) {
        int row0 = m0 + mW + mt * 16 + qr;
        float bv0 = bias ? bias[row0] : 0.f;
        float bv1 = bias ? bias[row0 + 8] : 0.f;
#pragma unroll
        for (int j = 0; j < 8; j++) {
            int col = n0 + nW + j * 8 + qc;
            float2 v0 = make_float2(acc[mt][j][0] + bv0, acc[mt][j][1] + bv0);
            float2 v1 = make_float2(acc[mt][j][2] + bv1, acc[mt][j][3] + bv1);
            *reinterpret_cast<float2*>(Cg + (size_t)row0 * NN + col) = v0;
            *reinterpret_cast<float2*>(Cg + (size_t)(row0 + 8) * NN + col) = v1;
        }
    }
}

// ---------------- BN stats -> per-channel scale/shift ------------------------
__global__ __launch_bounds__(256)
void k_bnstats(const float* __restrict__ gamma, const float* __restrict__ beta, int sel) {
    const float* src = sel ? g_out2 : g_out1;
    float* scale = sel ? g_scale2 : g_scale1;
    float* shift = sel ? g_shift2 : g_shift1;
    int ch = blockIdx.x;
    const float* p = src + (size_t)ch * NN;
    float s = 0.f, sq = 0.f;
    for (int i = threadIdx.x; i < NN; i += 256) {
        float v = p[i];
        s += v;
        sq = fmaf(v, v, sq);
    }
    __shared__ float rs[256], rq[256];
    int t = threadIdx.x;
    rs[t] = s; rq[t] = sq;
    __syncthreads();
    for (int off = 128; off > 0; off >>= 1) {
        if (t < off) { rs[t] += rs[t + off]; rq[t] += rq[t + off]; }
        __syncthreads();
    }
    if (t == 0) {
        float mean = rs[0] * (1.f / NN);
        float var = fmaxf(rq[0] * (1.f / NN) - mean * mean, 0.f);
        float inv = rsqrtf(var + EPSB);
        float sc = inv * gamma[ch];
        scale[ch] = sc;
        shift[ch] = beta[ch] - mean * sc;
    }
}

// ---------------- final: relu(bn2(out2) + x) in NCHW ------------------------
__global__ __launch_bounds__(256)
void k_final(const float* __restrict__ x, float* __restrict__ out) {
    int i = blockIdx.x * 256 + threadIdx.x;
    int hw = i & 4095;
    int o = (i >> 12) & 255;
    int b = i >> 20;
    float v = fmaf(g_out2[(size_t)o * NN + b * HWW + hw], g_scale2[o], g_shift2[o]) + x[i];
    out[i] = fmaxf(v, 0.f);
}

// ---------------- launch -----------------------------------------------------
extern "C" void kernel_launch(void* const* d_in, const int* in_sizes, int n_in,
                              void* d_out, int out_size) {
    const float* x     = (const float*)d_in[0];
    const float* off_w = (const float*)d_in[1];
    const float* off_b = (const float*)d_in[2];
    const float* dw    = (const float*)d_in[3];
    const float* db    = (const float*)d_in[4];
    const float* bn1_g = (const float*)d_in[5];
    const float* bn1_b = (const float*)d_in[6];
    const float* w2    = (const float*)d_in[7];
    const float* bn2_g = (const float*)d_in[8];
    const float* bn2_b = (const float*)d_in[9];
    float* out = (float*)d_out;

    cudaFuncSetAttribute(k_gemm_mma, cudaFuncAttributeMaxDynamicSharedMemorySize, GEMM_SMEM);

    k_zero_offset<<<(BB * 18 * HWW + 255) / 256, 256>>>();
    k_offset_conv<<<dim3(64, 4), 256>>>(x, off_w, off_b);
    k_wprep<<<dim3((OO * CKK + 255) / 256, 2), 256>>>(dw, w2);
    k_im2col_deform<<<dim3(NN / 32, 2), 256>>>(x);
    k_gemm_mma<<<dim3(2, 128), 256, GEMM_SMEM>>>(0, db, 0, 0);
    k_bnstats<<<256, 256>>>(bn1_g, bn1_b, 0);
    k_convert1<<<NN / 32, 256>>>();
    k_gemm_mma<<<dim3(2, 128), 256, GEMM_SMEM>>>(1, nullptr, 1, 1);
    k_bnstats<<<256, 256>>>(bn2_g, bn2_b, 1);
    k_final<<<(BB * OO * HWW + 255) / 256, 256>>>(x, out);
}

// round 7
// speedup vs baseline: 2.1430x; 1.1810x over previous
#include <cuda_runtime.h>
#include <cuda_bf16.h>
#include <cstdint>

#define BB 4
#define CC 256
#define OO 256
#define HWW 4096
#define NN 16384          // BB*HWW
#define CKK 2304          // CC*9
#define K3 6912           // 3*CKK (virtual bf16 split-triple K)
#define EPSB 1e-5f

#define NSTAGE 3
#define STAGE_SZ 32768      // A 16KB + B 16KB per stage (128 rows x 128B each)
#define GEMM_SMEM (NSTAGE * STAGE_SZ)
#define NUM_KCH 108         // K3*2 bytes / 128B per chunk

// col row: per pixel 9 kpt x (hi 256 + lo 256) shorts = 4608 shorts = 9216 B
#define COLROW 4608
// out1b row: (hi 256 + lo 256) shorts = 1024 B
#define O1ROW 512

// ---------------- scratch (device globals; no allocs allowed) ----------------
__device__ float g_offset[BB * 18 * HWW];                       // 4.7 MB
__device__ float g_xpm[(size_t)NN * CC];                        // 64 MB NHWC x
__device__ __nv_bfloat16 g_colb[(size_t)NN * COLROW];           // 151 MB planar
__device__ __nv_bfloat16 g_wA1[(size_t)OO * K3];                // 3.5 MB [m][k']
__device__ __nv_bfloat16 g_wA2[(size_t)OO * K3];
__device__ float g_out1[(size_t)OO * NN];                       // 16.8 MB [o][n]
__device__ float g_out2[(size_t)OO * NN];
__device__ __nv_bfloat16 g_out1b[(size_t)NN * O1ROW];           // 16.8 MB planar
__device__ float g_scale1[OO], g_shift1[OO], g_scale2[OO], g_shift2[OO];

// ---------------- helpers ----------------------------------------------------
__device__ __forceinline__ uint32_t smem_u32(const void* p) {
    uint32_t a;
    asm("{ .reg .u64 t; cvta.to.shared.u64 t, %1; cvt.u32.u64 %0, t; }" : "=r"(a) : "l"(p));
    return a;
}
#define SWZ128(o) ((o) ^ (((o) >> 3) & 0x70))
#define CP_ASYNC16(dst, src) \
    asm volatile("cp.async.cg.shared.global [%0], [%1], 16;" :: "r"(dst), "l"(src))
#define CP_ASYNC16Z(dst, src, sz) \
    asm volatile("cp.async.cg.shared.global [%0], [%1], 16, %2;" :: "r"(dst), "l"(src), "r"(sz))
#define CP_COMMIT() asm volatile("cp.async.commit_group;" ::: "memory")
#define CP_WAIT2()  asm volatile("cp.async.wait_group 2;" ::: "memory")

#define LDSM4(r0, r1, r2, r3, addr) \
    asm volatile("ldmatrix.sync.aligned.m8n8.x4.shared.b16 {%0,%1,%2,%3}, [%4];" \
                 : "=r"(r0), "=r"(r1), "=r"(r2), "=r"(r3) : "r"(addr))

#define MMA16816(d, a0, a1, a2, a3, b0, b1) \
    asm volatile("mma.sync.aligned.m16n8k16.row.col.f32.bf16.bf16.f32 " \
                 "{%0,%1,%2,%3},{%4,%5,%6,%7},{%8,%9},{%0,%1,%2,%3};" \
                 : "+f"((d)[0]), "+f"((d)[1]), "+f"((d)[2]), "+f"((d)[3]) \
                 : "r"(a0), "r"(a1), "r"(a2), "r"(a3), "r"(b0), "r"(b1))

__device__ __forceinline__ unsigned short f2bf(float v) {
    __nv_bfloat16 h = __float2bfloat16_rn(v);
    return *reinterpret_cast<unsigned short*>(&h);
}
__device__ __forceinline__ void split_hl(float v, unsigned short& hi, unsigned short& lo) {
    hi = f2bf(v);
    float hf = __bfloat162float(*reinterpret_cast<__nv_bfloat16*>(&hi));
    lo = f2bf(v - hf);
}

// ---------------- zero offset ------------------------------------------------
__global__ void k_zero_offset() {
    int i = blockIdx.x * 256 + threadIdx.x;
    if (i < BB * 18 * HWW) g_offset[i] = 0.f;
}

// ---------------- transpose x: NCHW -> NHWC (g_xpm) -------------------------
// FIX vs R6: x is [B][C][HW]; decompose n into (b, hw) before indexing.
__global__ __launch_bounds__(256)
void k_transpose_x(const float* __restrict__ x) {
    __shared__ float t[32][33];
    int n0 = blockIdx.x * 32;
    int c0 = blockIdx.y * 32;
    int b = n0 >> 12;
    int hw0 = n0 & 4095;
    int lane = threadIdx.x & 31, wy = threadIdx.x >> 5;
#pragma unroll
    for (int j = 0; j < 4; j++) {
        int cc = wy + j * 8;
        t[cc][lane] = x[((size_t)b * CC + c0 + cc) * HWW + hw0 + lane];
    }
    __syncthreads();
#pragma unroll
    for (int j = 0; j < 4; j++) {
        int r = wy + j * 8;
        g_xpm[(size_t)(n0 + r) * CC + c0 + lane] = t[lane][r];
    }
}

// ---------------- offset conv: 3x3, dil=2, pad=2, 256->18 -------------------
__global__ __launch_bounds__(256)
void k_offset_conv(const float* __restrict__ x, const float* __restrict__ off_w,
                   const float* __restrict__ off_b) {
    __shared__ float sw[18 * 64 * 9];
    int c0 = blockIdx.y * 64;
    for (int idx = threadIdx.x; idx < 18 * 64 * 9; idx += 256) {
        int oc = idx / 576;
        int rem = idx - oc * 576;
        sw[idx] = off_w[oc * CKK + c0 * 9 + rem];
    }
    __syncthreads();

    int n = blockIdx.x * 256 + threadIdx.x;
    int b = n >> 12, hw = n & 4095;
    int h = hw >> 6, w = hw & 63;

    float acc[18];
#pragma unroll
    for (int oc = 0; oc < 18; oc++) acc[oc] = 0.f;

    const float* xb = x + ((size_t)b * CC + c0) * HWW;
    for (int cc = 0; cc < 64; cc++) {
        const float* xc = xb + cc * HWW;
#pragma unroll
        for (int i = 0; i < 3; i++) {
            int y = h - 2 + 2 * i;
            if ((unsigned)y >= 64u) continue;
#pragma unroll
            for (int j = 0; j < 3; j++) {
                int xx = w - 2 + 2 * j;
                if ((unsigned)xx >= 64u) continue;
                float v = xc[(y << 6) + xx];
                const float* wp = &sw[cc * 9 + i * 3 + j];
#pragma unroll
                for (int oc = 0; oc < 18; oc++)
                    acc[oc] = fmaf(v, wp[oc * 576], acc[oc]);
            }
        }
    }
    float* op = g_offset + (size_t)b * 18 * HWW + hw;
    if (blockIdx.y == 0) {
#pragma unroll
        for (int oc = 0; oc < 18; oc++) atomicAdd(&op[oc * HWW], acc[oc] + off_b[oc]);
    } else {
#pragma unroll
        for (int oc = 0; oc < 18; oc++) atomicAdd(&op[oc * HWW], acc[oc]);
    }
}

// ---------------- weight prep: fp32 W -> planar bf16 A' [hi|lo|hi] ----------
__global__ __launch_bounds__(256)
void k_wprep(const float* __restrict__ dw, const float* __restrict__ w2) {
    int idx = blockIdx.x * 256 + threadIdx.x;
    if (idx >= OO * CKK) return;
    int m = idx / CKK;
    int ck = idx - m * CKK;
    int c = ck / 9, kpt = ck - c * 9;
    const float* w = blockIdx.y ? w2 : dw;
    __nv_bfloat16* dst = blockIdx.y ? g_wA2 : g_wA1;
    float v = w[idx];
    unsigned short hi, lo;
    split_hl(v, hi, lo);
    size_t base = (size_t)m * K3 + kpt * 768;
    unsigned short* d = reinterpret_cast<unsigned short*>(dst);
    d[base + c] = hi;            // plane0: hi (pairs B hi)
    d[base + 256 + c] = lo;      // plane1: lo (pairs B hi)
    d[base + 512 + c] = hi;      // plane2: hi (pairs B lo)
}

// ---------------- deformable im2col v4: NHWC coalesced ----------------------
// grid NN/32: 32 pixels x 9 kpt x 256 c per block. warp per (px,kpt), lane=8c.
__global__ __launch_bounds__(256)
void k_im2col_deform() {
    __shared__ float4 wts[9][32];
    __shared__ int4 idxs[9][32];     // global pixel indices (include batch)

    int n0 = blockIdx.x * 32;
    int b = n0 >> 12;

    for (int t = threadIdx.x; t < 288; t += 256) {
        int kpt = t >> 5, px = t & 31;
        int n = n0 + px;
        int hw = n & 4095;
        int h = hw >> 6, w = hw & 63;
        int ki = kpt / 3, kj = kpt - ki * 3;
        float offy = g_offset[((size_t)b * 18 + 2 * kpt) * HWW + hw];
        float offx = g_offset[((size_t)b * 18 + 2 * kpt + 1) * HWW + hw];
        float py = (float)(h - 2 + 2 * ki) + offy;
        float pxx = (float)(w - 2 + 2 * kj) + offx;
        float fy0 = floorf(py), fx0 = floorf(pxx);
        int y0 = (int)fy0, x0 = (int)fx0;
        int y1 = y0 + 1, x1 = x0 + 1;
        float wy1 = py - fy0, wx1 = pxx - fx0;
        float wy0 = 1.f - wy1, wx0 = 1.f - wx1;
        bool vy0 = (unsigned)y0 < 64u, vy1 = (unsigned)y1 < 64u;
        bool vx0 = (unsigned)x0 < 64u, vx1 = (unsigned)x1 < 64u;
        float w00 = (vy0 && vx0) ? wy0 * wx0 : 0.f;
        float w01 = (vy0 && vx1) ? wy0 * wx1 : 0.f;
        float w10 = (vy1 && vx0) ? wy1 * wx0 : 0.f;
        float w11 = (vy1 && vx1) ? wy1 * wx1 : 0.f;
        int yc0 = min(max(y0, 0), 63), yc1 = min(max(y1, 0), 63);
        int xc0 = min(max(x0, 0), 63), xc1 = min(max(x1, 0), 63);
        int gb = b << 12;
        wts[kpt][px] = make_float4(w00, w01, w10, w11);
        idxs[kpt][px] = make_int4(gb + (yc0 << 6) + xc0, gb + (yc0 << 6) + xc1,
                                  gb + (yc1 << 6) + xc0, gb + (yc1 << 6) + xc1);
    }
    __syncthreads();

    int wid = threadIdx.x >> 5, lane = threadIdx.x & 31;
    int c8 = lane * 8;
    unsigned short* colbase = reinterpret_cast<unsigned short*>(g_colb);

    for (int task = wid; task < 288; task += 8) {
        int kpt = task >> 5, px = task & 31;
        float4 wv = wts[kpt][px];
        int4 iv = idxs[kpt][px];
        const float4* p00 = reinterpret_cast<const float4*>(g_xpm + (size_t)iv.x * CC + c8);
        const float4* p01 = reinterpret_cast<const float4*>(g_xpm + (size_t)iv.y * CC + c8);
        const float4* p10 = reinterpret_cast<const float4*>(g_xpm + (size_t)iv.z * CC + c8);
        const float4* p11 = reinterpret_cast<const float4*>(g_xpm + (size_t)iv.w * CC + c8);
        float4 a0 = p00[0], a1 = p00[1];
        float4 b0 = p01[0], b1 = p01[1];
        float4 c0v = p10[0], c1 = p10[1];
        float4 d0 = p11[0], d1 = p11[1];
        float v[8];
        v[0] = wv.x * a0.x + wv.y * b0.x + wv.z * c0v.x + wv.w * d0.x;
        v[1] = wv.x * a0.y + wv.y * b0.y + wv.z * c0v.y + wv.w * d0.y;
        v[2] = wv.x * a0.z + wv.y * b0.z + wv.z * c0v.z + wv.w * d0.z;
        v[3] = wv.x * a0.w + wv.y * b0.w + wv.z * c0v.w + wv.w * d0.w;
        v[4] = wv.x * a1.x + wv.y * b1.x + wv.z * c1.x + wv.w * d1.x;
        v[5] = wv.x * a1.y + wv.y * b1.y + wv.z * c1.y + wv.w * d1.y;
        v[6] = wv.x * a1.z + wv.y * b1.z + wv.z * c1.z + wv.w * d1.z;
        v[7] = wv.x * a1.w + wv.y * b1.w + wv.z * c1.w + wv.w * d1.w;
        __align__(16) unsigned short his[8], los[8];
#pragma unroll
        for (int j = 0; j < 8; j++) split_hl(v[j], his[j], los[j]);
        unsigned short* row = colbase + (size_t)(n0 + px) * COLROW + kpt * 512;
        *reinterpret_cast<uint4*>(row + c8) = *reinterpret_cast<const uint4*>(his);
        *reinterpret_cast<uint4*>(row + 256 + c8) = *reinterpret_cast<const uint4*>(los);
    }
}

// ---------------- convert1: out1 -> pixel-major planar bf16 (BN1+ReLU) ------
__global__ __launch_bounds__(256)
void k_convert1() {
    __shared__ float t[64][33];
    __shared__ float sS[256], sH[256];
    int px0 = blockIdx.x * 32;
    int tid = threadIdx.x;
    int lane = tid & 31, wy = tid >> 5;
    for (int i = tid; i < 256; i += 256) { sS[i] = g_scale1[i]; sH[i] = g_shift1[i]; }
    __syncthreads();

    unsigned short* ob = reinterpret_cast<unsigned short*>(g_out1b);
    for (int c0 = 0; c0 < 256; c0 += 64) {
#pragma unroll
        for (int j = 0; j < 8; j++) {
            int cc = wy * 8 + j;
            t[cc][lane] = g_out1[(size_t)(c0 + cc) * NN + px0 + lane];
        }
        __syncthreads();
        int px = tid >> 3, g = tid & 7;
        __align__(16) unsigned short his[8], los[8];
#pragma unroll
        for (int j = 0; j < 8; j++) {
            int cc = g * 8 + j;
            float v = fmaxf(fmaf(t[cc][px], sS[c0 + cc], sH[c0 + cc]), 0.f);
            split_hl(v, his[j], los[j]);
        }
        unsigned short* row = ob + (size_t)(px0 + px) * O1ROW;
        *reinterpret_cast<uint4*>(row + c0 + g * 8) = *reinterpret_cast<const uint4*>(his);
        *reinterpret_cast<uint4*>(row + 256 + c0 + g * 8) = *reinterpret_cast<const uint4*>(los);
        __syncthreads();
    }
}

// ---------------- mma.sync bf16 GEMM; B from colb (planar) or out1b ---------
__global__ __launch_bounds__(256, 2)
void k_gemm_mma(int wsel, const float* __restrict__ bias, int outsel, int implicitB) {
    extern __shared__ char smem[];
    uint32_t sb = smem_u32(smem);
    int tid = threadIdx.x;
    int m0 = blockIdx.x * 128;
    int n0 = blockIdx.y * 128;

    const __nv_bfloat16* Ag = wsel ? g_wA2 : g_wA1;
    float* Cg = outsel ? g_out2 : g_out1;
    const char* Abase = reinterpret_cast<const char*>(Ag) + (size_t)m0 * (K3 * 2);
    const char* Bbase = reinterpret_cast<const char*>(g_colb) + (size_t)n0 * (COLROW * 2);
    const char* Obase = reinterpret_cast<const char*>(g_out1b);

    auto load_stage = [&](int kc, int s) {
        uint32_t st = sb + s * STAGE_SZ;
        size_t kb = (size_t)kc * 128;
        int kpt = kc / 12, part = kc - 12 * kpt;
        uint32_t srcoff = ((uint32_t)(part >> 3) << 9) + ((uint32_t)(part & 3) << 7);
        if (!implicitB) {
#pragma unroll
            for (int i = 0; i < 8; i++) {
                int idx = tid + i * 256;
                if (idx < 1024) {
                    int r = idx >> 3, c = idx & 7;
                    uint32_t off = SWZ128(r * 128 + c * 16);
                    CP_ASYNC16(st + off, Abase + (size_t)r * (K3 * 2) + kb + c * 16);
                } else {
                    int j = idx - 1024;
                    int r = j >> 3, c = j & 7;
                    uint32_t off = SWZ128(r * 128 + c * 16);
                    CP_ASYNC16(st + 16384 + off,
                               Bbase + (size_t)r * (COLROW * 2) + kpt * 1024 + srcoff + c * 16);
                }
            }
        } else {
            int ki = kpt / 3, kj = kpt - 3 * ki;
            int dn = (ki - 1) * 64 + (kj - 1);
#pragma unroll
            for (int i = 0; i < 8; i++) {
                int idx = tid + i * 256;
                if (idx < 1024) {
                    int r = idx >> 3, c = idx & 7;
                    uint32_t off = SWZ128(r * 128 + c * 16);
                    CP_ASYNC16(st + off, Abase + (size_t)r * (K3 * 2) + kb + c * 16);
                } else {
                    int j = idx - 1024;
                    int r = j >> 3, c = j & 7;
                    int n = n0 + r;
                    int h = (n >> 6) & 63, w = n & 63;
                    int y = h - 1 + ki, xw = w - 1 + kj;
                    bool valid = ((unsigned)y < 64u) && ((unsigned)xw < 64u);
                    int np = valid ? n + dn : 0;
                    uint32_t sz = valid ? 16u : 0u;
                    uint32_t off = SWZ128(r * 128 + c * 16);
                    CP_ASYNC16Z(st + 16384 + off,
                                Obase + (size_t)np * 1024 + srcoff + c * 16, sz);
                }
            }
        }
        CP_COMMIT();
    };

    int lane = tid & 31, w = tid >> 5;
    int wm = w >> 1, wn = w & 1;
    int mW = wm * 32, nW = wn * 64;
    int gq = lane >> 3, rr = lane & 7;
    int rowin = (gq & 1) * 8 + rr;
    int kboff = (gq >> 1) * 16;

    float acc[2][8][4];
#pragma unroll
    for (int mt = 0; mt < 2; mt++)
#pragma unroll
        for (int j = 0; j < 8; j++)
#pragma unroll
            for (int q = 0; q < 4; q++) acc[mt][j][q] = 0.f;

    uint32_t aOff[2], aXor[2], bOff[4], bXor[4];
#pragma unroll
    for (int mt = 0; mt < 2; mt++) {
        int row = mW + mt * 16 + rowin;
        aOff[mt] = row * 128;
        aXor[mt] = (row & 7) << 4;
    }
#pragma unroll
    for (int nt = 0; nt < 4; nt++) {
        int row = nW + nt * 16 + rowin;
        bOff[nt] = row * 128;
        bXor[nt] = (row & 7) << 4;
    }

    load_stage(0, 0);
    load_stage(1, 1);
    load_stage(2, 2);

    for (int k = 0; k < NUM_KCH; k++) {
        int s = k % NSTAGE;
        uint32_t stA = sb + s * STAGE_SZ;
        uint32_t stB = stA + 16384;
        CP_WAIT2();
        __syncthreads();

#pragma unroll
        for (int ks = 0; ks < 4; ks++) {
            uint32_t kb = ks * 32 + kboff;
            uint32_t af[2][4], bf[4][4];
#pragma unroll
            for (int mt = 0; mt < 2; mt++)
                LDSM4(af[mt][0], af[mt][1], af[mt][2], af[mt][3],
                      stA + aOff[mt] + (kb ^ aXor[mt]));
#pragma unroll
            for (int nt = 0; nt < 4; nt++)
                LDSM4(bf[nt][0], bf[nt][1], bf[nt][2], bf[nt][3],
                      stB + bOff[nt] + (kb ^ bXor[nt]));
#pragma unroll
            for (int mt = 0; mt < 2; mt++)
#pragma unroll
                for (int j = 0; j < 8; j++) {
                    int q = j >> 1, hh = j & 1;
                    MMA16816(acc[mt][j], af[mt][0], af[mt][1], af[mt][2], af[mt][3],
                             bf[q][hh ? 1 : 0], bf[q][hh ? 3 : 2]);
                }
        }
        __syncthreads();
        if (k + 3 < NUM_KCH) load_stage(k + 3, s);
        else CP_COMMIT();
    }

    int qr = lane >> 2;
    int qc = (lane & 3) * 2;
#pragma unroll
    for (int mt = 0; mt < 2; mt++) {
        int row0 = m0 + mW + mt * 16 + qr;
        float bv0 = bias ? bias[row0] : 0.f;
        float bv1 = bias ? bias[row0 + 8] : 0.f;
#pragma unroll
        for (int j = 0; j < 8; j++) {
            int col = n0 + nW + j * 8 + qc;
            float2 v0 = make_float2(acc[mt][j][0] + bv0, acc[mt][j][1] + bv0);
            float2 v1 = make_float2(acc[mt][j][2] + bv1, acc[mt][j][3] + bv1);
            *reinterpret_cast<float2*>(Cg + (size_t)row0 * NN + col) = v0;
            *reinterpret_cast<float2*>(Cg + (size_t)(row0 + 8) * NN + col) = v1;
        }
    }
}

// ---------------- BN stats -> per-channel scale/shift ------------------------
__global__ __launch_bounds__(256)
void k_bnstats(const float* __restrict__ gamma, const float* __restrict__ beta, int sel) {
    const float* src = sel ? g_out2 : g_out1;
    float* scale = sel ? g_scale2 : g_scale1;
    float* shift = sel ? g_shift2 : g_shift1;
    int ch = blockIdx.x;
    const float* p = src + (size_t)ch * NN;
    float s = 0.f, sq = 0.f;
    for (int i = threadIdx.x; i < NN; i += 256) {
        float v = p[i];
        s += v;
        sq = fmaf(v, v, sq);
    }
    __shared__ float rs[256], rq[256];
    int t = threadIdx.x;
    rs[t] = s; rq[t] = sq;
    __syncthreads();
    for (int off = 128; off > 0; off >>= 1) {
        if (t < off) { rs[t] += rs[t + off]; rq[t] += rq[t + off]; }
        __syncthreads();
    }
    if (t == 0) {
        float mean = rs[0] * (1.f / NN);
        float var = fmaxf(rq[0] * (1.f / NN) - mean * mean, 0.f);
        float inv = rsqrtf(var + EPSB);
        float sc = inv * gamma[ch];
        scale[ch] = sc;
        shift[ch] = beta[ch] - mean * sc;
    }
}

// ---------------- final: relu(bn2(out2) + x) in NCHW ------------------------
__global__ __launch_bounds__(256)
void k_final(const float* __restrict__ x, float* __restrict__ out) {
    int i = blockIdx.x * 256 + threadIdx.x;
    int hw = i & 4095;
    int o = (i >> 12) & 255;
    int b = i >> 20;
    float v = fmaf(g_out2[(size_t)o * NN + b * HWW + hw], g_scale2[o], g_shift2[o]) + x[i];
    out[i] = fmaxf(v, 0.f);
}

// ---------------- launch -----------------------------------------------------
extern "C" void kernel_launch(void* const* d_in, const int* in_sizes, int n_in,
                              void* d_out, int out_size) {
    const float* x     = (const float*)d_in[0];
    const float* off_w = (const float*)d_in[1];
    const float* off_b = (const float*)d_in[2];
    const float* dw    = (const float*)d_in[3];
    const float* db    = (const float*)d_in[4];
    const float* bn1_g = (const float*)d_in[5];
    const float* bn1_b = (const float*)d_in[6];
    const float* w2    = (const float*)d_in[7];
    const float* bn2_g = (const float*)d_in[8];
    const float* bn2_b = (const float*)d_in[9];
    float* out = (float*)d_out;

    cudaFuncSetAttribute(k_gemm_mma, cudaFuncAttributeMaxDynamicSharedMemorySize, GEMM_SMEM);

    k_zero_offset<<<(BB * 18 * HWW + 255) / 256, 256>>>();
    k_transpose_x<<<dim3(NN / 32, 8), 256>>>(x);
    k_offset_conv<<<dim3(64, 4), 256>>>(x, off_w, off_b);
    k_wprep<<<dim3((OO * CKK + 255) / 256, 2), 256>>>(dw, w2);
    k_im2col_deform<<<NN / 32, 256>>>();
    k_gemm_mma<<<dim3(2, 128), 256, GEMM_SMEM>>>(0, db, 0, 0);
    k_bnstats<<<256, 256>>>(bn1_g, bn1_b, 0);
    k_convert1<<<NN / 32, 256>>>();
    k_gemm_mma<<<dim3(2, 128), 256, GEMM_SMEM>>>(1, nullptr, 1, 1);
    k_bnstats<<<256, 256>>>(bn2_g, bn2_b, 1);
    k_final<<<(BB * OO * HWW + 255) / 256, 256>>>(x, out);
}

// round 8
// speedup vs baseline: 2.1492x; 1.0029x over previous
#include <cuda_runtime.h>
#include <cuda_bf16.h>
#include <cstdint>

#define BB 4
#define CC 256
#define OO 256
#define HWW 4096
#define NN 16384          // BB*HWW
#define CKK 2304          // CC*9
#define K3 6912           // 3*CKK (virtual bf16 split-triple K)
#define EPSB 1e-5f

#define NSTAGE 3
#define STAGE_SZ 49152      // A 16KB + B 32KB per stage
#define GEMM_SMEM (NSTAGE * STAGE_SZ)
#define NUM_KCH 108         // K3*2 bytes / 128B per chunk

// col row: per pixel 9 kpt x (hi 256 + lo 256) shorts = 4608 shorts = 9216 B
#define COLROW 4608
// out1b row: (hi 256 + lo 256) shorts = 1024 B
#define O1ROW 512

// ---------------- scratch (device globals; no allocs allowed) ----------------
__device__ float g_offset[BB * 18 * HWW];                       // 4.7 MB
__device__ float g_xpm[(size_t)NN * CC];                        // 64 MB NHWC x
__device__ __nv_bfloat16 g_colb[(size_t)NN * COLROW];           // 151 MB planar
__device__ __nv_bfloat16 g_wA1[(size_t)OO * K3];                // 3.5 MB [m][k']
__device__ __nv_bfloat16 g_wA2[(size_t)OO * K3];
__device__ float g_out1[(size_t)OO * NN];                       // 16.8 MB [o][n]
__device__ float g_out2[(size_t)OO * NN];
__device__ __nv_bfloat16 g_out1b[(size_t)NN * O1ROW];           // 16.8 MB planar
__device__ float g_scale1[OO], g_shift1[OO], g_scale2[OO], g_shift2[OO];

// ---------------- helpers ----------------------------------------------------
__device__ __forceinline__ uint32_t smem_u32(const void* p) {
    uint32_t a;
    asm("{ .reg .u64 t; cvta.to.shared.u64 t, %1; cvt.u32.u64 %0, t; }" : "=r"(a) : "l"(p));
    return a;
}
#define SWZ128(o) ((o) ^ (((o) >> 3) & 0x70))
#define CP_ASYNC16(dst, src) \
    asm volatile("cp.async.cg.shared.global [%0], [%1], 16;" :: "r"(dst), "l"(src))
#define CP_ASYNC16Z(dst, src, sz) \
    asm volatile("cp.async.cg.shared.global [%0], [%1], 16, %2;" :: "r"(dst), "l"(src), "r"(sz))
#define CP_COMMIT() asm volatile("cp.async.commit_group;" ::: "memory")
#define CP_WAIT2()  asm volatile("cp.async.wait_group 2;" ::: "memory")

#define LDSM4(r0, r1, r2, r3, addr) \
    asm volatile("ldmatrix.sync.aligned.m8n8.x4.shared.b16 {%0,%1,%2,%3}, [%4];" \
                 : "=r"(r0), "=r"(r1), "=r"(r2), "=r"(r3) : "r"(addr))

#define MMA16816(d, a0, a1, a2, a3, b0, b1) \
    asm volatile("mma.sync.aligned.m16n8k16.row.col.f32.bf16.bf16.f32 " \
                 "{%0,%1,%2,%3},{%4,%5,%6,%7},{%8,%9},{%0,%1,%2,%3};" \
                 : "+f"((d)[0]), "+f"((d)[1]), "+f"((d)[2]), "+f"((d)[3]) \
                 : "r"(a0), "r"(a1), "r"(a2), "r"(a3), "r"(b0), "r"(b1))

__device__ __forceinline__ unsigned short f2bf(float v) {
    __nv_bfloat16 h = __float2bfloat16_rn(v);
    return *reinterpret_cast<unsigned short*>(&h);
}
__device__ __forceinline__ void split_hl(float v, unsigned short& hi, unsigned short& lo) {
    hi = f2bf(v);
    float hf = __bfloat162float(*reinterpret_cast<__nv_bfloat16*>(&hi));
    lo = f2bf(v - hf);
}

// ---------------- zero offset ------------------------------------------------
__global__ void k_zero_offset() {
    int i = blockIdx.x * 256 + threadIdx.x;
    if (i < BB * 18 * HWW) g_offset[i] = 0.f;
}

// ---------------- transpose x: NCHW -> NHWC (g_xpm) -------------------------
__global__ __launch_bounds__(256)
void k_transpose_x(const float* __restrict__ x) {
    __shared__ float t[32][33];
    int n0 = blockIdx.x * 32;
    int c0 = blockIdx.y * 32;
    int b = n0 >> 12;
    int hw0 = n0 & 4095;
    int lane = threadIdx.x & 31, wy = threadIdx.x >> 5;
#pragma unroll
    for (int j = 0; j < 4; j++) {
        int cc = wy + j * 8;
        t[cc][lane] = x[((size_t)b * CC + c0 + cc) * HWW + hw0 + lane];
    }
    __syncthreads();
#pragma unroll
    for (int j = 0; j < 4; j++) {
        int r = wy + j * 8;
        g_xpm[(size_t)(n0 + r) * CC + c0 + lane] = t[lane][r];
    }
}

// ---------------- offset conv: 3x3, dil=2, pad=2, 256->18 -------------------
__global__ __launch_bounds__(256)
void k_offset_conv(const float* __restrict__ x, const float* __restrict__ off_w,
                   const float* __restrict__ off_b) {
    __shared__ float sw[18 * 64 * 9];
    int c0 = blockIdx.y * 64;
    for (int idx = threadIdx.x; idx < 18 * 64 * 9; idx += 256) {
        int oc = idx / 576;
        int rem = idx - oc * 576;
        sw[idx] = off_w[oc * CKK + c0 * 9 + rem];
    }
    __syncthreads();

    int n = blockIdx.x * 256 + threadIdx.x;
    int b = n >> 12, hw = n & 4095;
    int h = hw >> 6, w = hw & 63;

    float acc[18];
#pragma unroll
    for (int oc = 0; oc < 18; oc++) acc[oc] = 0.f;

    const float* xb = x + ((size_t)b * CC + c0) * HWW;
    for (int cc = 0; cc < 64; cc++) {
        const float* xc = xb + cc * HWW;
#pragma unroll
        for (int i = 0; i < 3; i++) {
            int y = h - 2 + 2 * i;
            if ((unsigned)y >= 64u) continue;
#pragma unroll
            for (int j = 0; j < 3; j++) {
                int xx = w - 2 + 2 * j;
                if ((unsigned)xx >= 64u) continue;
                float v = xc[(y << 6) + xx];
                const float* wp = &sw[cc * 9 + i * 3 + j];
#pragma unroll
                for (int oc = 0; oc < 18; oc++)
                    acc[oc] = fmaf(v, wp[oc * 576], acc[oc]);
            }
        }
    }
    float* op = g_offset + (size_t)b * 18 * HWW + hw;
    if (blockIdx.y == 0) {
#pragma unroll
        for (int oc = 0; oc < 18; oc++) atomicAdd(&op[oc * HWW], acc[oc] + off_b[oc]);
    } else {
#pragma unroll
        for (int oc = 0; oc < 18; oc++) atomicAdd(&op[oc * HWW], acc[oc]);
    }
}

// ---------------- weight prep: fp32 W -> planar bf16 A' [hi|lo|hi] ----------
__global__ __launch_bounds__(256)
void k_wprep(const float* __restrict__ dw, const float* __restrict__ w2) {
    int idx = blockIdx.x * 256 + threadIdx.x;
    if (idx >= OO * CKK) return;
    int m = idx / CKK;
    int ck = idx - m * CKK;
    int c = ck / 9, kpt = ck - c * 9;
    const float* w = blockIdx.y ? w2 : dw;
    __nv_bfloat16* dst = blockIdx.y ? g_wA2 : g_wA1;
    float v = w[idx];
    unsigned short hi, lo;
    split_hl(v, hi, lo);
    size_t base = (size_t)m * K3 + kpt * 768;
    unsigned short* d = reinterpret_cast<unsigned short*>(dst);
    d[base + c] = hi;            // plane0: hi (pairs B hi)
    d[base + 256 + c] = lo;      // plane1: lo (pairs B hi)
    d[base + 512 + c] = hi;      // plane2: hi (pairs B lo)
}

// ---------------- deformable im2col v4: NHWC coalesced ----------------------
__global__ __launch_bounds__(256)
void k_im2col_deform() {
    __shared__ float4 wts[9][32];
    __shared__ int4 idxs[9][32];

    int n0 = blockIdx.x * 32;
    int b = n0 >> 12;

    for (int t = threadIdx.x; t < 288; t += 256) {
        int kpt = t >> 5, px = t & 31;
        int n = n0 + px;
        int hw = n & 4095;
        int h = hw >> 6, w = hw & 63;
        int ki = kpt / 3, kj = kpt - ki * 3;
        float offy = g_offset[((size_t)b * 18 + 2 * kpt) * HWW + hw];
        float offx = g_offset[((size_t)b * 18 + 2 * kpt + 1) * HWW + hw];
        float py = (float)(h - 2 + 2 * ki) + offy;
        float pxx = (float)(w - 2 + 2 * kj) + offx;
        float fy0 = floorf(py), fx0 = floorf(pxx);
        int y0 = (int)fy0, x0 = (int)fx0;
        int y1 = y0 + 1, x1 = x0 + 1;
        float wy1 = py - fy0, wx1 = pxx - fx0;
        float wy0 = 1.f - wy1, wx0 = 1.f - wx1;
        bool vy0 = (unsigned)y0 < 64u, vy1 = (unsigned)y1 < 64u;
        bool vx0 = (unsigned)x0 < 64u, vx1 = (unsigned)x1 < 64u;
        float w00 = (vy0 && vx0) ? wy0 * wx0 : 0.f;
        float w01 = (vy0 && vx1) ? wy0 * wx1 : 0.f;
        float w10 = (vy1 && vx0) ? wy1 * wx0 : 0.f;
        float w11 = (vy1 && vx1) ? wy1 * wx1 : 0.f;
        int yc0 = min(max(y0, 0), 63), yc1 = min(max(y1, 0), 63);
        int xc0 = min(max(x0, 0), 63), xc1 = min(max(x1, 0), 63);
        int gb = b << 12;
        wts[kpt][px] = make_float4(w00, w01, w10, w11);
        idxs[kpt][px] = make_int4(gb + (yc0 << 6) + xc0, gb + (yc0 << 6) + xc1,
                                  gb + (yc1 << 6) + xc0, gb + (yc1 << 6) + xc1);
    }
    __syncthreads();

    int wid = threadIdx.x >> 5, lane = threadIdx.x & 31;
    int c8 = lane * 8;
    unsigned short* colbase = reinterpret_cast<unsigned short*>(g_colb);

    for (int task = wid; task < 288; task += 8) {
        int kpt = task >> 5, px = task & 31;
        float4 wv = wts[kpt][px];
        int4 iv = idxs[kpt][px];
        const float4* p00 = reinterpret_cast<const float4*>(g_xpm + (size_t)iv.x * CC + c8);
        const float4* p01 = reinterpret_cast<const float4*>(g_xpm + (size_t)iv.y * CC + c8);
        const float4* p10 = reinterpret_cast<const float4*>(g_xpm + (size_t)iv.z * CC + c8);
        const float4* p11 = reinterpret_cast<const float4*>(g_xpm + (size_t)iv.w * CC + c8);
        float4 a0 = p00[0], a1 = p00[1];
        float4 b0 = p01[0], b1 = p01[1];
        float4 c0v = p10[0], c1 = p10[1];
        float4 d0 = p11[0], d1 = p11[1];
        float v[8];
        v[0] = wv.x * a0.x + wv.y * b0.x + wv.z * c0v.x + wv.w * d0.x;
        v[1] = wv.x * a0.y + wv.y * b0.y + wv.z * c0v.y + wv.w * d0.y;
        v[2] = wv.x * a0.z + wv.y * b0.z + wv.z * c0v.z + wv.w * d0.z;
        v[3] = wv.x * a0.w + wv.y * b0.w + wv.z * c0v.w + wv.w * d0.w;
        v[4] = wv.x * a1.x + wv.y * b1.x + wv.z * c1.x + wv.w * d1.x;
        v[5] = wv.x * a1.y + wv.y * b1.y + wv.z * c1.y + wv.w * d1.y;
        v[6] = wv.x * a1.z + wv.y * b1.z + wv.z * c1.z + wv.w * d1.z;
        v[7] = wv.x * a1.w + wv.y * b1.w + wv.z * c1.w + wv.w * d1.w;
        __align__(16) unsigned short his[8], los[8];
#pragma unroll
        for (int j = 0; j < 8; j++) split_hl(v[j], his[j], los[j]);
        unsigned short* row = colbase + (size_t)(n0 + px) * COLROW + kpt * 512;
        *reinterpret_cast<uint4*>(row + c8) = *reinterpret_cast<const uint4*>(his);
        *reinterpret_cast<uint4*>(row + 256 + c8) = *reinterpret_cast<const uint4*>(los);
    }
}

// ---------------- convert1: out1 -> pixel-major planar bf16 (BN1+ReLU) ------
__global__ __launch_bounds__(256)
void k_convert1() {
    __shared__ float t[64][33];
    __shared__ float sS[256], sH[256];
    int px0 = blockIdx.x * 32;
    int tid = threadIdx.x;
    int lane = tid & 31, wy = tid >> 5;
    for (int i = tid; i < 256; i += 256) { sS[i] = g_scale1[i]; sH[i] = g_shift1[i]; }
    __syncthreads();

    unsigned short* ob = reinterpret_cast<unsigned short*>(g_out1b);
    for (int c0 = 0; c0 < 256; c0 += 64) {
#pragma unroll
        for (int j = 0; j < 8; j++) {
            int cc = wy * 8 + j;
            t[cc][lane] = g_out1[(size_t)(c0 + cc) * NN + px0 + lane];
        }
        __syncthreads();
        int px = tid >> 3, g = tid & 7;
        __align__(16) unsigned short his[8], los[8];
#pragma unroll
        for (int j = 0; j < 8; j++) {
            int cc = g * 8 + j;
            float v = fmaxf(fmaf(t[cc][px], sS[c0 + cc], sH[c0 + cc]), 0.f);
            split_hl(v, his[j], los[j]);
        }
        unsigned short* row = ob + (size_t)(px0 + px) * O1ROW;
        *reinterpret_cast<uint4*>(row + c0 + g * 8) = *reinterpret_cast<const uint4*>(his);
        *reinterpret_cast<uint4*>(row + 256 + c0 + g * 8) = *reinterpret_cast<const uint4*>(los);
        __syncthreads();
    }
}

// ---------------- mma.sync bf16 GEMM, CTA tile 128x256 ----------------------
// grid (2, 64): x = m-tile (128 rows), y = n-tile (256 pixels). 8 warps 4x2,
// warp tile 32x128.
__global__ __launch_bounds__(256, 1)
void k_gemm_mma(int wsel, const float* __restrict__ bias, int outsel, int implicitB) {
    extern __shared__ char smem[];
    uint32_t sb = smem_u32(smem);
    int tid = threadIdx.x;
    int m0 = blockIdx.x * 128;
    int n0 = blockIdx.y * 256;

    const __nv_bfloat16* Ag = wsel ? g_wA2 : g_wA1;
    float* Cg = outsel ? g_out2 : g_out1;
    const char* Abase = reinterpret_cast<const char*>(Ag) + (size_t)m0 * (K3 * 2);
    const char* Bbase = reinterpret_cast<const char*>(g_colb) + (size_t)n0 * (COLROW * 2);
    const char* Obase = reinterpret_cast<const char*>(g_out1b);

    // stage: A 1024 chunks (128 rows x 8), B 2048 chunks (256 rows x 8) = 3072
    auto load_stage = [&](int kc, int s) {
        uint32_t st = sb + s * STAGE_SZ;
        size_t kb = (size_t)kc * 128;
        int kpt = kc / 12, part = kc - 12 * kpt;
        uint32_t srcoff = ((uint32_t)(part >> 3) << 9) + ((uint32_t)(part & 3) << 7);
        if (!implicitB) {
#pragma unroll
            for (int i = 0; i < 12; i++) {
                int idx = tid + i * 256;
                if (idx < 1024) {
                    int r = idx >> 3, c = idx & 7;
                    uint32_t off = SWZ128(r * 128 + c * 16);
                    CP_ASYNC16(st + off, Abase + (size_t)r * (K3 * 2) + kb + c * 16);
                } else {
                    int j = idx - 1024;
                    int r = j >> 3, c = j & 7;
                    uint32_t off = SWZ128(r * 128 + c * 16);
                    CP_ASYNC16(st + 16384 + off,
                               Bbase + (size_t)r * (COLROW * 2) + kpt * 1024 + srcoff + c * 16);
                }
            }
        } else {
            int ki = kpt / 3, kj = kpt - 3 * ki;
            int dn = (ki - 1) * 64 + (kj - 1);
#pragma unroll
            for (int i = 0; i < 12; i++) {
                int idx = tid + i * 256;
                if (idx < 1024) {
                    int r = idx >> 3, c = idx & 7;
                    uint32_t off = SWZ128(r * 128 + c * 16);
                    CP_ASYNC16(st + off, Abase + (size_t)r * (K3 * 2) + kb + c * 16);
                } else {
                    int j = idx - 1024;
                    int r = j >> 3, c = j & 7;
                    int n = n0 + r;
                    int h = (n >> 6) & 63, w = n & 63;
                    int y = h - 1 + ki, xw = w - 1 + kj;
                    bool valid = ((unsigned)y < 64u) && ((unsigned)xw < 64u);
                    int np = valid ? n + dn : 0;
                    uint32_t sz = valid ? 16u : 0u;
                    uint32_t off = SWZ128(r * 128 + c * 16);
                    CP_ASYNC16Z(st + 16384 + off,
                                Obase + (size_t)np * 1024 + srcoff + c * 16, sz);
                }
            }
        }
        CP_COMMIT();
    };

    int lane = tid & 31, w = tid >> 5;
    int wm = w >> 1, wn = w & 1;       // 4x2 warp grid
    int mW = wm * 32, nW = wn * 128;   // warp tile 32x128
    int gq = lane >> 3, rr = lane & 7;
    int rowin = (gq & 1) * 8 + rr;
    int kboff = (gq >> 1) * 16;

    float acc[2][16][4];
#pragma unroll
    for (int mt = 0; mt < 2; mt++)
#pragma unroll
        for (int j = 0; j < 16; j++)
#pragma unroll
            for (int q = 0; q < 4; q++) acc[mt][j][q] = 0.f;

    uint32_t aOff[2], aXor[2], bOff[8], bXor[8];
#pragma unroll
    for (int mt = 0; mt < 2; mt++) {
        int row = mW + mt * 16 + rowin;
        aOff[mt] = row * 128;
        aXor[mt] = (row & 7) << 4;
    }
#pragma unroll
    for (int nt = 0; nt < 8; nt++) {
        int row = nW + nt * 16 + rowin;
        bOff[nt] = row * 128;
        bXor[nt] = (row & 7) << 4;
    }

    load_stage(0, 0);
    load_stage(1, 1);
    load_stage(2, 2);

    for (int k = 0; k < NUM_KCH; k++) {
        int s = k % NSTAGE;
        uint32_t stA = sb + s * STAGE_SZ;
        uint32_t stB = stA + 16384;
        CP_WAIT2();
        __syncthreads();

#pragma unroll
        for (int ks = 0; ks < 4; ks++) {
            uint32_t kb = ks * 32 + kboff;
            uint32_t af[2][4];
#pragma unroll
            for (int mt = 0; mt < 2; mt++)
                LDSM4(af[mt][0], af[mt][1], af[mt][2], af[mt][3],
                      stA + aOff[mt] + (kb ^ aXor[mt]));
#pragma unroll
            for (int nt = 0; nt < 8; nt++) {
                uint32_t bf0, bf1, bf2, bf3;
                LDSM4(bf0, bf1, bf2, bf3, stB + bOff[nt] + (kb ^ bXor[nt]));
#pragma unroll
                for (int mt = 0; mt < 2; mt++) {
                    MMA16816(acc[mt][nt * 2], af[mt][0], af[mt][1], af[mt][2], af[mt][3],
                             bf0, bf2);
                    MMA16816(acc[mt][nt * 2 + 1], af[mt][0], af[mt][1], af[mt][2], af[mt][3],
                             bf1, bf3);
                }
            }
        }
        __syncthreads();
        if (k + 3 < NUM_KCH) load_stage(k + 3, s);
        else CP_COMMIT();
    }

    int qr = lane >> 2;
    int qc = (lane & 3) * 2;
#pragma unroll
    for (int mt = 0; mt < 2; mt++) {
        int row0 = m0 + mW + mt * 16 + qr;
        float bv0 = bias ? bias[row0] : 0.f;
        float bv1 = bias ? bias[row0 + 8] : 0.f;
#pragma unroll
        for (int j = 0; j < 16; j++) {
            int col = n0 + nW + j * 8 + qc;
            float2 v0 = make_float2(acc[mt][j][0] + bv0, acc[mt][j][1] + bv0);
            float2 v1 = make_float2(acc[mt][j][2] + bv1, acc[mt][j][3] + bv1);
            *reinterpret_cast<float2*>(Cg + (size_t)row0 * NN + col) = v0;
            *reinterpret_cast<float2*>(Cg + (size_t)(row0 + 8) * NN + col) = v1;
        }
    }
}

// ---------------- BN stats -> per-channel scale/shift ------------------------
__global__ __launch_bounds__(256)
void k_bnstats(const float* __restrict__ gamma, const float* __restrict__ beta, int sel) {
    const float* src = sel ? g_out2 : g_out1;
    float* scale = sel ? g_scale2 : g_scale1;
    float* shift = sel ? g_shift2 : g_shift1;
    int ch = blockIdx.x;
    const float* p = src + (size_t)ch * NN;
    float s = 0.f, sq = 0.f;
    for (int i = threadIdx.x; i < NN; i += 256) {
        float v = p[i];
        s += v;
        sq = fmaf(v, v, sq);
    }
    __shared__ float rs[256], rq[256];
    int t = threadIdx.x;
    rs[t] = s; rq[t] = sq;
    __syncthreads();
    for (int off = 128; off > 0; off >>= 1) {
        if (t < off) { rs[t] += rs[t + off]; rq[t] += rq[t + off]; }
        __syncthreads();
    }
    if (t == 0) {
        float mean = rs[0] * (1.f / NN);
        float var = fmaxf(rq[0] * (1.f / NN) - mean * mean, 0.f);
        float inv = rsqrtf(var + EPSB);
        float sc = inv * gamma[ch];
        scale[ch] = sc;
        shift[ch] = beta[ch] - mean * sc;
    }
}

// ---------------- final: relu(bn2(out2) + x) in NCHW ------------------------
__global__ __launch_bounds__(256)
void k_final(const float* __restrict__ x, float* __restrict__ out) {
    int i = blockIdx.x * 256 + threadIdx.x;
    int hw = i & 4095;
    int o = (i >> 12) & 255;
    int b = i >> 20;
    float v = fmaf(g_out2[(size_t)o * NN + b * HWW + hw], g_scale2[o], g_shift2[o]) + x[i];
    out[i] = fmaxf(v, 0.f);
}

// ---------------- launch -----------------------------------------------------
extern "C" void kernel_launch(void* const* d_in, const int* in_sizes, int n_in,
                              void* d_out, int out_size) {
    const float* x     = (const float*)d_in[0];
    const float* off_w = (const float*)d_in[1];
    const float* off_b = (const float*)d_in[2];
    const float* dw    = (const float*)d_in[3];
    const float* db    = (const float*)d_in[4];
    const float* bn1_g = (const float*)d_in[5];
    const float* bn1_b = (const float*)d_in[6];
    const float* w2    = (const float*)d_in[7];
    const float* bn2_g = (const float*)d_in[8];
    const float* bn2_b = (const float*)d_in[9];
    float* out = (float*)d_out;

    cudaFuncSetAttribute(k_gemm_mma, cudaFuncAttributeMaxDynamicSharedMemorySize, GEMM_SMEM);

    k_zero_offset<<<(BB * 18 * HWW + 255) / 256, 256>>>();
    k_transpose_x<<<dim3(NN / 32, 8), 256>>>(x);
    k_offset_conv<<<dim3(64, 4), 256>>>(x, off_w, off_b);
    k_wprep<<<dim3((OO * CKK + 255) / 256, 2), 256>>>(dw, w2);
    k_im2col_deform<<<NN / 32, 256>>>();
    k_gemm_mma<<<dim3(2, 64), 256, GEMM_SMEM>>>(0, db, 0, 0);
    k_bnstats<<<256, 256>>>(bn1_g, bn1_b, 0);
    k_convert1<<<NN / 32, 256>>>();
    k_gemm_mma<<<dim3(2, 64), 256, GEMM_SMEM>>>(1, nullptr, 1, 1);
    k_bnstats<<<256, 256>>>(bn2_g, bn2_b, 1);
    k_final<<<(BB * OO * HWW + 255) / 256, 256>>>(x, out);
}

// round 10
// speedup vs baseline: 2.8099x; 1.3074x over previous
#include <cuda_runtime.h>
#include <cuda_fp16.h>
#include <cstdint>

#define BB 4
#define CC 256
#define OO 256
#define HWW 4096
#define NN 16384          // BB*HWW
#define CKK 2304          // CC*9
#define K2 4608           // 2*CKK (fp16 split-double K: A=[wh,wl], B=[xh,xh])
#define EPSB 1e-5f

#define NSTAGE 3
#define STAGE_SZ 49152      // A 16KB + B 32KB per stage
#define GEMM_SMEM (NSTAGE * STAGE_SZ)
#define NUM_KCH 72          // K2*2 bytes / 128B per chunk

// col row: per pixel 9 kpt x 256 fp16 (hi only) = 2304 fp16 = 4608 B
#define COLROW 2304
// out1b row: 256 fp16 = 512 B
#define O1ROW 256

// ---------------- scratch (device globals; no allocs allowed) ----------------
__device__ float g_offset[BB * 18 * HWW];                       // 4.7 MB
__device__ float g_xpm[(size_t)NN * CC];                        // 64 MB NHWC x
__device__ __half g_colb[(size_t)NN * COLROW];                  // 75.5 MB hi-plane
__device__ __half g_wA1[(size_t)OO * K2];                       // 2.4 MB [m][k']
__device__ __half g_wA2[(size_t)OO * K2];
__device__ float g_out1[(size_t)OO * NN];                       // 16.8 MB [o][n]
__device__ float g_out2[(size_t)OO * NN];
__device__ __half g_out1b[(size_t)NN * O1ROW];                  // 8.4 MB
__device__ float g_scale1[OO], g_shift1[OO], g_scale2[OO], g_shift2[OO];

// ---------------- helpers ----------------------------------------------------
__device__ __forceinline__ uint32_t smem_u32(const void* p) {
    uint32_t a;
    asm("{ .reg .u64 t; cvta.to.shared.u64 t, %1; cvt.u32.u64 %0, t; }" : "=r"(a) : "l"(p));
    return a;
}
#define SWZ128(o) ((o) ^ (((o) >> 3) & 0x70))
#define CP_ASYNC16(dst, src) \
    asm volatile("cp.async.cg.shared.global [%0], [%1], 16;" :: "r"(dst), "l"(src))
#define CP_ASYNC16Z(dst, src, sz) \
    asm volatile("cp.async.cg.shared.global [%0], [%1], 16, %2;" :: "r"(dst), "l"(src), "r"(sz))
#define CP_COMMIT() asm volatile("cp.async.commit_group;" ::: "memory")
#define CP_WAIT2()  asm volatile("cp.async.wait_group 2;" ::: "memory")

#define LDSM4(r0, r1, r2, r3, addr) \
    asm volatile("ldmatrix.sync.aligned.m8n8.x4.shared.b16 {%0,%1,%2,%3}, [%4];" \
                 : "=r"(r0), "=r"(r1), "=r"(r2), "=r"(r3) : "r"(addr))

#define MMA16816F16(d, a0, a1, a2, a3, b0, b1) \
    asm volatile("mma.sync.aligned.m16n8k16.row.col.f32.f16.f16.f32 " \
                 "{%0,%1,%2,%3},{%4,%5,%6,%7},{%8,%9},{%0,%1,%2,%3};" \
                 : "+f"((d)[0]), "+f"((d)[1]), "+f"((d)[2]), "+f"((d)[3]) \
                 : "r"(a0), "r"(a1), "r"(a2), "r"(a3), "r"(b0), "r"(b1))

__device__ __forceinline__ unsigned short f2h(float v) {
    __half h = __float2half_rn(v);
    return *reinterpret_cast<unsigned short*>(&h);
}
__device__ __forceinline__ void split_hl(float v, unsigned short& hi, unsigned short& lo) {
    hi = f2h(v);
    float hf = __half2float(*reinterpret_cast<__half*>(&hi));
    lo = f2h(v - hf);
}

// ---------------- zero offset ------------------------------------------------
__global__ void k_zero_offset() {
    int i = blockIdx.x * 256 + threadIdx.x;
    if (i < BB * 18 * HWW) g_offset[i] = 0.f;
}

// ---------------- transpose x: NCHW -> NHWC (g_xpm) -------------------------
__global__ __launch_bounds__(256)
void k_transpose_x(const float* __restrict__ x) {
    __shared__ float t[32][33];
    int n0 = blockIdx.x * 32;
    int c0 = blockIdx.y * 32;
    int b = n0 >> 12;
    int hw0 = n0 & 4095;
    int lane = threadIdx.x & 31, wy = threadIdx.x >> 5;
#pragma unroll
    for (int j = 0; j < 4; j++) {
        int cc = wy + j * 8;
        t[cc][lane] = x[((size_t)b * CC + c0 + cc) * HWW + hw0 + lane];
    }
    __syncthreads();
#pragma unroll
    for (int j = 0; j < 4; j++) {
        int r = wy + j * 8;
        g_xpm[(size_t)(n0 + r) * CC + c0 + lane] = t[lane][r];
    }
}

// ---------------- offset conv: 3x3, dil=2, pad=2, 256->18 -------------------
__global__ __launch_bounds__(256)
void k_offset_conv(const float* __restrict__ x, const float* __restrict__ off_w,
                   const float* __restrict__ off_b) {
    __shared__ float sw[18 * 64 * 9];
    int c0 = blockIdx.y * 64;
    for (int idx = threadIdx.x; idx < 18 * 64 * 9; idx += 256) {
        int oc = idx / 576;
        int rem = idx - oc * 576;
        sw[idx] = off_w[oc * CKK + c0 * 9 + rem];
    }
    __syncthreads();

    int n = blockIdx.x * 256 + threadIdx.x;
    int b = n >> 12, hw = n & 4095;
    int h = hw >> 6, w = hw & 63;

    float acc[18];
#pragma unroll
    for (int oc = 0; oc < 18; oc++) acc[oc] = 0.f;

    const float* xb = x + ((size_t)b * CC + c0) * HWW;
    for (int cc = 0; cc < 64; cc++) {
        const float* xc = xb + cc * HWW;
#pragma unroll
        for (int i = 0; i < 3; i++) {
            int y = h - 2 + 2 * i;
            if ((unsigned)y >= 64u) continue;
#pragma unroll
            for (int j = 0; j < 3; j++) {
                int xx = w - 2 + 2 * j;
                if ((unsigned)xx >= 64u) continue;
                float v = xc[(y << 6) + xx];
                const float* wp = &sw[cc * 9 + i * 3 + j];
#pragma unroll
                for (int oc = 0; oc < 18; oc++)
                    acc[oc] = fmaf(v, wp[oc * 576], acc[oc]);
            }
        }
    }
    float* op = g_offset + (size_t)b * 18 * HWW + hw;
    if (blockIdx.y == 0) {
#pragma unroll
        for (int oc = 0; oc < 18; oc++) atomicAdd(&op[oc * HWW], acc[oc] + off_b[oc]);
    } else {
#pragma unroll
        for (int oc = 0; oc < 18; oc++) atomicAdd(&op[oc * HWW], acc[oc]);
    }
}

// ---------------- weight prep: fp32 W -> fp16 A' [wh(256) | wl(256)] per kpt
__global__ __launch_bounds__(256)
void k_wprep(const float* __restrict__ dw, const float* __restrict__ w2) {
    int idx = blockIdx.x * 256 + threadIdx.x;
    if (idx >= OO * CKK) return;
    int m = idx / CKK;
    int ck = idx - m * CKK;
    int c = ck / 9, kpt = ck - c * 9;
    const float* w = blockIdx.y ? w2 : dw;
    __half* dst = blockIdx.y ? g_wA2 : g_wA1;
    float v = w[idx];
    unsigned short hi, lo;
    split_hl(v, hi, lo);
    size_t base = (size_t)m * K2 + kpt * 512;
    unsigned short* d = reinterpret_cast<unsigned short*>(dst);
    d[base + c] = hi;            // plane wh (pairs B xh)
    d[base + 256 + c] = lo;      // plane wl (pairs B xh again)
}

// ---------------- deformable im2col v5: NHWC coalesced, fp16 hi only --------
__global__ __launch_bounds__(256)
void k_im2col_deform() {
    __shared__ float4 wts[9][32];
    __shared__ int4 idxs[9][32];

    int n0 = blockIdx.x * 32;
    int b = n0 >> 12;

    for (int t = threadIdx.x; t < 288; t += 256) {
        int kpt = t >> 5, px = t & 31;
        int n = n0 + px;
        int hw = n & 4095;
        int h = hw >> 6, w = hw & 63;
        int ki = kpt / 3, kj = kpt - ki * 3;
        float offy = g_offset[((size_t)b * 18 + 2 * kpt) * HWW + hw];
        float offx = g_offset[((size_t)b * 18 + 2 * kpt + 1) * HWW + hw];
        float py = (float)(h - 2 + 2 * ki) + offy;
        float pxx = (float)(w - 2 + 2 * kj) + offx;
        float fy0 = floorf(py), fx0 = floorf(pxx);
        int y0 = (int)fy0, x0 = (int)fx0;
        int y1 = y0 + 1, x1 = x0 + 1;
        float wy1 = py - fy0, wx1 = pxx - fx0;
        float wy0 = 1.f - wy1, wx0 = 1.f - wx1;
        bool vy0 = (unsigned)y0 < 64u, vy1 = (unsigned)y1 < 64u;
        bool vx0 = (unsigned)x0 < 64u, vx1 = (unsigned)x1 < 64u;
        float w00 = (vy0 && vx0) ? wy0 * wx0 : 0.f;
        float w01 = (vy0 && vx1) ? wy0 * wx1 : 0.f;
        float w10 = (vy1 && vx0) ? wy1 * wx0 : 0.f;
        float w11 = (vy1 && vx1) ? wy1 * wx1 : 0.f;
        int yc0 = min(max(y0, 0), 63), yc1 = min(max(y1, 0), 63);
        int xc0 = min(max(x0, 0), 63), xc1 = min(max(x1, 0), 63);
        int gb = b << 12;
        wts[kpt][px] = make_float4(w00, w01, w10, w11);
        idxs[kpt][px] = make_int4(gb + (yc0 << 6) + xc0, gb + (yc0 << 6) + xc1,
                                  gb + (yc1 << 6) + xc0, gb + (yc1 << 6) + xc1);
    }
    __syncthreads();

    int wid = threadIdx.x >> 5, lane = threadIdx.x & 31;
    int c8 = lane * 8;
    unsigned short* colbase = reinterpret_cast<unsigned short*>(g_colb);

    for (int task = wid; task < 288; task += 8) {
        int kpt = task >> 5, px = task & 31;
        float4 wv = wts[kpt][px];
        int4 iv = idxs[kpt][px];
        const float4* p00 = reinterpret_cast<const float4*>(g_xpm + (size_t)iv.x * CC + c8);
        const float4* p01 = reinterpret_cast<const float4*>(g_xpm + (size_t)iv.y * CC + c8);
        const float4* p10 = reinterpret_cast<const float4*>(g_xpm + (size_t)iv.z * CC + c8);
        const float4* p11 = reinterpret_cast<const float4*>(g_xpm + (size_t)iv.w * CC + c8);
        float4 a0 = p00[0], a1 = p00[1];
        float4 b0 = p01[0], b1 = p01[1];
        float4 c0v = p10[0], c1 = p10[1];
        float4 d0 = p11[0], d1 = p11[1];
        float v[8];
        v[0] = wv.x * a0.x + wv.y * b0.x + wv.z * c0v.x + wv.w * d0.x;
        v[1] = wv.x * a0.y + wv.y * b0.y + wv.z * c0v.y + wv.w * d0.y;
        v[2] = wv.x * a0.z + wv.y * b0.z + wv.z * c0v.z + wv.w * d0.z;
        v[3] = wv.x * a0.w + wv.y * b0.w + wv.z * c0v.w + wv.w * d0.w;
        v[4] = wv.x * a1.x + wv.y * b1.x + wv.z * c1.x + wv.w * d1.x;
        v[5] = wv.x * a1.y + wv.y * b1.y + wv.z * c1.y + wv.w * d1.y;
        v[6] = wv.x * a1.z + wv.y * b1.z + wv.z * c1.z + wv.w * d1.z;
        v[7] = wv.x * a1.w + wv.y * b1.w + wv.z * c1.w + wv.w * d1.w;
        __align__(16) unsigned short his[8];
#pragma unroll
        for (int j = 0; j < 8; j++) his[j] = f2h(v[j]);
        unsigned short* row = colbase + (size_t)(n0 + px) * COLROW + kpt * 256;
        *reinterpret_cast<uint4*>(row + c8) = *reinterpret_cast<const uint4*>(his);
    }
}

// ---------------- convert1: out1 -> pixel-major fp16 (BN1+ReLU) -------------
__global__ __launch_bounds__(256)
void k_convert1() {
    __shared__ float t[64][33];
    __shared__ float sS[256], sH[256];
    int px0 = blockIdx.x * 32;
    int tid = threadIdx.x;
    int lane = tid & 31, wy = tid >> 5;
    for (int i = tid; i < 256; i += 256) { sS[i] = g_scale1[i]; sH[i] = g_shift1[i]; }
    __syncthreads();

    unsigned short* ob = reinterpret_cast<unsigned short*>(g_out1b);
    for (int c0 = 0; c0 < 256; c0 += 64) {
#pragma unroll
        for (int j = 0; j < 8; j++) {
            int cc = wy * 8 + j;
            t[cc][lane] = g_out1[(size_t)(c0 + cc) * NN + px0 + lane];
        }
        __syncthreads();
        int px = tid >> 3, g = tid & 7;
        __align__(16) unsigned short his[8];
#pragma unroll
        for (int j = 0; j < 8; j++) {
            int cc = g * 8 + j;
            float v = fmaxf(fmaf(t[cc][px], sS[c0 + cc], sH[c0 + cc]), 0.f);
            his[j] = f2h(v);
        }
        unsigned short* row = ob + (size_t)(px0 + px) * O1ROW;
        *reinterpret_cast<uint4*>(row + c0 + g * 8) = *reinterpret_cast<const uint4*>(his);
        __syncthreads();
    }
}

// ---------------- mma.sync fp16 GEMM, CTA tile 128x256, K2=4608 -------------
// grid (2, 64). A chunk kc: kpt=kc/8, part=kc%8 (0-3 wh, 4-7 wl).
// B chunk = xh channels [64*(part&3), +64) of kpt (read twice: part p and p+4).
__global__ __launch_bounds__(256, 1)
void k_gemm_mma(int wsel, const float* __restrict__ bias, int outsel, int implicitB) {
    extern __shared__ char smem[];
    uint32_t sb = smem_u32(smem);
    int tid = threadIdx.x;
    int m0 = blockIdx.x * 128;
    int n0 = blockIdx.y * 256;

    const __half* Ag = wsel ? g_wA2 : g_wA1;
    float* Cg = outsel ? g_out2 : g_out1;
    const char* Abase = reinterpret_cast<const char*>(Ag) + (size_t)m0 * (K2 * 2);
    const char* Bbase = reinterpret_cast<const char*>(g_colb) + (size_t)n0 * (COLROW * 2);
    const char* Obase = reinterpret_cast<const char*>(g_out1b);

    auto load_stage = [&](int kc, int s) {
        uint32_t st = sb + s * STAGE_SZ;
        size_t kb = (size_t)kc * 128;
        int kpt = kc >> 3, part = kc & 7;
        uint32_t srcoff = ((uint32_t)(part & 3)) << 7;    // xh chunk within kpt
        if (!implicitB) {
#pragma unroll
            for (int i = 0; i < 12; i++) {
                int idx = tid + i * 256;
                if (idx < 1024) {
                    int r = idx >> 3, c = idx & 7;
                    uint32_t off = SWZ128(r * 128 + c * 16);
                    CP_ASYNC16(st + off, Abase + (size_t)r * (K2 * 2) + kb + c * 16);
                } else {
                    int j = idx - 1024;
                    int r = j >> 3, c = j & 7;
                    uint32_t off = SWZ128(r * 128 + c * 16);
                    CP_ASYNC16(st + 16384 + off,
                               Bbase + (size_t)r * (COLROW * 2) + kpt * 512 + srcoff + c * 16);
                }
            }
        } else {
            int ki = kpt / 3, kj = kpt - 3 * ki;
            int dn = (ki - 1) * 64 + (kj - 1);
#pragma unroll
            for (int i = 0; i < 12; i++) {
                int idx = tid + i * 256;
                if (idx < 1024) {
                    int r = idx >> 3, c = idx & 7;
                    uint32_t off = SWZ128(r * 128 + c * 16);
                    CP_ASYNC16(st + off, Abase + (size_t)r * (K2 * 2) + kb + c * 16);
                } else {
                    int j = idx - 1024;
                    int r = j >> 3, c = j & 7;
                    int n = n0 + r;
                    int h = (n >> 6) & 63, w = n & 63;
                    int y = h - 1 + ki, xw = w - 1 + kj;
                    bool valid = ((unsigned)y < 64u) && ((unsigned)xw < 64u);
                    int np = valid ? n + dn : 0;
                    uint32_t sz = valid ? 16u : 0u;
                    uint32_t off = SWZ128(r * 128 + c * 16);
                    CP_ASYNC16Z(st + 16384 + off,
                                Obase + (size_t)np * 512 + srcoff + c * 16, sz);
                }
            }
        }
        CP_COMMIT();
    };

    int lane = tid & 31, w = tid >> 5;
    int wm = w >> 1, wn = w & 1;       // 4x2 warp grid
    int mW = wm * 32, nW = wn * 128;   // warp tile 32x128
    int gq = lane >> 3, rr = lane & 7;
    int rowin = (gq & 1) * 8 + rr;
    int kboff = (gq >> 1) * 16;

    float acc[2][16][4];
#pragma unroll
    for (int mt = 0; mt < 2; mt++)
#pragma unroll
        for (int j = 0; j < 16; j++)
#pragma unroll
            for (int q = 0; q < 4; q++) acc[mt][j][q] = 0.f;

    uint32_t aOff[2], aXor[2], bOff[8], bXor[8];
#pragma unroll
    for (int mt = 0; mt < 2; mt++) {
        int row = mW + mt * 16 + rowin;
        aOff[mt] = row * 128;
        aXor[mt] = (row & 7) << 4;
    }
#pragma unroll
    for (int nt = 0; nt < 8; nt++) {
        int row = nW + nt * 16 + rowin;
        bOff[nt] = row * 128;
        bXor[nt] = (row & 7) << 4;
    }

    load_stage(0, 0);
    load_stage(1, 1);
    load_stage(2, 2);

    for (int k = 0; k < NUM_KCH; k++) {
        int s = k % NSTAGE;
        uint32_t stA = sb + s * STAGE_SZ;
        uint32_t stB = stA + 16384;
        CP_WAIT2();
        __syncthreads();

#pragma unroll
        for (int ks = 0; ks < 4; ks++) {
            uint32_t kb = ks * 32 + kboff;
            uint32_t af[2][4];
#pragma unroll
            for (int mt = 0; mt < 2; mt++)
                LDSM4(af[mt][0], af[mt][1], af[mt][2], af[mt][3],
                      stA + aOff[mt] + (kb ^ aXor[mt]));
#pragma unroll
            for (int nt = 0; nt < 8; nt++) {
                uint32_t bf0, bf1, bf2, bf3;
                LDSM4(bf0, bf1, bf2, bf3, stB + bOff[nt] + (kb ^ bXor[nt]));
#pragma unroll
                for (int mt = 0; mt < 2; mt++) {
                    MMA16816F16(acc[mt][nt * 2], af[mt][0], af[mt][1], af[mt][2], af[mt][3],
                                bf0, bf2);
                    MMA16816F16(acc[mt][nt * 2 + 1], af[mt][0], af[mt][1], af[mt][2], af[mt][3],
                                bf1, bf3);
                }
            }
        }
        __syncthreads();
        if (k + 3 < NUM_KCH) load_stage(k + 3, s);
        else CP_COMMIT();
    }

    int qr = lane >> 2;
    int qc = (lane & 3) * 2;
#pragma unroll
    for (int mt = 0; mt < 2; mt++) {
        int row0 = m0 + mW + mt * 16 + qr;
        float bv0 = bias ? bias[row0] : 0.f;
        float bv1 = bias ? bias[row0 + 8] : 0.f;
#pragma unroll
        for (int j = 0; j < 16; j++) {
            int col = n0 + nW + j * 8 + qc;
            float2 v0 = make_float2(acc[mt][j][0] + bv0, acc[mt][j][1] + bv0);
            float2 v1 = make_float2(acc[mt][j][2] + bv1, acc[mt][j][3] + bv1);
            *reinterpret_cast<float2*>(Cg + (size_t)row0 * NN + col) = v0;
            *reinterpret_cast<float2*>(Cg + (size_t)(row0 + 8) * NN + col) = v1;
        }
    }
}

// ---------------- BN stats -> per-channel scale/shift ------------------------
__global__ __launch_bounds__(256)
void k_bnstats(const float* __restrict__ gamma, const float* __restrict__ beta, int sel) {
    const float* src = sel ? g_out2 : g_out1;
    float* scale = sel ? g_scale2 : g_scale1;
    float* shift = sel ? g_shift2 : g_shift1;
    int ch = blockIdx.x;
    const float* p = src + (size_t)ch * NN;
    float s = 0.f, sq = 0.f;
    for (int i = threadIdx.x; i < NN; i += 256) {
        float v = p[i];
        s += v;
        sq = fmaf(v, v, sq);
    }
    __shared__ float rs[256], rq[256];
    int t = threadIdx.x;
    rs[t] = s; rq[t] = sq;
    __syncthreads();
    for (int off = 128; off > 0; off >>= 1) {
        if (t < off) { rs[t] += rs[t + off]; rq[t] += rq[t + off]; }
        __syncthreads();
    }
    if (t == 0) {
        float mean = rs[0] * (1.f / NN);
        float var = fmaxf(rq[0] * (1.f / NN) - mean * mean, 0.f);
        float inv = rsqrtf(var + EPSB);
        float sc = inv * gamma[ch];
        scale[ch] = sc;
        shift[ch] = beta[ch] - mean * sc;
    }
}

// ---------------- final: relu(bn2(out2) + x) in NCHW ------------------------
__global__ __launch_bounds__(256)
void k_final(const float* __restrict__ x, float* __restrict__ out) {
    int i = blockIdx.x * 256 + threadIdx.x;
    int hw = i & 4095;
    int o = (i >> 12) & 255;
    int b = i >> 20;
    float v = fmaf(g_out2[(size_t)o * NN + b * HWW + hw], g_scale2[o], g_shift2[o]) + x[i];
    out[i] = fmaxf(v, 0.f);
}

// ---------------- launch -----------------------------------------------------
extern "C" void kernel_launch(void* const* d_in, const int* in_sizes, int n_in,
                              void* d_out, int out_size) {
    const float* x     = (const float*)d_in[0];
    const float* off_w = (const float*)d_in[1];
    const float* off_b = (const float*)d_in[2];
    const float* dw    = (const float*)d_in[3];
    const float* db    = (const float*)d_in[4];
    const float* bn1_g = (const float*)d_in[5];
    const float* bn1_b = (const float*)d_in[6];
    const float* w2    = (const float*)d_in[7];
    const float* bn2_g = (const float*)d_in[8];
    const float* bn2_b = (const float*)d_in[9];
    float* out = (float*)d_out;

    cudaFuncSetAttribute(k_gemm_mma, cudaFuncAttributeMaxDynamicSharedMemorySize, GEMM_SMEM);

    k_zero_offset<<<(BB * 18 * HWW + 255) / 256, 256>>>();
    k_transpose_x<<<dim3(NN / 32, 8), 256>>>(x);
    k_offset_conv<<<dim3(64, 4), 256>>>(x, off_w, off_b);
    k_wprep<<<dim3((OO * CKK + 255) / 256, 2), 256>>>(dw, w2);
    k_im2col_deform<<<NN / 32, 256>>>();
    k_gemm_mma<<<dim3(2, 64), 256, GEMM_SMEM>>>(0, db, 0, 0);
    k_bnstats<<<256, 256>>>(bn1_g, bn1_b, 0);
    k_convert1<<<NN / 32, 256>>>();
    k_gemm_mma<<<dim3(2, 64), 256, GEMM_SMEM>>>(1, nullptr, 1, 1);
    k_bnstats<<<256, 256>>>(bn2_g, bn2_b, 1);
    k_final<<<(BB * OO * HWW + 255) / 256, 256>>>(x, out);
}

// round 11
// speedup vs baseline: 3.8255x; 1.3614x over previous
#include <cuda_runtime.h>
#include <cuda_fp16.h>
#include <cstdint>

#define BB 4
#define CC 256
#define OO 256
#define HWW 4096
#define NN 16384          // BB*HWW
#define CKK 2304          // CC*9 — plain fp16 K (single plane, both A and B)
#define EPSB 1e-5f

#define NSTAGE 3
#define STAGE_SZ 49152      // A 16KB + B 32KB per stage
#define GEMM_SMEM (NSTAGE * STAGE_SZ)
#define NUM_KCH 36          // CKK*2 bytes / 128B per chunk

// col row: per pixel 9 kpt x 256 fp16 = 2304 fp16 = 4608 B
#define COLROW 2304
// out1b row: 256 fp16 = 512 B
#define O1ROW 256

// ---------------- scratch (device globals; no allocs allowed) ----------------
__device__ float g_offset[BB * 18 * HWW];                       // 4.7 MB
__device__ float g_xpm[(size_t)NN * CC];                        // 64 MB NHWC x
__device__ __half g_colb[(size_t)NN * COLROW];                  // 75.5 MB
__device__ __half g_wA1[(size_t)OO * CKK];                      // 1.2 MB [m][k]
__device__ __half g_wA2[(size_t)OO * CKK];
__device__ float g_out1[(size_t)OO * NN];                       // 16.8 MB [o][n]
__device__ float g_out2[(size_t)OO * NN];
__device__ __half g_out1b[(size_t)NN * O1ROW];                  // 8.4 MB
__device__ float g_scale1[OO], g_shift1[OO], g_scale2[OO], g_shift2[OO];

// ---------------- helpers ----------------------------------------------------
__device__ __forceinline__ uint32_t smem_u32(const void* p) {
    uint32_t a;
    asm("{ .reg .u64 t; cvta.to.shared.u64 t, %1; cvt.u32.u64 %0, t; }" : "=r"(a) : "l"(p));
    return a;
}
#define SWZ128(o) ((o) ^ (((o) >> 3) & 0x70))
#define CP_ASYNC16(dst, src) \
    asm volatile("cp.async.cg.shared.global [%0], [%1], 16;" :: "r"(dst), "l"(src))
#define CP_ASYNC16Z(dst, src, sz) \
    asm volatile("cp.async.cg.shared.global [%0], [%1], 16, %2;" :: "r"(dst), "l"(src), "r"(sz))
#define CP_COMMIT() asm volatile("cp.async.commit_group;" ::: "memory")
#define CP_WAIT2()  asm volatile("cp.async.wait_group 2;" ::: "memory")

#define LDSM4(r0, r1, r2, r3, addr) \
    asm volatile("ldmatrix.sync.aligned.m8n8.x4.shared.b16 {%0,%1,%2,%3}, [%4];" \
                 : "=r"(r0), "=r"(r1), "=r"(r2), "=r"(r3) : "r"(addr))

#define MMA16816F16(d, a0, a1, a2, a3, b0, b1) \
    asm volatile("mma.sync.aligned.m16n8k16.row.col.f32.f16.f16.f32 " \
                 "{%0,%1,%2,%3},{%4,%5,%6,%7},{%8,%9},{%0,%1,%2,%3};" \
                 : "+f"((d)[0]), "+f"((d)[1]), "+f"((d)[2]), "+f"((d)[3]) \
                 : "r"(a0), "r"(a1), "r"(a2), "r"(a3), "r"(b0), "r"(b1))

__device__ __forceinline__ unsigned short f2h(float v) {
    __half h = __float2half_rn(v);
    return *reinterpret_cast<unsigned short*>(&h);
}

// ---------------- zero offset ------------------------------------------------
__global__ void k_zero_offset() {
    int i = blockIdx.x * 256 + threadIdx.x;
    if (i < BB * 18 * HWW) g_offset[i] = 0.f;
}

// ---------------- transpose x: NCHW -> NHWC (g_xpm) -------------------------
__global__ __launch_bounds__(256)
void k_transpose_x(const float* __restrict__ x) {
    __shared__ float t[32][33];
    int n0 = blockIdx.x * 32;
    int c0 = blockIdx.y * 32;
    int b = n0 >> 12;
    int hw0 = n0 & 4095;
    int lane = threadIdx.x & 31, wy = threadIdx.x >> 5;
#pragma unroll
    for (int j = 0; j < 4; j++) {
        int cc = wy + j * 8;
        t[cc][lane] = x[((size_t)b * CC + c0 + cc) * HWW + hw0 + lane];
    }
    __syncthreads();
#pragma unroll
    for (int j = 0; j < 4; j++) {
        int r = wy + j * 8;
        g_xpm[(size_t)(n0 + r) * CC + c0 + lane] = t[lane][r];
    }
}

// ---------------- offset conv: 3x3, dil=2, pad=2, 256->18 -------------------
__global__ __launch_bounds__(256)
void k_offset_conv(const float* __restrict__ x, const float* __restrict__ off_w,
                   const float* __restrict__ off_b) {
    __shared__ float sw[18 * 64 * 9];
    int c0 = blockIdx.y * 64;
    for (int idx = threadIdx.x; idx < 18 * 64 * 9; idx += 256) {
        int oc = idx / 576;
        int rem = idx - oc * 576;
        sw[idx] = off_w[oc * CKK + c0 * 9 + rem];
    }
    __syncthreads();

    int n = blockIdx.x * 256 + threadIdx.x;
    int b = n >> 12, hw = n & 4095;
    int h = hw >> 6, w = hw & 63;

    float acc[18];
#pragma unroll
    for (int oc = 0; oc < 18; oc++) acc[oc] = 0.f;

    const float* xb = x + ((size_t)b * CC + c0) * HWW;
    for (int cc = 0; cc < 64; cc++) {
        const float* xc = xb + cc * HWW;
#pragma unroll
        for (int i = 0; i < 3; i++) {
            int y = h - 2 + 2 * i;
            if ((unsigned)y >= 64u) continue;
#pragma unroll
            for (int j = 0; j < 3; j++) {
                int xx = w - 2 + 2 * j;
                if ((unsigned)xx >= 64u) continue;
                float v = xc[(y << 6) + xx];
                const float* wp = &sw[cc * 9 + i * 3 + j];
#pragma unroll
                for (int oc = 0; oc < 18; oc++)
                    acc[oc] = fmaf(v, wp[oc * 576], acc[oc]);
            }
        }
    }
    float* op = g_offset + (size_t)b * 18 * HWW + hw;
    if (blockIdx.y == 0) {
#pragma unroll
        for (int oc = 0; oc < 18; oc++) atomicAdd(&op[oc * HWW], acc[oc] + off_b[oc]);
    } else {
#pragma unroll
        for (int oc = 0; oc < 18; oc++) atomicAdd(&op[oc * HWW], acc[oc]);
    }
}

// ---------------- weight prep: fp32 W -> fp16 A' [m][kpt*256+c] -------------
__global__ __launch_bounds__(256)
void k_wprep(const float* __restrict__ dw, const float* __restrict__ w2) {
    int idx = blockIdx.x * 256 + threadIdx.x;
    if (idx >= OO * CKK) return;
    int m = idx / CKK;
    int ck = idx - m * CKK;
    int c = ck / 9, kpt = ck - c * 9;
    const float* w = blockIdx.y ? w2 : dw;
    __half* dst = blockIdx.y ? g_wA2 : g_wA1;
    unsigned short hi = f2h(w[idx]);
    reinterpret_cast<unsigned short*>(dst)[(size_t)m * CKK + kpt * 256 + c] = hi;
}

// ---------------- deformable im2col: NHWC coalesced, fp16 -------------------
__global__ __launch_bounds__(256)
void k_im2col_deform() {
    __shared__ float4 wts[9][32];
    __shared__ int4 idxs[9][32];

    int n0 = blockIdx.x * 32;
    int b = n0 >> 12;

    for (int t = threadIdx.x; t < 288; t += 256) {
        int kpt = t >> 5, px = t & 31;
        int n = n0 + px;
        int hw = n & 4095;
        int h = hw >> 6, w = hw & 63;
        int ki = kpt / 3, kj = kpt - ki * 3;
        float offy = g_offset[((size_t)b * 18 + 2 * kpt) * HWW + hw];
        float offx = g_offset[((size_t)b * 18 + 2 * kpt + 1) * HWW + hw];
        float py = (float)(h - 2 + 2 * ki) + offy;
        float pxx = (float)(w - 2 + 2 * kj) + offx;
        float fy0 = floorf(py), fx0 = floorf(pxx);
        int y0 = (int)fy0, x0 = (int)fx0;
        int y1 = y0 + 1, x1 = x0 + 1;
        float wy1 = py - fy0, wx1 = pxx - fx0;
        float wy0 = 1.f - wy1, wx0 = 1.f - wx1;
        bool vy0 = (unsigned)y0 < 64u, vy1 = (unsigned)y1 < 64u;
        bool vx0 = (unsigned)x0 < 64u, vx1 = (unsigned)x1 < 64u;
        float w00 = (vy0 && vx0) ? wy0 * wx0 : 0.f;
        float w01 = (vy0 && vx1) ? wy0 * wx1 : 0.f;
        float w10 = (vy1 && vx0) ? wy1 * wx0 : 0.f;
        float w11 = (vy1 && vx1) ? wy1 * wx1 : 0.f;
        int yc0 = min(max(y0, 0), 63), yc1 = min(max(y1, 0), 63);
        int xc0 = min(max(x0, 0), 63), xc1 = min(max(x1, 0), 63);
        int gb = b << 12;
        wts[kpt][px] = make_float4(w00, w01, w10, w11);
        idxs[kpt][px] = make_int4(gb + (yc0 << 6) + xc0, gb + (yc0 << 6) + xc1,
                                  gb + (yc1 << 6) + xc0, gb + (yc1 << 6) + xc1);
    }
    __syncthreads();

    int wid = threadIdx.x >> 5, lane = threadIdx.x & 31;
    int c8 = lane * 8;
    unsigned short* colbase = reinterpret_cast<unsigned short*>(g_colb);

    for (int task = wid; task < 288; task += 8) {
        int kpt = task >> 5, px = task & 31;
        float4 wv = wts[kpt][px];
        int4 iv = idxs[kpt][px];
        const float4* p00 = reinterpret_cast<const float4*>(g_xpm + (size_t)iv.x * CC + c8);
        const float4* p01 = reinterpret_cast<const float4*>(g_xpm + (size_t)iv.y * CC + c8);
        const float4* p10 = reinterpret_cast<const float4*>(g_xpm + (size_t)iv.z * CC + c8);
        const float4* p11 = reinterpret_cast<const float4*>(g_xpm + (size_t)iv.w * CC + c8);
        float4 a0 = p00[0], a1 = p00[1];
        float4 b0 = p01[0], b1 = p01[1];
        float4 c0v = p10[0], c1 = p10[1];
        float4 d0 = p11[0], d1 = p11[1];
        float v[8];
        v[0] = wv.x * a0.x + wv.y * b0.x + wv.z * c0v.x + wv.w * d0.x;
        v[1] = wv.x * a0.y + wv.y * b0.y + wv.z * c0v.y + wv.w * d0.y;
        v[2] = wv.x * a0.z + wv.y * b0.z + wv.z * c0v.z + wv.w * d0.z;
        v[3] = wv.x * a0.w + wv.y * b0.w + wv.z * c0v.w + wv.w * d0.w;
        v[4] = wv.x * a1.x + wv.y * b1.x + wv.z * c1.x + wv.w * d1.x;
        v[5] = wv.x * a1.y + wv.y * b1.y + wv.z * c1.y + wv.w * d1.y;
        v[6] = wv.x * a1.z + wv.y * b1.z + wv.z * c1.z + wv.w * d1.z;
        v[7] = wv.x * a1.w + wv.y * b1.w + wv.z * c1.w + wv.w * d1.w;
        __align__(16) unsigned short his[8];
#pragma unroll
        for (int j = 0; j < 8; j++) his[j] = f2h(v[j]);
        unsigned short* row = colbase + (size_t)(n0 + px) * COLROW + kpt * 256;
        *reinterpret_cast<uint4*>(row + c8) = *reinterpret_cast<const uint4*>(his);
    }
}

// ---------------- convert1: out1 -> pixel-major fp16 (BN1+ReLU) -------------
__global__ __launch_bounds__(256)
void k_convert1() {
    __shared__ float t[64][33];
    __shared__ float sS[256], sH[256];
    int px0 = blockIdx.x * 32;
    int tid = threadIdx.x;
    int lane = tid & 31, wy = tid >> 5;
    for (int i = tid; i < 256; i += 256) { sS[i] = g_scale1[i]; sH[i] = g_shift1[i]; }
    __syncthreads();

    unsigned short* ob = reinterpret_cast<unsigned short*>(g_out1b);
    for (int c0 = 0; c0 < 256; c0 += 64) {
#pragma unroll
        for (int j = 0; j < 8; j++) {
            int cc = wy * 8 + j;
            t[cc][lane] = g_out1[(size_t)(c0 + cc) * NN + px0 + lane];
        }
        __syncthreads();
        int px = tid >> 3, g = tid & 7;
        __align__(16) unsigned short his[8];
#pragma unroll
        for (int j = 0; j < 8; j++) {
            int cc = g * 8 + j;
            float v = fmaxf(fmaf(t[cc][px], sS[c0 + cc], sH[c0 + cc]), 0.f);
            his[j] = f2h(v);
        }
        unsigned short* row = ob + (size_t)(px0 + px) * O1ROW;
        *reinterpret_cast<uint4*>(row + c0 + g * 8) = *reinterpret_cast<const uint4*>(his);
        __syncthreads();
    }
}

// ---------------- mma.sync fp16 GEMM, CTA tile 128x256, K=2304 --------------
// grid (2, 64). kc: kpt=kc/4, part=kc%4 -> channels [64*part, +64).
__global__ __launch_bounds__(256, 1)
void k_gemm_mma(int wsel, const float* __restrict__ bias, int outsel, int implicitB) {
    extern __shared__ char smem[];
    uint32_t sb = smem_u32(smem);
    int tid = threadIdx.x;
    int m0 = blockIdx.x * 128;
    int n0 = blockIdx.y * 256;

    const __half* Ag = wsel ? g_wA2 : g_wA1;
    float* Cg = outsel ? g_out2 : g_out1;
    const char* Abase = reinterpret_cast<const char*>(Ag) + (size_t)m0 * (CKK * 2);
    const char* Bbase = reinterpret_cast<const char*>(g_colb) + (size_t)n0 * (COLROW * 2);
    const char* Obase = reinterpret_cast<const char*>(g_out1b);

    auto load_stage = [&](int kc, int s) {
        uint32_t st = sb + s * STAGE_SZ;
        size_t kb = (size_t)kc * 128;
        int kpt = kc >> 2, part = kc & 3;
        uint32_t srcoff = ((uint32_t)part) << 7;    // channel chunk within kpt
        if (!implicitB) {
#pragma unroll
            for (int i = 0; i < 12; i++) {
                int idx = tid + i * 256;
                if (idx < 1024) {
                    int r = idx >> 3, c = idx & 7;
                    uint32_t off = SWZ128(r * 128 + c * 16);
                    CP_ASYNC16(st + off, Abase + (size_t)r * (CKK * 2) + kb + c * 16);
                } else {
                    int j = idx - 1024;
                    int r = j >> 3, c = j & 7;
                    uint32_t off = SWZ128(r * 128 + c * 16);
                    CP_ASYNC16(st + 16384 + off,
                               Bbase + (size_t)r * (COLROW * 2) + kpt * 512 + srcoff + c * 16);
                }
            }
        } else {
            int ki = kpt / 3, kj = kpt - 3 * ki;
            int dn = (ki - 1) * 64 + (kj - 1);
#pragma unroll
            for (int i = 0; i < 12; i++) {
                int idx = tid + i * 256;
                if (idx < 1024) {
                    int r = idx >> 3, c = idx & 7;
                    uint32_t off = SWZ128(r * 128 + c * 16);
                    CP_ASYNC16(st + off, Abase + (size_t)r * (CKK * 2) + kb + c * 16);
                } else {
                    int j = idx - 1024;
                    int r = j >> 3, c = j & 7;
                    int n = n0 + r;
                    int h = (n >> 6) & 63, w = n & 63;
                    int y = h - 1 + ki, xw = w - 1 + kj;
                    bool valid = ((unsigned)y < 64u) && ((unsigned)xw < 64u);
                    int np = valid ? n + dn : 0;
                    uint32_t sz = valid ? 16u : 0u;
                    uint32_t off = SWZ128(r * 128 + c * 16);
                    CP_ASYNC16Z(st + 16384 + off,
                                Obase + (size_t)np * 512 + srcoff + c * 16, sz);
                }
            }
        }
        CP_COMMIT();
    };

    int lane = tid & 31, w = tid >> 5;
    int wm = w >> 1, wn = w & 1;       // 4x2 warp grid
    int mW = wm * 32, nW = wn * 128;   // warp tile 32x128
    int gq = lane >> 3, rr = lane & 7;
    int rowin = (gq & 1) * 8 + rr;
    int kboff = (gq >> 1) * 16;

    float acc[2][16][4];
#pragma unroll
    for (int mt = 0; mt < 2; mt++)
#pragma unroll
        for (int j = 0; j < 16; j++)
#pragma unroll
            for (int q = 0; q < 4; q++) acc[mt][j][q] = 0.f;

    uint32_t aOff[2], aXor[2], bOff[8], bXor[8];
#pragma unroll
    for (int mt = 0; mt < 2; mt++) {
        int row = mW + mt * 16 + rowin;
        aOff[mt] = row * 128;
        aXor[mt] = (row & 7) << 4;
    }
#pragma unroll
    for (int nt = 0; nt < 8; nt++) {
        int row = nW + nt * 16 + rowin;
        bOff[nt] = row * 128;
        bXor[nt] = (row & 7) << 4;
    }

    load_stage(0, 0);
    load_stage(1, 1);
    load_stage(2, 2);

    for (int k = 0; k < NUM_KCH; k++) {
        int s = k % NSTAGE;
        uint32_t stA = sb + s * STAGE_SZ;
        uint32_t stB = stA + 16384;
        CP_WAIT2();
        __syncthreads();

#pragma unroll
        for (int ks = 0; ks < 4; ks++) {
            uint32_t kb = ks * 32 + kboff;
            uint32_t af[2][4];
#pragma unroll
            for (int mt = 0; mt < 2; mt++)
                LDSM4(af[mt][0], af[mt][1], af[mt][2], af[mt][3],
                      stA + aOff[mt] + (kb ^ aXor[mt]));
#pragma unroll
            for (int nt = 0; nt < 8; nt++) {
                uint32_t bf0, bf1, bf2, bf3;
                LDSM4(bf0, bf1, bf2, bf3, stB + bOff[nt] + (kb ^ bXor[nt]));
#pragma unroll
                for (int mt = 0; mt < 2; mt++) {
                    MMA16816F16(acc[mt][nt * 2], af[mt][0], af[mt][1], af[mt][2], af[mt][3],
                                bf0, bf2);
                    MMA16816F16(acc[mt][nt * 2 + 1], af[mt][0], af[mt][1], af[mt][2], af[mt][3],
                                bf1, bf3);
                }
            }
        }
        __syncthreads();
        if (k + 3 < NUM_KCH) load_stage(k + 3, s);
        else CP_COMMIT();
    }

    int qr = lane >> 2;
    int qc = (lane & 3) * 2;
#pragma unroll
    for (int mt = 0; mt < 2; mt++) {
        int row0 = m0 + mW + mt * 16 + qr;
        float bv0 = bias ? bias[row0] : 0.f;
        float bv1 = bias ? bias[row0 + 8] : 0.f;
#pragma unroll
        for (int j = 0; j < 16; j++) {
            int col = n0 + nW + j * 8 + qc;
            float2 v0 = make_float2(acc[mt][j][0] + bv0, acc[mt][j][1] + bv0);
            float2 v1 = make_float2(acc[mt][j][2] + bv1, acc[mt][j][3] + bv1);
            *reinterpret_cast<float2*>(Cg + (size_t)row0 * NN + col) = v0;
            *reinterpret_cast<float2*>(Cg + (size_t)(row0 + 8) * NN + col) = v1;
        }
    }
}

// ---------------- BN stats -> per-channel scale/shift ------------------------
__global__ __launch_bounds__(256)
void k_bnstats(const float* __restrict__ gamma, const float* __restrict__ beta, int sel) {
    const float* src = sel ? g_out2 : g_out1;
    float* scale = sel ? g_scale2 : g_scale1;
    float* shift = sel ? g_shift2 : g_shift1;
    int ch = blockIdx.x;
    const float* p = src + (size_t)ch * NN;
    float s = 0.f, sq = 0.f;
    for (int i = threadIdx.x; i < NN; i += 256) {
        float v = p[i];
        s += v;
        sq = fmaf(v, v, sq);
    }
    __shared__ float rs[256], rq[256];
    int t = threadIdx.x;
    rs[t] = s; rq[t] = sq;
    __syncthreads();
    for (int off = 128; off > 0; off >>= 1) {
        if (t < off) { rs[t] += rs[t + off]; rq[t] += rq[t + off]; }
        __syncthreads();
    }
    if (t == 0) {
        float mean = rs[0] * (1.f / NN);
        float var = fmaxf(rq[0] * (1.f / NN) - mean * mean, 0.f);
        float inv = rsqrtf(var + EPSB);
        float sc = inv * gamma[ch];
        scale[ch] = sc;
        shift[ch] = beta[ch] - mean * sc;
    }
}

// ---------------- final: relu(bn2(out2) + x) in NCHW ------------------------
__global__ __launch_bounds__(256)
void k_final(const float* __restrict__ x, float* __restrict__ out) {
    int i = blockIdx.x * 256 + threadIdx.x;
    int hw = i & 4095;
    int o = (i >> 12) & 255;
    int b = i >> 20;
    float v = fmaf(g_out2[(size_t)o * NN + b * HWW + hw], g_scale2[o], g_shift2[o]) + x[i];
    out[i] = fmaxf(v, 0.f);
}

// ---------------- launch -----------------------------------------------------
extern "C" void kernel_launch(void* const* d_in, const int* in_sizes, int n_in,
                              void* d_out, int out_size) {
    const float* x     = (const float*)d_in[0];
    const float* off_w = (const float*)d_in[1];
    const float* off_b = (const float*)d_in[2];
    const float* dw    = (const float*)d_in[3];
    const float* db    = (const float*)d_in[4];
    const float* bn1_g = (const float*)d_in[5];
    const float* bn1_b = (const float*)d_in[6];
    const float* w2    = (const float*)d_in[7];
    const float* bn2_g = (const float*)d_in[8];
    const float* bn2_b = (const float*)d_in[9];
    float* out = (float*)d_out;

    cudaFuncSetAttribute(k_gemm_mma, cudaFuncAttributeMaxDynamicSharedMemorySize, GEMM_SMEM);

    k_zero_offset<<<(BB * 18 * HWW + 255) / 256, 256>>>();
    k_transpose_x<<<dim3(NN / 32, 8), 256>>>(x);
    k_offset_conv<<<dim3(64, 4), 256>>>(x, off_w, off_b);
    k_wprep<<<dim3((OO * CKK + 255) / 256, 2), 256>>>(dw, w2);
    k_im2col_deform<<<NN / 32, 256>>>();
    k_gemm_mma<<<dim3(2, 64), 256, GEMM_SMEM>>>(0, db, 0, 0);
    k_bnstats<<<256, 256>>>(bn1_g, bn1_b, 0);
    k_convert1<<<NN / 32, 256>>>();
    k_gemm_mma<<<dim3(2, 64), 256, GEMM_SMEM>>>(1, nullptr, 1, 1);
    k_bnstats<<<256, 256>>>(bn2_g, bn2_b, 1);
    k_final<<<(BB * OO * HWW + 255) / 256, 256>>>(x, out);
}

// round 12
// speedup vs baseline: 4.2055x; 1.0993x over previous
#include <cuda_runtime.h>
#include <cuda_fp16.h>
#include <cstdint>

#define BB 4
#define CC 256
#define OO 256
#define HWW 4096
#define NN 16384          // BB*HWW
#define CKK 2304          // CC*9 — plain fp16 K
#define EPSB 1e-5f
#define FNN 16384.0f

#define NSTAGE 3
#define STAGE_SZ 49152      // A 16KB + B 32KB per stage
#define GEMM_SMEM (NSTAGE * STAGE_SZ)
#define NUM_KCH 36          // CKK*2 bytes / 128B per chunk

#define COLROW 2304         // per pixel: 9 kpt x 256 fp16
#define O1ROW 256           // per pixel: 256 fp16

// ---------------- scratch (device globals; no allocs allowed) ----------------
__device__ float g_offset[BB * 18 * HWW];                       // 4.7 MB
__device__ __half g_xpm[(size_t)NN * CC];                       // 32 MB NHWC fp16 x
__device__ __half g_colb[(size_t)NN * COLROW];                  // 75.5 MB
__device__ __half g_wA1[(size_t)OO * CKK];                      // 1.2 MB [m][k]
__device__ __half g_wA2[(size_t)OO * CKK];
__device__ float g_out1[(size_t)OO * NN];                       // 16.8 MB [o][n]
__device__ float g_out2[(size_t)OO * NN];
__device__ __half g_out1b[(size_t)NN * O1ROW];                  // 8.4 MB
__device__ float g_scale1[OO], g_shift1[OO], g_scale2[OO], g_shift2[OO];
__device__ float g_bnsum1[OO], g_bnsq1[OO], g_bnsum2[OO], g_bnsq2[OO];

// ---------------- helpers ----------------------------------------------------
__device__ __forceinline__ uint32_t smem_u32(const void* p) {
    uint32_t a;
    asm("{ .reg .u64 t; cvta.to.shared.u64 t, %1; cvt.u32.u64 %0, t; }" : "=r"(a) : "l"(p));
    return a;
}
#define SWZ128(o) ((o) ^ (((o) >> 3) & 0x70))
#define CP_ASYNC16(dst, src) \
    asm volatile("cp.async.cg.shared.global [%0], [%1], 16;" :: "r"(dst), "l"(src))
#define CP_ASYNC16Z(dst, src, sz) \
    asm volatile("cp.async.cg.shared.global [%0], [%1], 16, %2;" :: "r"(dst), "l"(src), "r"(sz))
#define CP_COMMIT() asm volatile("cp.async.commit_group;" ::: "memory")
#define CP_WAIT2()  asm volatile("cp.async.wait_group 2;" ::: "memory")

#define LDSM4(r0, r1, r2, r3, addr) \
    asm volatile("ldmatrix.sync.aligned.m8n8.x4.shared.b16 {%0,%1,%2,%3}, [%4];" \
                 : "=r"(r0), "=r"(r1), "=r"(r2), "=r"(r3) : "r"(addr))

#define MMA16816F16(d, a0, a1, a2, a3, b0, b1) \
    asm volatile("mma.sync.aligned.m16n8k16.row.col.f32.f16.f16.f32 " \
                 "{%0,%1,%2,%3},{%4,%5,%6,%7},{%8,%9},{%0,%1,%2,%3};" \
                 : "+f"((d)[0]), "+f"((d)[1]), "+f"((d)[2]), "+f"((d)[3]) \
                 : "r"(a0), "r"(a1), "r"(a2), "r"(a3), "r"(b0), "r"(b1))

__device__ __forceinline__ unsigned short f2h(float v) {
    __half h = __float2half_rn(v);
    return *reinterpret_cast<unsigned short*>(&h);
}

// ---------------- zero offset + stats ----------------------------------------
__global__ void k_zero_offset() {
    int i = blockIdx.x * 256 + threadIdx.x;
    if (i < BB * 18 * HWW) g_offset[i] = 0.f;
    if (i < OO) { g_bnsum1[i] = 0.f; g_bnsq1[i] = 0.f; g_bnsum2[i] = 0.f; g_bnsq2[i] = 0.f; }
}

// ---------------- transpose x: NCHW fp32 -> NHWC fp16 (g_xpm) ---------------
// block: 32 pixels x 64 channels. grid (NN/32, 4).
__global__ __launch_bounds__(256)
void k_transpose_x(const float* __restrict__ x) {
    __shared__ float t[64][33];
    int n0 = blockIdx.x * 32;
    int c0 = blockIdx.y * 64;
    int b = n0 >> 12;
    int hw0 = n0 & 4095;
    int lane = threadIdx.x & 31, wy = threadIdx.x >> 5;
#pragma unroll
    for (int j = 0; j < 8; j++) {
        int cc = wy * 8 + j;
        t[cc][lane] = x[((size_t)b * CC + c0 + cc) * HWW + hw0 + lane];
    }
    __syncthreads();
    // each warp writes 4 pixels x 64 channels (128B fp16 per pixel)
#pragma unroll
    for (int j = 0; j < 4; j++) {
        int px = wy * 4 + j;
        __half2 h = __floats2half2_rn(t[lane * 2][px], t[lane * 2 + 1][px]);
        *reinterpret_cast<__half2*>(g_xpm + (size_t)(n0 + px) * CC + c0 + lane * 2) = h;
    }
}

// ---------------- offset conv: 3x3, dil=2, pad=2, 256->18 -------------------
__global__ __launch_bounds__(256)
void k_offset_conv(const float* __restrict__ x, const float* __restrict__ off_w,
                   const float* __restrict__ off_b) {
    __shared__ float sw[18 * 64 * 9];
    int c0 = blockIdx.y * 64;
    for (int idx = threadIdx.x; idx < 18 * 64 * 9; idx += 256) {
        int oc = idx / 576;
        int rem = idx - oc * 576;
        sw[idx] = off_w[oc * CKK + c0 * 9 + rem];
    }
    __syncthreads();

    int n = blockIdx.x * 256 + threadIdx.x;
    int b = n >> 12, hw = n & 4095;
    int h = hw >> 6, w = hw & 63;

    float acc[18];
#pragma unroll
    for (int oc = 0; oc < 18; oc++) acc[oc] = 0.f;

    const float* xb = x + ((size_t)b * CC + c0) * HWW;
    for (int cc = 0; cc < 64; cc++) {
        const float* xc = xb + cc * HWW;
#pragma unroll
        for (int i = 0; i < 3; i++) {
            int y = h - 2 + 2 * i;
            if ((unsigned)y >= 64u) continue;
#pragma unroll
            for (int j = 0; j < 3; j++) {
                int xx = w - 2 + 2 * j;
                if ((unsigned)xx >= 64u) continue;
                float v = xc[(y << 6) + xx];
                const float* wp = &sw[cc * 9 + i * 3 + j];
#pragma unroll
                for (int oc = 0; oc < 18; oc++)
                    acc[oc] = fmaf(v, wp[oc * 576], acc[oc]);
            }
        }
    }
    float* op = g_offset + (size_t)b * 18 * HWW + hw;
    if (blockIdx.y == 0) {
#pragma unroll
        for (int oc = 0; oc < 18; oc++) atomicAdd(&op[oc * HWW], acc[oc] + off_b[oc]);
    } else {
#pragma unroll
        for (int oc = 0; oc < 18; oc++) atomicAdd(&op[oc * HWW], acc[oc]);
    }
}

// ---------------- weight prep: fp32 W -> fp16 A' [m][kpt*256+c] -------------
__global__ __launch_bounds__(256)
void k_wprep(const float* __restrict__ dw, const float* __restrict__ w2) {
    int idx = blockIdx.x * 256 + threadIdx.x;
    if (idx >= OO * CKK) return;
    int m = idx / CKK;
    int ck = idx - m * CKK;
    int c = ck / 9, kpt = ck - c * 9;
    const float* w = blockIdx.y ? w2 : dw;
    __half* dst = blockIdx.y ? g_wA2 : g_wA1;
    reinterpret_cast<unsigned short*>(dst)[(size_t)m * CKK + kpt * 256 + c] = f2h(w[idx]);
}

// ---------------- deformable im2col: NHWC fp16 gather -----------------------
__global__ __launch_bounds__(256)
void k_im2col_deform() {
    __shared__ float4 wts[9][32];
    __shared__ int4 idxs[9][32];

    int n0 = blockIdx.x * 32;
    int b = n0 >> 12;

    for (int t = threadIdx.x; t < 288; t += 256) {
        int kpt = t >> 5, px = t & 31;
        int n = n0 + px;
        int hw = n & 4095;
        int h = hw >> 6, w = hw & 63;
        int ki = kpt / 3, kj = kpt - ki * 3;
        float offy = g_offset[((size_t)b * 18 + 2 * kpt) * HWW + hw];
        float offx = g_offset[((size_t)b * 18 + 2 * kpt + 1) * HWW + hw];
        float py = (float)(h - 2 + 2 * ki) + offy;
        float pxx = (float)(w - 2 + 2 * kj) + offx;
        float fy0 = floorf(py), fx0 = floorf(pxx);
        int y0 = (int)fy0, x0 = (int)fx0;
        int y1 = y0 + 1, x1 = x0 + 1;
        float wy1 = py - fy0, wx1 = pxx - fx0;
        float wy0 = 1.f - wy1, wx0 = 1.f - wx1;
        bool vy0 = (unsigned)y0 < 64u, vy1 = (unsigned)y1 < 64u;
        bool vx0 = (unsigned)x0 < 64u, vx1 = (unsigned)x1 < 64u;
        float w00 = (vy0 && vx0) ? wy0 * wx0 : 0.f;
        float w01 = (vy0 && vx1) ? wy0 * wx1 : 0.f;
        float w10 = (vy1 && vx0) ? wy1 * wx0 : 0.f;
        float w11 = (vy1 && vx1) ? wy1 * wx1 : 0.f;
        int yc0 = min(max(y0, 0), 63), yc1 = min(max(y1, 0), 63);
        int xc0 = min(max(x0, 0), 63), xc1 = min(max(x1, 0), 63);
        int gb = b << 12;
        wts[kpt][px] = make_float4(w00, w01, w10, w11);
        idxs[kpt][px] = make_int4(gb + (yc0 << 6) + xc0, gb + (yc0 << 6) + xc1,
                                  gb + (yc1 << 6) + xc0, gb + (yc1 << 6) + xc1);
    }
    __syncthreads();

    int wid = threadIdx.x >> 5, lane = threadIdx.x & 31;
    int c8 = lane * 8;
    unsigned short* colbase = reinterpret_cast<unsigned short*>(g_colb);

    for (int task = wid; task < 288; task += 8) {
        int kpt = task >> 5, px = task & 31;
        float4 wv = wts[kpt][px];
        int4 iv = idxs[kpt][px];
        uint4 u00 = *reinterpret_cast<const uint4*>(g_xpm + (size_t)iv.x * CC + c8);
        uint4 u01 = *reinterpret_cast<const uint4*>(g_xpm + (size_t)iv.y * CC + c8);
        uint4 u10 = *reinterpret_cast<const uint4*>(g_xpm + (size_t)iv.z * CC + c8);
        uint4 u11 = *reinterpret_cast<const uint4*>(g_xpm + (size_t)iv.w * CC + c8);
        const __half2* h00 = reinterpret_cast<const __half2*>(&u00);
        const __half2* h01 = reinterpret_cast<const __half2*>(&u01);
        const __half2* h10 = reinterpret_cast<const __half2*>(&u10);
        const __half2* h11 = reinterpret_cast<const __half2*>(&u11);
        __align__(16) unsigned short his[8];
#pragma unroll
        for (int q = 0; q < 4; q++) {
            float2 a = __half22float2(h00[q]);
            float2 bq = __half22float2(h01[q]);
            float2 c = __half22float2(h10[q]);
            float2 d = __half22float2(h11[q]);
            float v0 = wv.x * a.x + wv.y * bq.x + wv.z * c.x + wv.w * d.x;
            float v1 = wv.x * a.y + wv.y * bq.y + wv.z * c.y + wv.w * d.y;
            his[q * 2] = f2h(v0);
            his[q * 2 + 1] = f2h(v1);
        }
        unsigned short* row = colbase + (size_t)(n0 + px) * COLROW + kpt * 256;
        *reinterpret_cast<uint4*>(row + c8) = *reinterpret_cast<const uint4*>(his);
    }
}

// ---------------- bn finalize: sums -> scale/shift (1 block) -----------------
__global__ void k_bnfin(const float* __restrict__ gamma, const float* __restrict__ beta,
                        int sel) {
    int ch = threadIdx.x;
    float s = sel ? g_bnsum2[ch] : g_bnsum1[ch];
    float q = sel ? g_bnsq2[ch] : g_bnsq1[ch];
    float mean = s * (1.f / FNN);
    float var = fmaxf(q * (1.f / FNN) - mean * mean, 0.f);
    float inv = rsqrtf(var + EPSB);
    float sc = inv * gamma[ch];
    if (sel) { g_scale2[ch] = sc; g_shift2[ch] = beta[ch] - mean * sc; }
    else     { g_scale1[ch] = sc; g_shift1[ch] = beta[ch] - mean * sc; }
}

// ---------------- convert1: out1 -> pixel-major fp16 (BN1+ReLU) -------------
__global__ __launch_bounds__(256)
void k_convert1() {
    __shared__ float t[64][33];
    __shared__ float sS[256], sH[256];
    int px0 = blockIdx.x * 32;
    int tid = threadIdx.x;
    int lane = tid & 31, wy = tid >> 5;
    for (int i = tid; i < 256; i += 256) { sS[i] = g_scale1[i]; sH[i] = g_shift1[i]; }
    __syncthreads();

    unsigned short* ob = reinterpret_cast<unsigned short*>(g_out1b);
    for (int c0 = 0; c0 < 256; c0 += 64) {
#pragma unroll
        for (int j = 0; j < 8; j++) {
            int cc = wy * 8 + j;
            t[cc][lane] = g_out1[(size_t)(c0 + cc) * NN + px0 + lane];
        }
        __syncthreads();
        int px = tid >> 3, g = tid & 7;
        __align__(16) unsigned short his[8];
#pragma unroll
        for (int j = 0; j < 8; j++) {
            int cc = g * 8 + j;
            float v = fmaxf(fmaf(t[cc][px], sS[c0 + cc], sH[c0 + cc]), 0.f);
            his[j] = f2h(v);
        }
        unsigned short* row = ob + (size_t)(px0 + px) * O1ROW;
        *reinterpret_cast<uint4*>(row + c0 + g * 8) = *reinterpret_cast<const uint4*>(his);
        __syncthreads();
    }
}

// ---------------- mma.sync fp16 GEMM, 128x256, K=2304, fused BN stats -------
__global__ __launch_bounds__(256, 1)
void k_gemm_mma(int wsel, const float* __restrict__ bias, int outsel, int implicitB) {
    extern __shared__ char smem[];
    uint32_t sb = smem_u32(smem);
    int tid = threadIdx.x;
    int m0 = blockIdx.x * 128;
    int n0 = blockIdx.y * 256;

    const __half* Ag = wsel ? g_wA2 : g_wA1;
    float* Cg = outsel ? g_out2 : g_out1;
    float* bns = outsel ? g_bnsum2 : g_bnsum1;
    float* bnq = outsel ? g_bnsq2 : g_bnsq1;
    const char* Abase = reinterpret_cast<const char*>(Ag) + (size_t)m0 * (CKK * 2);
    const char* Bbase = reinterpret_cast<const char*>(g_colb) + (size_t)n0 * (COLROW * 2);
    const char* Obase = reinterpret_cast<const char*>(g_out1b);

    auto load_stage = [&](int kc, int s) {
        uint32_t st = sb + s * STAGE_SZ;
        size_t kb = (size_t)kc * 128;
        int kpt = kc >> 2, part = kc & 3;
        uint32_t srcoff = ((uint32_t)part) << 7;
        if (!implicitB) {
#pragma unroll
            for (int i = 0; i < 12; i++) {
                int idx = tid + i * 256;
                if (idx < 1024) {
                    int r = idx >> 3, c = idx & 7;
                    uint32_t off = SWZ128(r * 128 + c * 16);
                    CP_ASYNC16(st + off, Abase + (size_t)r * (CKK * 2) + kb + c * 16);
                } else {
                    int j = idx - 1024;
                    int r = j >> 3, c = j & 7;
                    uint32_t off = SWZ128(r * 128 + c * 16);
                    CP_ASYNC16(st + 16384 + off,
                               Bbase + (size_t)r * (COLROW * 2) + kpt * 512 + srcoff + c * 16);
                }
            }
        } else {
            int ki = kpt / 3, kj = kpt - 3 * ki;
            int dn = (ki - 1) * 64 + (kj - 1);
#pragma unroll
            for (int i = 0; i < 12; i++) {
                int idx = tid + i * 256;
                if (idx < 1024) {
                    int r = idx >> 3, c = idx & 7;
                    uint32_t off = SWZ128(r * 128 + c * 16);
                    CP_ASYNC16(st + off, Abase + (size_t)r * (CKK * 2) + kb + c * 16);
                } else {
                    int j = idx - 1024;
                    int r = j >> 3, c = j & 7;
                    int n = n0 + r;
                    int h = (n >> 6) & 63, w = n & 63;
                    int y = h - 1 + ki, xw = w - 1 + kj;
                    bool valid = ((unsigned)y < 64u) && ((unsigned)xw < 64u);
                    int np = valid ? n + dn : 0;
                    uint32_t sz = valid ? 16u : 0u;
                    uint32_t off = SWZ128(r * 128 + c * 16);
                    CP_ASYNC16Z(st + 16384 + off,
                                Obase + (size_t)np * 512 + srcoff + c * 16, sz);
                }
            }
        }
        CP_COMMIT();
    };

    int lane = tid & 31, w = tid >> 5;
    int wm = w >> 1, wn = w & 1;
    int mW = wm * 32, nW = wn * 128;
    int gq = lane >> 3, rr = lane & 7;
    int rowin = (gq & 1) * 8 + rr;
    int kboff = (gq >> 1) * 16;

    float acc[2][16][4];
#pragma unroll
    for (int mt = 0; mt < 2; mt++)
#pragma unroll
        for (int j = 0; j < 16; j++)
#pragma unroll
            for (int q = 0; q < 4; q++) acc[mt][j][q] = 0.f;

    uint32_t aOff[2], aXor[2], bOff[8], bXor[8];
#pragma unroll
    for (int mt = 0; mt < 2; mt++) {
        int row = mW + mt * 16 + rowin;
        aOff[mt] = row * 128;
        aXor[mt] = (row & 7) << 4;
    }
#pragma unroll
    for (int nt = 0; nt < 8; nt++) {
        int row = nW + nt * 16 + rowin;
        bOff[nt] = row * 128;
        bXor[nt] = (row & 7) << 4;
    }

    load_stage(0, 0);
    load_stage(1, 1);
    load_stage(2, 2);

    for (int k = 0; k < NUM_KCH; k++) {
        int s = k % NSTAGE;
        uint32_t stA = sb + s * STAGE_SZ;
        uint32_t stB = stA + 16384;
        CP_WAIT2();
        __syncthreads();

#pragma unroll
        for (int ks = 0; ks < 4; ks++) {
            uint32_t kb = ks * 32 + kboff;
            uint32_t af[2][4];
#pragma unroll
            for (int mt = 0; mt < 2; mt++)
                LDSM4(af[mt][0], af[mt][1], af[mt][2], af[mt][3],
                      stA + aOff[mt] + (kb ^ aXor[mt]));
#pragma unroll
            for (int nt = 0; nt < 8; nt++) {
                uint32_t bf0, bf1, bf2, bf3;
                LDSM4(bf0, bf1, bf2, bf3, stB + bOff[nt] + (kb ^ bXor[nt]));
#pragma unroll
                for (int mt = 0; mt < 2; mt++) {
                    MMA16816F16(acc[mt][nt * 2], af[mt][0], af[mt][1], af[mt][2], af[mt][3],
                                bf0, bf2);
                    MMA16816F16(acc[mt][nt * 2 + 1], af[mt][0], af[mt][1], af[mt][2], af[mt][3],
                                bf1, bf3);
                }
            }
        }
        __syncthreads();
        if (k + 3 < NUM_KCH) load_stage(k + 3, s);
        else CP_COMMIT();
    }

    // epilogue: write C (+bias) and accumulate per-row BN partial sums
    int qr = lane >> 2;
    int qc = (lane & 3) * 2;
#pragma unroll
    for (int mt = 0; mt < 2; mt++) {
        int row0 = m0 + mW + mt * 16 + qr;
        float bv0 = bias ? bias[row0] : 0.f;
        float bv1 = bias ? bias[row0 + 8] : 0.f;
        float s0 = 0.f, q0 = 0.f, s1 = 0.f, q1 = 0.f;
#pragma unroll
        for (int j = 0; j < 16; j++) {
            int col = n0 + nW + j * 8 + qc;
            float2 v0 = make_float2(acc[mt][j][0] + bv0, acc[mt][j][1] + bv0);
            float2 v1 = make_float2(acc[mt][j][2] + bv1, acc[mt][j][3] + bv1);
            s0 += v0.x + v0.y;
            q0 = fmaf(v0.x, v0.x, fmaf(v0.y, v0.y, q0));
            s1 += v1.x + v1.y;
            q1 = fmaf(v1.x, v1.x, fmaf(v1.y, v1.y, q1));
            *reinterpret_cast<float2*>(Cg + (size_t)row0 * NN + col) = v0;
            *reinterpret_cast<float2*>(Cg + (size_t)(row0 + 8) * NN + col) = v1;
        }
        // reduce over the 4 lanes sharing each row
        s0 += __shfl_xor_sync(0xffffffff, s0, 1);
        s0 += __shfl_xor_sync(0xffffffff, s0, 2);
        q0 += __shfl_xor_sync(0xffffffff, q0, 1);
        q0 += __shfl_xor_sync(0xffffffff, q0, 2);
        s1 += __shfl_xor_sync(0xffffffff, s1, 1);
        s1 += __shfl_xor_sync(0xffffffff, s1, 2);
        q1 += __shfl_xor_sync(0xffffffff, q1, 1);
        q1 += __shfl_xor_sync(0xffffffff, q1, 2);
        if ((lane & 3) == 0) {
            atomicAdd(&bns[row0], s0);
            atomicAdd(&bnq[row0], q0);
            atomicAdd(&bns[row0 + 8], s1);
            atomicAdd(&bnq[row0 + 8], q1);
        }
    }
}

// ---------------- final: relu(bn2(out2) + x) in NCHW ------------------------
__global__ __launch_bounds__(256)
void k_final(const float* __restrict__ x, float* __restrict__ out) {
    int i = blockIdx.x * 256 + threadIdx.x;
    int hw = i & 4095;
    int o = (i >> 12) & 255;
    int b = i >> 20;
    float v = fmaf(g_out2[(size_t)o * NN + b * HWW + hw], g_scale2[o], g_shift2[o]) + x[i];
    out[i] = fmaxf(v, 0.f);
}

// ---------------- launch -----------------------------------------------------
extern "C" void kernel_launch(void* const* d_in, const int* in_sizes, int n_in,
                              void* d_out, int out_size) {
    const float* x     = (const float*)d_in[0];
    const float* off_w = (const float*)d_in[1];
    const float* off_b = (const float*)d_in[2];
    const float* dw    = (const float*)d_in[3];
    const float* db    = (const float*)d_in[4];
    const float* bn1_g = (const float*)d_in[5];
    const float* bn1_b = (const float*)d_in[6];
    const float* w2    = (const float*)d_in[7];
    const float* bn2_g = (const float*)d_in[8];
    const float* bn2_b = (const float*)d_in[9];
    float* out = (float*)d_out;

    cudaFuncSetAttribute(k_gemm_mma, cudaFuncAttributeMaxDynamicSharedMemorySize, GEMM_SMEM);

    k_zero_offset<<<(BB * 18 * HWW + 255) / 256, 256>>>();
    k_transpose_x<<<dim3(NN / 32, 4), 256>>>(x);
    k_offset_conv<<<dim3(64, 4), 256>>>(x, off_w, off_b);
    k_wprep<<<dim3((OO * CKK + 255) / 256, 2), 256>>>(dw, w2);
    k_im2col_deform<<<NN / 32, 256>>>();
    k_gemm_mma<<<dim3(2, 64), 256, GEMM_SMEM>>>(0, db, 0, 0);
    k_bnfin<<<1, 256>>>(bn1_g, bn1_b, 0);
    k_convert1<<<NN / 32, 256>>>();
    k_gemm_mma<<<dim3(2, 64), 256, GEMM_SMEM>>>(1, nullptr, 1, 1);
    k_bnfin<<<1, 256>>>(bn2_g, bn2_b, 1);
    k_final<<<(BB * OO * HWW + 255) / 256, 256>>>(x, out);
}

// round 13
// speedup vs baseline: 5.8731x; 1.3965x over previous
#include <cuda_runtime.h>
#include <cuda_fp16.h>
#include <cstdint>

#define BB 4
#define CC 256
#define OO 256
#define HWW 4096
#define NN 16384          // BB*HWW
#define CKK 2304          // CC*9 — plain fp16 K
#define EPSB 1e-5f
#define FNN 16384.0f

#define NSTAGE 3
#define STAGE_SZ 49152      // A 16KB + B 32KB per stage (main GEMM)
#define GEMM_SMEM (NSTAGE * STAGE_SZ)
#define NUM_KCH 36          // CKK*2 bytes / 128B per chunk

#define OFF_STAGE 20480     // A 4KB (32 rows) + B 16KB (128 rows)
#define OFF_SMEM (NSTAGE * OFF_STAGE)

#define COLROW 2304         // per pixel: 9 kpt x 256 fp16
#define O1ROW 256           // per pixel: 256 fp16

// ---------------- scratch (device globals; no allocs allowed) ----------------
__device__ float g_offset[BB * 18 * HWW];                       // 4.7 MB
__device__ __half g_xpm[(size_t)NN * CC];                       // 32 MB NHWC fp16 x
__device__ __half g_colb[(size_t)NN * COLROW];                  // 75.5 MB
__device__ __half g_wA1[(size_t)OO * CKK];                      // 1.2 MB [m][k]
__device__ __half g_wA2[(size_t)OO * CKK];
__device__ __half g_wOff[32 * CKK];                             // 147 KB (18 pad 32)
__device__ float g_out1[(size_t)OO * NN];                       // 16.8 MB [o][n]
__device__ float g_out2[(size_t)OO * NN];
__device__ __half g_out1b[(size_t)NN * O1ROW];                  // 8.4 MB
__device__ float g_scale1[OO], g_shift1[OO], g_scale2[OO], g_shift2[OO];
__device__ float g_bnsum1[OO], g_bnsq1[OO], g_bnsum2[OO], g_bnsq2[OO];

// ---------------- helpers ----------------------------------------------------
__device__ __forceinline__ uint32_t smem_u32(const void* p) {
    uint32_t a;
    asm("{ .reg .u64 t; cvta.to.shared.u64 t, %1; cvt.u32.u64 %0, t; }" : "=r"(a) : "l"(p));
    return a;
}
#define SWZ128(o) ((o) ^ (((o) >> 3) & 0x70))
#define CP_ASYNC16(dst, src) \
    asm volatile("cp.async.cg.shared.global [%0], [%1], 16;" :: "r"(dst), "l"(src))
#define CP_ASYNC16Z(dst, src, sz) \
    asm volatile("cp.async.cg.shared.global [%0], [%1], 16, %2;" :: "r"(dst), "l"(src), "r"(sz))
#define CP_COMMIT() asm volatile("cp.async.commit_group;" ::: "memory")
#define CP_WAIT2()  asm volatile("cp.async.wait_group 2;" ::: "memory")

#define LDSM4(r0, r1, r2, r3, addr) \
    asm volatile("ldmatrix.sync.aligned.m8n8.x4.shared.b16 {%0,%1,%2,%3}, [%4];" \
                 : "=r"(r0), "=r"(r1), "=r"(r2), "=r"(r3) : "r"(addr))

#define MMA16816F16(d, a0, a1, a2, a3, b0, b1) \
    asm volatile("mma.sync.aligned.m16n8k16.row.col.f32.f16.f16.f32 " \
                 "{%0,%1,%2,%3},{%4,%5,%6,%7},{%8,%9},{%0,%1,%2,%3};" \
                 : "+f"((d)[0]), "+f"((d)[1]), "+f"((d)[2]), "+f"((d)[3]) \
                 : "r"(a0), "r"(a1), "r"(a2), "r"(a3), "r"(b0), "r"(b1))

__device__ __forceinline__ unsigned short f2h(float v) {
    __half h = __float2half_rn(v);
    return *reinterpret_cast<unsigned short*>(&h);
}

// ---------------- zero: wOff pad rows + bn sums ------------------------------
__global__ void k_zero() {
    int i = blockIdx.x * 256 + threadIdx.x;
    if (i < 32 * CKK) reinterpret_cast<unsigned short*>(g_wOff)[i] = 0;
    if (i < OO) { g_bnsum1[i] = 0.f; g_bnsq1[i] = 0.f; g_bnsum2[i] = 0.f; g_bnsq2[i] = 0.f; }
}

// ---------------- transpose x: NCHW fp32 -> NHWC fp16 (g_xpm) ---------------
__global__ __launch_bounds__(256)
void k_transpose_x(const float* __restrict__ x) {
    __shared__ float t[64][33];
    int n0 = blockIdx.x * 32;
    int c0 = blockIdx.y * 64;
    int b = n0 >> 12;
    int hw0 = n0 & 4095;
    int lane = threadIdx.x & 31, wy = threadIdx.x >> 5;
#pragma unroll
    for (int j = 0; j < 8; j++) {
        int cc = wy * 8 + j;
        t[cc][lane] = x[((size_t)b * CC + c0 + cc) * HWW + hw0 + lane];
    }
    __syncthreads();
#pragma unroll
    for (int j = 0; j < 4; j++) {
        int px = wy * 4 + j;
        __half2 h = __floats2half2_rn(t[lane * 2][px], t[lane * 2 + 1][px]);
        *reinterpret_cast<__half2*>(g_xpm + (size_t)(n0 + px) * CC + c0 + lane * 2) = h;
    }
}

// ---------------- weight prep: fp32 -> fp16 [m][kpt*256+c]; y: 0=dw 1=w2 2=off
__global__ __launch_bounds__(256)
void k_wprep(const float* __restrict__ dw, const float* __restrict__ w2,
             const float* __restrict__ off_w) {
    int idx = blockIdx.x * 256 + threadIdx.x;
    int lim = (blockIdx.y == 2) ? 18 * CKK : OO * CKK;
    if (idx >= lim) return;
    int m = idx / CKK;
    int ck = idx - m * CKK;
    int c = ck / 9, kpt = ck - c * 9;
    const float* w = (blockIdx.y == 0) ? dw : (blockIdx.y == 1 ? w2 : off_w);
    __half* dst = (blockIdx.y == 0) ? g_wA1 : (blockIdx.y == 1 ? g_wA2 : g_wOff);
    reinterpret_cast<unsigned short*>(dst)[(size_t)m * CKK + kpt * 256 + c] = f2h(w[idx]);
}

// ---------------- offset conv as implicit fp16 GEMM: [18(32)x2304]@[2304xNN]
// grid 128: n-tile 128 pixels. 8 warps, warp tile 32x16.
__global__ __launch_bounds__(256, 2)
void k_gemm_off(const float* __restrict__ off_b) {
    extern __shared__ char smem[];
    uint32_t sb = smem_u32(smem);
    int tid = threadIdx.x;
    int n0 = blockIdx.x * 128;
    int b = n0 >> 12;

    const char* Abase = reinterpret_cast<const char*>(g_wOff);
    const char* Xbase = reinterpret_cast<const char*>(g_xpm);

    auto load_stage = [&](int kc, int s) {
        uint32_t st = sb + s * OFF_STAGE;
        int kpt = kc >> 2, part = kc & 3;
        uint32_t srcoff = ((uint32_t)part) << 7;
        int ki = kpt / 3, kj = kpt - 3 * ki;
        int dn = (ki - 1) * 128 + (kj - 1) * 2;   // dil=2 shifts
#pragma unroll
        for (int i = 0; i < 5; i++) {
            int idx = tid + i * 256;
            if (idx < 256) {
                int r = idx >> 3, c = idx & 7;
                uint32_t off = SWZ128(r * 128 + c * 16);
                CP_ASYNC16(st + off, Abase + (size_t)r * (CKK * 2) + (size_t)kc * 128 + c * 16);
            } else {
                int j = idx - 256;
                int r = j >> 3, c = j & 7;
                int n = n0 + r;
                int h = (n >> 6) & 63, w = n & 63;
                int y = h - 2 + 2 * ki, xw = w - 2 + 2 * kj;
                bool valid = ((unsigned)y < 64u) && ((unsigned)xw < 64u);
                int np = valid ? n + dn : 0;
                uint32_t sz = valid ? 16u : 0u;
                uint32_t off = SWZ128(r * 128 + c * 16);
                CP_ASYNC16Z(st + 4096 + off, Xbase + (size_t)np * 512 + srcoff + c * 16, sz);
            }
        }
        CP_COMMIT();
    };

    int lane = tid & 31, w = tid >> 5;
    int nW = w * 16;                 // 8 warps cover 128 n
    int gq = lane >> 3, rr = lane & 7;
    int rowin = (gq & 1) * 8 + rr;
    int kboff = (gq >> 1) * 16;

    float acc[2][2][4];
#pragma unroll
    for (int mt = 0; mt < 2; mt++)
#pragma unroll
        for (int j = 0; j < 2; j++)
#pragma unroll
            for (int q = 0; q < 4; q++) acc[mt][j][q] = 0.f;

    uint32_t aOff[2], aXor[2];
#pragma unroll
    for (int mt = 0; mt < 2; mt++) {
        int row = mt * 16 + rowin;
        aOff[mt] = row * 128;
        aXor[mt] = (row & 7) << 4;
    }
    uint32_t bOff = (nW + rowin) * 128;
    uint32_t bXor = ((nW + rowin) & 7) << 4;

    load_stage(0, 0);
    load_stage(1, 1);
    load_stage(2, 2);

    for (int k = 0; k < NUM_KCH; k++) {
        int s = k % NSTAGE;
        uint32_t stA = sb + s * OFF_STAGE;
        uint32_t stB = stA + 4096;
        CP_WAIT2();
        __syncthreads();

#pragma unroll
        for (int ks = 0; ks < 4; ks++) {
            uint32_t kb = ks * 32 + kboff;
            uint32_t af[2][4];
#pragma unroll
            for (int mt = 0; mt < 2; mt++)
                LDSM4(af[mt][0], af[mt][1], af[mt][2], af[mt][3],
                      stA + aOff[mt] + (kb ^ aXor[mt]));
            uint32_t bf0, bf1, bf2, bf3;
            LDSM4(bf0, bf1, bf2, bf3, stB + bOff + (kb ^ bXor));
#pragma unroll
            for (int mt = 0; mt < 2; mt++) {
                MMA16816F16(acc[mt][0], af[mt][0], af[mt][1], af[mt][2], af[mt][3], bf0, bf2);
                MMA16816F16(acc[mt][1], af[mt][0], af[mt][1], af[mt][2], af[mt][3], bf1, bf3);
            }
        }
        __syncthreads();
        if (k + 3 < NUM_KCH) load_stage(k + 3, s);
        else CP_COMMIT();
    }

    // epilogue: write rows < 18 to g_offset[(b*18+row)*HWW + hw] (+ off_b)
    int qr = lane >> 2;
    int qc = (lane & 3) * 2;
    int hw0 = (n0 & 4095) + nW + qc;
#pragma unroll
    for (int mt = 0; mt < 2; mt++) {
        int rowA = mt * 16 + qr;
        int rowB = rowA + 8;
#pragma unroll
        for (int j = 0; j < 2; j++) {
            int hw = hw0 + j * 8;
            if (rowA < 18) {
                float bv = off_b[rowA];
                float2 v = make_float2(acc[mt][j][0] + bv, acc[mt][j][1] + bv);
                *reinterpret_cast<float2*>(g_offset + (size_t)(b * 18 + rowA) * HWW + hw) = v;
            }
            if (rowB < 18) {
                float bv = off_b[rowB];
                float2 v = make_float2(acc[mt][j][2] + bv, acc[mt][j][3] + bv);
                *reinterpret_cast<float2*>(g_offset + (size_t)(b * 18 + rowB) * HWW + hw) = v;
            }
        }
    }
}

// ---------------- deformable im2col: NHWC fp16 gather -----------------------
__global__ __launch_bounds__(256)
void k_im2col_deform() {
    __shared__ float4 wts[9][32];
    __shared__ int4 idxs[9][32];

    int n0 = blockIdx.x * 32;
    int b = n0 >> 12;

    for (int t = threadIdx.x; t < 288; t += 256) {
        int kpt = t >> 5, px = t & 31;
        int n = n0 + px;
        int hw = n & 4095;
        int h = hw >> 6, w = hw & 63;
        int ki = kpt / 3, kj = kpt - ki * 3;
        float offy = g_offset[((size_t)b * 18 + 2 * kpt) * HWW + hw];
        float offx = g_offset[((size_t)b * 18 + 2 * kpt + 1) * HWW + hw];
        float py = (float)(h - 2 + 2 * ki) + offy;
        float pxx = (float)(w - 2 + 2 * kj) + offx;
        float fy0 = floorf(py), fx0 = floorf(pxx);
        int y0 = (int)fy0, x0 = (int)fx0;
        int y1 = y0 + 1, x1 = x0 + 1;
        float wy1 = py - fy0, wx1 = pxx - fx0;
        float wy0 = 1.f - wy1, wx0 = 1.f - wx1;
        bool vy0 = (unsigned)y0 < 64u, vy1 = (unsigned)y1 < 64u;
        bool vx0 = (unsigned)x0 < 64u, vx1 = (unsigned)x1 < 64u;
        float w00 = (vy0 && vx0) ? wy0 * wx0 : 0.f;
        float w01 = (vy0 && vx1) ? wy0 * wx1 : 0.f;
        float w10 = (vy1 && vx0) ? wy1 * wx0 : 0.f;
        float w11 = (vy1 && vx1) ? wy1 * wx1 : 0.f;
        int yc0 = min(max(y0, 0), 63), yc1 = min(max(y1, 0), 63);
        int xc0 = min(max(x0, 0), 63), xc1 = min(max(x1, 0), 63);
        int gb = b << 12;
        wts[kpt][px] = make_float4(w00, w01, w10, w11);
        idxs[kpt][px] = make_int4(gb + (yc0 << 6) + xc0, gb + (yc0 << 6) + xc1,
                                  gb + (yc1 << 6) + xc0, gb + (yc1 << 6) + xc1);
    }
    __syncthreads();

    int wid = threadIdx.x >> 5, lane = threadIdx.x & 31;
    int c8 = lane * 8;
    unsigned short* colbase = reinterpret_cast<unsigned short*>(g_colb);

    for (int task = wid; task < 288; task += 8) {
        int kpt = task >> 5, px = task & 31;
        float4 wv = wts[kpt][px];
        int4 iv = idxs[kpt][px];
        uint4 u00 = *reinterpret_cast<const uint4*>(g_xpm + (size_t)iv.x * CC + c8);
        uint4 u01 = *reinterpret_cast<const uint4*>(g_xpm + (size_t)iv.y * CC + c8);
        uint4 u10 = *reinterpret_cast<const uint4*>(g_xpm + (size_t)iv.z * CC + c8);
        uint4 u11 = *reinterpret_cast<const uint4*>(g_xpm + (size_t)iv.w * CC + c8);
        const __half2* h00 = reinterpret_cast<const __half2*>(&u00);
        const __half2* h01 = reinterpret_cast<const __half2*>(&u01);
        const __half2* h10 = reinterpret_cast<const __half2*>(&u10);
        const __half2* h11 = reinterpret_cast<const __half2*>(&u11);
        __align__(16) unsigned short his[8];
#pragma unroll
        for (int q = 0; q < 4; q++) {
            float2 a = __half22float2(h00[q]);
            float2 bq = __half22float2(h01[q]);
            float2 c = __half22float2(h10[q]);
            float2 d = __half22float2(h11[q]);
            float v0 = wv.x * a.x + wv.y * bq.x + wv.z * c.x + wv.w * d.x;
            float v1 = wv.x * a.y + wv.y * bq.y + wv.z * c.y + wv.w * d.y;
            his[q * 2] = f2h(v0);
            his[q * 2 + 1] = f2h(v1);
        }
        unsigned short* row = colbase + (size_t)(n0 + px) * COLROW + kpt * 256;
        *reinterpret_cast<uint4*>(row + c8) = *reinterpret_cast<const uint4*>(his);
    }
}

// ---------------- bn finalize: sums -> scale/shift (1 block) -----------------
__global__ void k_bnfin(const float* __restrict__ gamma, const float* __restrict__ beta,
                        int sel) {
    int ch = threadIdx.x;
    float s = sel ? g_bnsum2[ch] : g_bnsum1[ch];
    float q = sel ? g_bnsq2[ch] : g_bnsq1[ch];
    float mean = s * (1.f / FNN);
    float var = fmaxf(q * (1.f / FNN) - mean * mean, 0.f);
    float inv = rsqrtf(var + EPSB);
    float sc = inv * gamma[ch];
    if (sel) { g_scale2[ch] = sc; g_shift2[ch] = beta[ch] - mean * sc; }
    else     { g_scale1[ch] = sc; g_shift1[ch] = beta[ch] - mean * sc; }
}

// ---------------- convert1: out1 -> pixel-major fp16 (BN1+ReLU) -------------
__global__ __launch_bounds__(256)
void k_convert1() {
    __shared__ float t[64][33];
    __shared__ float sS[256], sH[256];
    int px0 = blockIdx.x * 32;
    int tid = threadIdx.x;
    int lane = tid & 31, wy = tid >> 5;
    for (int i = tid; i < 256; i += 256) { sS[i] = g_scale1[i]; sH[i] = g_shift1[i]; }
    __syncthreads();

    unsigned short* ob = reinterpret_cast<unsigned short*>(g_out1b);
    for (int c0 = 0; c0 < 256; c0 += 64) {
#pragma unroll
        for (int j = 0; j < 8; j++) {
            int cc = wy * 8 + j;
            t[cc][lane] = g_out1[(size_t)(c0 + cc) * NN + px0 + lane];
        }
        __syncthreads();
        int px = tid >> 3, g = tid & 7;
        __align__(16) unsigned short his[8];
#pragma unroll
        for (int j = 0; j < 8; j++) {
            int cc = g * 8 + j;
            float v = fmaxf(fmaf(t[cc][px], sS[c0 + cc], sH[c0 + cc]), 0.f);
            his[j] = f2h(v);
        }
        unsigned short* row = ob + (size_t)(px0 + px) * O1ROW;
        *reinterpret_cast<uint4*>(row + c0 + g * 8) = *reinterpret_cast<const uint4*>(his);
        __syncthreads();
    }
}

// ---------------- mma.sync fp16 GEMM, 128x256, K=2304, fused BN stats -------
__global__ __launch_bounds__(256, 1)
void k_gemm_mma(int wsel, const float* __restrict__ bias, int outsel, int implicitB) {
    extern __shared__ char smem[];
    uint32_t sb = smem_u32(smem);
    int tid = threadIdx.x;
    int m0 = blockIdx.x * 128;
    int n0 = blockIdx.y * 256;

    const __half* Ag = wsel ? g_wA2 : g_wA1;
    float* Cg = outsel ? g_out2 : g_out1;
    float* bns = outsel ? g_bnsum2 : g_bnsum1;
    float* bnq = outsel ? g_bnsq2 : g_bnsq1;
    const char* Abase = reinterpret_cast<const char*>(Ag) + (size_t)m0 * (CKK * 2);
    const char* Bbase = reinterpret_cast<const char*>(g_colb) + (size_t)n0 * (COLROW * 2);
    const char* Obase = reinterpret_cast<const char*>(g_out1b);

    auto load_stage = [&](int kc, int s) {
        uint32_t st = sb + s * STAGE_SZ;
        size_t kb = (size_t)kc * 128;
        int kpt = kc >> 2, part = kc & 3;
        uint32_t srcoff = ((uint32_t)part) << 7;
        if (!implicitB) {
#pragma unroll
            for (int i = 0; i < 12; i++) {
                int idx = tid + i * 256;
                if (idx < 1024) {
                    int r = idx >> 3, c = idx & 7;
                    uint32_t off = SWZ128(r * 128 + c * 16);
                    CP_ASYNC16(st + off, Abase + (size_t)r * (CKK * 2) + kb + c * 16);
                } else {
                    int j = idx - 1024;
                    int r = j >> 3, c = j & 7;
                    uint32_t off = SWZ128(r * 128 + c * 16);
                    CP_ASYNC16(st + 16384 + off,
                               Bbase + (size_t)r * (COLROW * 2) + kpt * 512 + srcoff + c * 16);
                }
            }
        } else {
            int ki = kpt / 3, kj = kpt - 3 * ki;
            int dn = (ki - 1) * 64 + (kj - 1);
#pragma unroll
            for (int i = 0; i < 12; i++) {
                int idx = tid + i * 256;
                if (idx < 1024) {
                    int r = idx >> 3, c = idx & 7;
                    uint32_t off = SWZ128(r * 128 + c * 16);
                    CP_ASYNC16(st + off, Abase + (size_t)r * (CKK * 2) + kb + c * 16);
                } else {
                    int j = idx - 1024;
                    int r = j >> 3, c = j & 7;
                    int n = n0 + r;
                    int h = (n >> 6) & 63, w = n & 63;
                    int y = h - 1 + ki, xw = w - 1 + kj;
                    bool valid = ((unsigned)y < 64u) && ((unsigned)xw < 64u);
                    int np = valid ? n + dn : 0;
                    uint32_t sz = valid ? 16u : 0u;
                    uint32_t off = SWZ128(r * 128 + c * 16);
                    CP_ASYNC16Z(st + 16384 + off,
                                Obase + (size_t)np * 512 + srcoff + c * 16, sz);
                }
            }
        }
        CP_COMMIT();
    };

    int lane = tid & 31, w = tid >> 5;
    int wm = w >> 1, wn = w & 1;
    int mW = wm * 32, nW = wn * 128;
    int gq = lane >> 3, rr = lane & 7;
    int rowin = (gq & 1) * 8 + rr;
    int kboff = (gq >> 1) * 16;

    float acc[2][16][4];
#pragma unroll
    for (int mt = 0; mt < 2; mt++)
#pragma unroll
        for (int j = 0; j < 16; j++)
#pragma unroll
            for (int q = 0; q < 4; q++) acc[mt][j][q] = 0.f;

    uint32_t aOff[2], aXor[2], bOff[8], bXor[8];
#pragma unroll
    for (int mt = 0; mt < 2; mt++) {
        int row = mW + mt * 16 + rowin;
        aOff[mt] = row * 128;
        aXor[mt] = (row & 7) << 4;
    }
#pragma unroll
    for (int nt = 0; nt < 8; nt++) {
        int row = nW + nt * 16 + rowin;
        bOff[nt] = row * 128;
        bXor[nt] = (row & 7) << 4;
    }

    load_stage(0, 0);
    load_stage(1, 1);
    load_stage(2, 2);

    for (int k = 0; k < NUM_KCH; k++) {
        int s = k % NSTAGE;
        uint32_t stA = sb + s * STAGE_SZ;
        uint32_t stB = stA + 16384;
        CP_WAIT2();
        __syncthreads();

#pragma unroll
        for (int ks = 0; ks < 4; ks++) {
            uint32_t kb = ks * 32 + kboff;
            uint32_t af[2][4];
#pragma unroll
            for (int mt = 0; mt < 2; mt++)
                LDSM4(af[mt][0], af[mt][1], af[mt][2], af[mt][3],
                      stA + aOff[mt] + (kb ^ aXor[mt]));
#pragma unroll
            for (int nt = 0; nt < 8; nt++) {
                uint32_t bf0, bf1, bf2, bf3;
                LDSM4(bf0, bf1, bf2, bf3, stB + bOff[nt] + (kb ^ bXor[nt]));
#pragma unroll
                for (int mt = 0; mt < 2; mt++) {
                    MMA16816F16(acc[mt][nt * 2], af[mt][0], af[mt][1], af[mt][2], af[mt][3],
                                bf0, bf2);
                    MMA16816F16(acc[mt][nt * 2 + 1], af[mt][0], af[mt][1], af[mt][2], af[mt][3],
                                bf1, bf3);
                }
            }
        }
        __syncthreads();
        if (k + 3 < NUM_KCH) load_stage(k + 3, s);
        else CP_COMMIT();
    }

    int qr = lane >> 2;
    int qc = (lane & 3) * 2;
#pragma unroll
    for (int mt = 0; mt < 2; mt++) {
        int row0 = m0 + mW + mt * 16 + qr;
        float bv0 = bias ? bias[row0] : 0.f;
        float bv1 = bias ? bias[row0 + 8] : 0.f;
        float s0 = 0.f, q0 = 0.f, s1 = 0.f, q1 = 0.f;
#pragma unroll
        for (int j = 0; j < 16; j++) {
            int col = n0 + nW + j * 8 + qc;
            float2 v0 = make_float2(acc[mt][j][0] + bv0, acc[mt][j][1] + bv0);
            float2 v1 = make_float2(acc[mt][j][2] + bv1, acc[mt][j][3] + bv1);
            s0 += v0.x + v0.y;
            q0 = fmaf(v0.x, v0.x, fmaf(v0.y, v0.y, q0));
            s1 += v1.x + v1.y;
            q1 = fmaf(v1.x, v1.x, fmaf(v1.y, v1.y, q1));
            *reinterpret_cast<float2*>(Cg + (size_t)row0 * NN + col) = v0;
            *reinterpret_cast<float2*>(Cg + (size_t)(row0 + 8) * NN + col) = v1;
        }
        s0 += __shfl_xor_sync(0xffffffff, s0, 1);
        s0 += __shfl_xor_sync(0xffffffff, s0, 2);
        q0 += __shfl_xor_sync(0xffffffff, q0, 1);
        q0 += __shfl_xor_sync(0xffffffff, q0, 2);
        s1 += __shfl_xor_sync(0xffffffff, s1, 1);
        s1 += __shfl_xor_sync(0xffffffff, s1, 2);
        q1 += __shfl_xor_sync(0xffffffff, q1, 1);
        q1 += __shfl_xor_sync(0xffffffff, q1, 2);
        if ((lane & 3) == 0) {
            atomicAdd(&bns[row0], s0);
            atomicAdd(&bnq[row0], q0);
            atomicAdd(&bns[row0 + 8], s1);
            atomicAdd(&bnq[row0 + 8], q1);
        }
    }
}

// ---------------- final: relu(bn2(out2) + x) in NCHW ------------------------
__global__ __launch_bounds__(256)
void k_final(const float* __restrict__ x, float* __restrict__ out) {
    int i = blockIdx.x * 256 + threadIdx.x;
    int hw = i & 4095;
    int o = (i >> 12) & 255;
    int b = i >> 20;
    float v = fmaf(g_out2[(size_t)o * NN + b * HWW + hw], g_scale2[o], g_shift2[o]) + x[i];
    out[i] = fmaxf(v, 0.f);
}

// ---------------- launch -----------------------------------------------------
extern "C" void kernel_launch(void* const* d_in, const int* in_sizes, int n_in,
                              void* d_out, int out_size) {
    const float* x     = (const float*)d_in[0];
    const float* off_w = (const float*)d_in[1];
    const float* off_b = (const float*)d_in[2];
    const float* dw    = (const float*)d_in[3];
    const float* db    = (const float*)d_in[4];
    const float* bn1_g = (const float*)d_in[5];
    const float* bn1_b = (const float*)d_in[6];
    const float* w2    = (const float*)d_in[7];
    const float* bn2_g = (const float*)d_in[8];
    const float* bn2_b = (const float*)d_in[9];
    float* out = (float*)d_out;

    cudaFuncSetAttribute(k_gemm_mma, cudaFuncAttributeMaxDynamicSharedMemorySize, GEMM_SMEM);
    cudaFuncSetAttribute(k_gemm_off, cudaFuncAttributeMaxDynamicSharedMemorySize, OFF_SMEM);

    k_zero<<<(32 * CKK + 255) / 256, 256>>>();
    k_transpose_x<<<dim3(NN / 32, 4), 256>>>(x);
    k_wprep<<<dim3((OO * CKK + 255) / 256, 3), 256>>>(dw, w2, off_w);
    k_gemm_off<<<128, 256, OFF_SMEM>>>(off_b);
    k_im2col_deform<<<NN / 32, 256>>>();
    k_gemm_mma<<<dim3(2, 64), 256, GEMM_SMEM>>>(0, db, 0, 0);
    k_bnfin<<<1, 256>>>(bn1_g, bn1_b, 0);
    k_convert1<<<NN / 32, 256>>>();
    k_gemm_mma<<<dim3(2, 64), 256, GEMM_SMEM>>>(1, nullptr, 1, 1);
    k_bnfin<<<1, 256>>>(bn2_g, bn2_b, 1);
    k_final<<<(BB * OO * HWW + 255) / 256, 256>>>(x, out);
}

// round 15
// speedup vs baseline: 5.8791x; 1.0010x over previous
#include <cuda_runtime.h>
#include <cuda_fp16.h>
#include <cstdint>

#define BB 4
#define CC 256
#define OO 256
#define HWW 4096
#define NN 16384          // BB*HWW
#define CKK 2304          // CC*9 — plain fp16 K
#define EPSB 1e-5f
#define FNN 16384.0f

#define NSTAGE 3
#define STAGE_SZ 49152      // A 16KB + B 32KB per stage (main GEMM)
#define GEMM_SMEM (NSTAGE * STAGE_SZ)
#define NUM_KCH 36          // CKK*2 bytes / 128B per chunk

#define OFF_STAGE 12288     // A 4KB (32 rows) + B 8KB (64 rows)
#define OFF_SMEM (NSTAGE * OFF_STAGE)

#define COLROW 2304         // per pixel: 9 kpt x 256 fp16
#define O1ROW 256           // per pixel: 256 fp16

// ---------------- scratch (device globals; no allocs allowed) ----------------
__device__ float g_offset[BB * 18 * HWW];                       // 4.7 MB
__device__ __half g_xpm[(size_t)NN * CC];                       // 32 MB NHWC fp16 x
__device__ __half g_colb[(size_t)NN * COLROW];                  // 75.5 MB
__device__ __half g_wA1[(size_t)OO * CKK];                      // 1.2 MB [m][k]
__device__ __half g_wA2[(size_t)OO * CKK];
__device__ __half g_wOff[32 * CKK];                             // 147 KB (18 pad 32)
__device__ float g_out1[(size_t)OO * NN];                       // 16.8 MB [o][n]
__device__ float g_out2[(size_t)OO * NN];
__device__ __half g_out1b[(size_t)NN * O1ROW];                  // 8.4 MB
__device__ float g_scale1[OO], g_shift1[OO], g_scale2[OO], g_shift2[OO];
__device__ float g_bnsum1[OO], g_bnsq1[OO], g_bnsum2[OO], g_bnsq2[OO];

// ---------------- helpers ----------------------------------------------------
__device__ __forceinline__ uint32_t smem_u32(const void* p) {
    uint32_t a;
    asm("{ .reg .u64 t; cvta.to.shared.u64 t, %1; cvt.u32.u64 %0, t; }" : "=r"(a) : "l"(p));
    return a;
}
#define SWZ128(o) ((o) ^ (((o) >> 3) & 0x70))
#define CP_ASYNC16(dst, src) \
    asm volatile("cp.async.cg.shared.global [%0], [%1], 16;" :: "r"(dst), "l"(src))
#define CP_ASYNC16Z(dst, src, sz) \
    asm volatile("cp.async.cg.shared.global [%0], [%1], 16, %2;" :: "r"(dst), "l"(src), "r"(sz))
#define CP_COMMIT() asm volatile("cp.async.commit_group;" ::: "memory")
#define CP_WAIT2()  asm volatile("cp.async.wait_group 2;" ::: "memory")

#define LDSM4(r0, r1, r2, r3, addr) \
    asm volatile("ldmatrix.sync.aligned.m8n8.x4.shared.b16 {%0,%1,%2,%3}, [%4];" \
                 : "=r"(r0), "=r"(r1), "=r"(r2), "=r"(r3) : "r"(addr))

#define MMA16816F16(d, a0, a1, a2, a3, b0, b1) \
    asm volatile("mma.sync.aligned.m16n8k16.row.col.f32.f16.f16.f32 " \
                 "{%0,%1,%2,%3},{%4,%5,%6,%7},{%8,%9},{%0,%1,%2,%3};" \
                 : "+f"((d)[0]), "+f"((d)[1]), "+f"((d)[2]), "+f"((d)[3]) \
                 : "r"(a0), "r"(a1), "r"(a2), "r"(a3), "r"(b0), "r"(b1))

__device__ __forceinline__ unsigned short f2h(float v) {
    __half h = __float2half_rn(v);
    return *reinterpret_cast<unsigned short*>(&h);
}

// ---------------- zero: bn sums (1 block) ------------------------------------
__global__ void k_zero() {
    int i = threadIdx.x;
    g_bnsum1[i] = 0.f; g_bnsq1[i] = 0.f; g_bnsum2[i] = 0.f; g_bnsq2[i] = 0.f;
}

// ---------------- transpose x: NCHW fp32 -> NHWC fp16 (g_xpm) ---------------
__global__ __launch_bounds__(256)
void k_transpose_x(const float* __restrict__ x) {
    __shared__ float t[64][33];
    int n0 = blockIdx.x * 32;
    int c0 = blockIdx.y * 64;
    int b = n0 >> 12;
    int hw0 = n0 & 4095;
    int lane = threadIdx.x & 31, wy = threadIdx.x >> 5;
#pragma unroll
    for (int j = 0; j < 8; j++) {
        int cc = wy * 8 + j;
        t[cc][lane] = x[((size_t)b * CC + c0 + cc) * HWW + hw0 + lane];
    }
    __syncthreads();
#pragma unroll
    for (int j = 0; j < 4; j++) {
        int px = wy * 4 + j;
        __half2 h = __floats2half2_rn(t[lane * 2][px], t[lane * 2 + 1][px]);
        *reinterpret_cast<__half2*>(g_xpm + (size_t)(n0 + px) * CC + c0 + lane * 2) = h;
    }
}

// ---------------- weight prep: fp32 -> fp16 [m][kpt*256+c]; y: 0=dw 1=w2 2=off
__global__ __launch_bounds__(256)
void k_wprep(const float* __restrict__ dw, const float* __restrict__ w2,
             const float* __restrict__ off_w) {
    int idx = blockIdx.x * 256 + threadIdx.x;
    int lim = (blockIdx.y == 2) ? 32 * CKK : OO * CKK;
    if (idx >= lim) return;
    int m = idx / CKK;
    int ck = idx - m * CKK;
    int c = ck / 9, kpt = ck - c * 9;
    const float* w = (blockIdx.y == 0) ? dw : (blockIdx.y == 1 ? w2 : off_w);
    __half* dst = (blockIdx.y == 0) ? g_wA1 : (blockIdx.y == 1 ? g_wA2 : g_wOff);
    unsigned short hv = (blockIdx.y == 2 && m >= 18) ? 0 : f2h(w[idx]);
    reinterpret_cast<unsigned short*>(dst)[(size_t)m * CKK + kpt * 256 + c] = hv;
}

// ---------------- offset conv as implicit fp16 GEMM: [18(32)x2304]@[2304xNN]
// grid 256: n-tile 64 pixels. 8 warps 2m x 4n, warp tile 16x16.
__global__ __launch_bounds__(256, 3)
void k_gemm_off(const float* __restrict__ off_b) {
    extern __shared__ char smem[];
    uint32_t sb = smem_u32(smem);
    int tid = threadIdx.x;
    int n0 = blockIdx.x * 64;
    int b = n0 >> 12;

    const char* Abase = reinterpret_cast<const char*>(g_wOff);
    const char* Xbase = reinterpret_cast<const char*>(g_xpm);

    auto load_stage = [&](int kc, int s) {
        uint32_t st = sb + s * OFF_STAGE;
        int kpt = kc >> 2, part = kc & 3;
        uint32_t srcoff = ((uint32_t)part) << 7;
        int ki = kpt / 3, kj = kpt - 3 * ki;
        int dn = (ki - 1) * 128 + (kj - 1) * 2;   // dil=2 shifts
#pragma unroll
        for (int i = 0; i < 3; i++) {
            int idx = tid + i * 256;
            if (idx < 256) {
                int r = idx >> 3, c = idx & 7;
                uint32_t off = SWZ128(r * 128 + c * 16);
                CP_ASYNC16(st + off, Abase + (size_t)r * (CKK * 2) + (size_t)kc * 128 + c * 16);
            } else {
                int j = idx - 256;
                int r = j >> 3, c = j & 7;
                int n = n0 + r;
                int h = (n >> 6) & 63, w = n & 63;
                int y = h - 2 + 2 * ki, xw = w - 2 + 2 * kj;
                bool valid = ((unsigned)y < 64u) && ((unsigned)xw < 64u);
                int np = valid ? n + dn : 0;
                uint32_t sz = valid ? 16u : 0u;
                uint32_t off = SWZ128(r * 128 + c * 16);
                CP_ASYNC16Z(st + 4096 + off, Xbase + (size_t)np * 512 + srcoff + c * 16, sz);
            }
        }
        CP_COMMIT();
    };

    int lane = tid & 31, w = tid >> 5;
    int wm = w >> 2, wn = w & 3;      // 2m x 4n warp grid
    int mW = wm * 16, nW = wn * 16;
    int gq = lane >> 3, rr = lane & 7;
    int rowin = (gq & 1) * 8 + rr;
    int kboff = (gq >> 1) * 16;

    float acc[2][4];
#pragma unroll
    for (int j = 0; j < 2; j++)
#pragma unroll
        for (int q = 0; q < 4; q++) acc[j][q] = 0.f;

    uint32_t aOff = (mW + rowin) * 128;
    uint32_t aXor = ((mW + rowin) & 7) << 4;
    uint32_t bOff = (nW + rowin) * 128;
    uint32_t bXor = ((nW + rowin) & 7) << 4;

    load_stage(0, 0);
    load_stage(1, 1);
    load_stage(2, 2);

    for (int k = 0; k < NUM_KCH; k++) {
        int s = k % NSTAGE;
        uint32_t stA = sb + s * OFF_STAGE;
        uint32_t stB = stA + 4096;
        CP_WAIT2();
        __syncthreads();

#pragma unroll
        for (int ks = 0; ks < 4; ks++) {
            uint32_t kb = ks * 32 + kboff;
            uint32_t a0, a1, a2, a3;
            LDSM4(a0, a1, a2, a3, stA + aOff + (kb ^ aXor));
            uint32_t bf0, bf1, bf2, bf3;
            LDSM4(bf0, bf1, bf2, bf3, stB + bOff + (kb ^ bXor));
            MMA16816F16(acc[0], a0, a1, a2, a3, bf0, bf2);
            MMA16816F16(acc[1], a0, a1, a2, a3, bf1, bf3);
        }
        __syncthreads();
        if (k + 3 < NUM_KCH) load_stage(k + 3, s);
        else CP_COMMIT();
    }

    // epilogue: rows < 18 -> g_offset[(b*18+row)*HWW + hw] (+ off_b)
    int qr = lane >> 2;
    int qc = (lane & 3) * 2;
    int hw0 = (n0 & 4095) + nW + qc;
    int rowA = mW + qr;
    int rowB = rowA + 8;
#pragma unroll
    for (int j = 0; j < 2; j++) {
        int hw = hw0 + j * 8;
        if (rowA < 18) {
            float bv = off_b[rowA];
            float2 v = make_float2(acc[j][0] + bv, acc[j][1] + bv);
            *reinterpret_cast<float2*>(g_offset + (size_t)(b * 18 + rowA) * HWW + hw) = v;
        }
        if (rowB < 18) {
            float bv = off_b[rowB];
            float2 v = make_float2(acc[j][2] + bv, acc[j][3] + bv);
            *reinterpret_cast<float2*>(g_offset + (size_t)(b * 18 + rowB) * HWW + hw) = v;
        }
    }
}

// ---------------- deformable im2col: NHWC fp16 gather -----------------------
__global__ __launch_bounds__(256)
void k_im2col_deform() {
    __shared__ float4 wts[9][32];
    __shared__ int4 idxs[9][32];

    int n0 = blockIdx.x * 32;
    int b = n0 >> 12;

    for (int t = threadIdx.x; t < 288; t += 256) {
        int kpt = t >> 5, px = t & 31;
        int n = n0 + px;
        int hw = n & 4095;
        int h = hw >> 6, w = hw & 63;
        int ki = kpt / 3, kj = kpt - ki * 3;
        float offy = g_offset[((size_t)b * 18 + 2 * kpt) * HWW + hw];
        float offx = g_offset[((size_t)b * 18 + 2 * kpt + 1) * HWW + hw];
        float py = (float)(h - 2 + 2 * ki) + offy;
        float pxx = (float)(w - 2 + 2 * kj) + offx;
        float fy0 = floorf(py), fx0 = floorf(pxx);
        int y0 = (int)fy0, x0 = (int)fx0;
        int y1 = y0 + 1, x1 = x0 + 1;
        float wy1 = py - fy0, wx1 = pxx - fx0;
        float wy0 = 1.f - wy1, wx0 = 1.f - wx1;
        bool vy0 = (unsigned)y0 < 64u, vy1 = (unsigned)y1 < 64u;
        bool vx0 = (unsigned)x0 < 64u, vx1 = (unsigned)x1 < 64u;
        float w00 = (vy0 && vx0) ? wy0 * wx0 : 0.f;
        float w01 = (vy0 && vx1) ? wy0 * wx1 : 0.f;
        float w10 = (vy1 && vx0) ? wy1 * wx0 : 0.f;
        float w11 = (vy1 && vx1) ? wy1 * wx1 : 0.f;
        int yc0 = min(max(y0, 0), 63), yc1 = min(max(y1, 0), 63);
        int xc0 = min(max(x0, 0), 63), xc1 = min(max(x1, 0), 63);
        int gb = b << 12;
        wts[kpt][px] = make_float4(w00, w01, w10, w11);
        idxs[kpt][px] = make_int4(gb + (yc0 << 6) + xc0, gb + (yc0 << 6) + xc1,
                                  gb + (yc1 << 6) + xc0, gb + (yc1 << 6) + xc1);
    }
    __syncthreads();

    int wid = threadIdx.x >> 5, lane = threadIdx.x & 31;
    int c8 = lane * 8;
    unsigned short* colbase = reinterpret_cast<unsigned short*>(g_colb);

    for (int task = wid; task < 288; task += 8) {
        int kpt = task >> 5, px = task & 31;
        float4 wv = wts[kpt][px];
        int4 iv = idxs[kpt][px];
        uint4 u00 = *reinterpret_cast<const uint4*>(g_xpm + (size_t)iv.x * CC + c8);
        uint4 u01 = *reinterpret_cast<const uint4*>(g_xpm + (size_t)iv.y * CC + c8);
        uint4 u10 = *reinterpret_cast<const uint4*>(g_xpm + (size_t)iv.z * CC + c8);
        uint4 u11 = *reinterpret_cast<const uint4*>(g_xpm + (size_t)iv.w * CC + c8);
        const __half2* h00 = reinterpret_cast<const __half2*>(&u00);
        const __half2* h01 = reinterpret_cast<const __half2*>(&u01);
        const __half2* h10 = reinterpret_cast<const __half2*>(&u10);
        const __half2* h11 = reinterpret_cast<const __half2*>(&u11);
        __align__(16) unsigned short his[8];
#pragma unroll
        for (int q = 0; q < 4; q++) {
            float2 a = __half22float2(h00[q]);
            float2 bq = __half22float2(h01[q]);
            float2 c = __half22float2(h10[q]);
            float2 d = __half22float2(h11[q]);
            float v0 = wv.x * a.x + wv.y * bq.x + wv.z * c.x + wv.w * d.x;
            float v1 = wv.x * a.y + wv.y * bq.y + wv.z * c.y + wv.w * d.y;
            his[q * 2] = f2h(v0);
            his[q * 2 + 1] = f2h(v1);
        }
        unsigned short* row = colbase + (size_t)(n0 + px) * COLROW + kpt * 256;
        *reinterpret_cast<uint4*>(row + c8) = *reinterpret_cast<const uint4*>(his);
    }
}

// ---------------- bn finalize: sums -> scale/shift (1 block) -----------------
__global__ void k_bnfin(const float* __restrict__ gamma, const float* __restrict__ beta,
                        int sel) {
    int ch = threadIdx.x;
    float s = sel ? g_bnsum2[ch] : g_bnsum1[ch];
    float q = sel ? g_bnsq2[ch] : g_bnsq1[ch];
    float mean = s * (1.f / FNN);
    float var = fmaxf(q * (1.f / FNN) - mean * mean, 0.f);
    float inv = rsqrtf(var + EPSB);
    float sc = inv * gamma[ch];
    if (sel) { g_scale2[ch] = sc; g_shift2[ch] = beta[ch] - mean * sc; }
    else     { g_scale1[ch] = sc; g_shift1[ch] = beta[ch] - mean * sc; }
}

// ---------------- convert1: out1 -> pixel-major fp16 (BN1+ReLU) -------------
__global__ __launch_bounds__(256)
void k_convert1() {
    __shared__ float t[64][33];
    __shared__ float sS[256], sH[256];
    int px0 = blockIdx.x * 32;
    int tid = threadIdx.x;
    int lane = tid & 31, wy = tid >> 5;
    for (int i = tid; i < 256; i += 256) { sS[i] = g_scale1[i]; sH[i] = g_shift1[i]; }
    __syncthreads();

    unsigned short* ob = reinterpret_cast<unsigned short*>(g_out1b);
    for (int c0 = 0; c0 < 256; c0 += 64) {
#pragma unroll
        for (int j = 0; j < 8; j++) {
            int cc = wy * 8 + j;
            t[cc][lane] = g_out1[(size_t)(c0 + cc) * NN + px0 + lane];
        }
        __syncthreads();
        int px = tid >> 3, g = tid & 7;
        __align__(16) unsigned short his[8];
#pragma unroll
        for (int j = 0; j < 8; j++) {
            int cc = g * 8 + j;
            float v = fmaxf(fmaf(t[cc][px], sS[c0 + cc], sH[c0 + cc]), 0.f);
            his[j] = f2h(v);
        }
        unsigned short* row = ob + (size_t)(px0 + px) * O1ROW;
        *reinterpret_cast<uint4*>(row + c0 + g * 8) = *reinterpret_cast<const uint4*>(his);
        __syncthreads();
    }
}

// ---------------- mma.sync fp16 GEMM, 128x256, K=2304, fused BN stats -------
__global__ __launch_bounds__(256, 1)
void k_gemm_mma(int wsel, const float* __restrict__ bias, int outsel, int implicitB) {
    extern __shared__ char smem[];
    uint32_t sb = smem_u32(smem);
    int tid = threadIdx.x;
    int m0 = blockIdx.x * 128;
    int n0 = blockIdx.y * 256;

    const __half* Ag = wsel ? g_wA2 : g_wA1;
    float* Cg = outsel ? g_out2 : g_out1;
    float* bns = outsel ? g_bnsum2 : g_bnsum1;
    float* bnq = outsel ? g_bnsq2 : g_bnsq1;
    const char* Abase = reinterpret_cast<const char*>(Ag) + (size_t)m0 * (CKK * 2);
    const char* Bbase = reinterpret_cast<const char*>(g_colb) + (size_t)n0 * (COLROW * 2);
    const char* Obase = reinterpret_cast<const char*>(g_out1b);

    auto load_stage = [&](int kc, int s) {
        uint32_t st = sb + s * STAGE_SZ;
        size_t kb = (size_t)kc * 128;
        int kpt = kc >> 2, part = kc & 3;
        uint32_t srcoff = ((uint32_t)part) << 7;
        if (!implicitB) {
#pragma unroll
            for (int i = 0; i < 12; i++) {
                int idx = tid + i * 256;
                if (idx < 1024) {
                    int r = idx >> 3, c = idx & 7;
                    uint32_t off = SWZ128(r * 128 + c * 16);
                    CP_ASYNC16(st + off, Abase + (size_t)r * (CKK * 2) + kb + c * 16);
                } else {
                    int j = idx - 1024;
                    int r = j >> 3, c = j & 7;
                    uint32_t off = SWZ128(r * 128 + c * 16);
                    CP_ASYNC16(st + 16384 + off,
                               Bbase + (size_t)r * (COLROW * 2) + kpt * 512 + srcoff + c * 16);
                }
            }
        } else {
            int ki = kpt / 3, kj = kpt - 3 * ki;
            int dn = (ki - 1) * 64 + (kj - 1);
#pragma unroll
            for (int i = 0; i < 12; i++) {
                int idx = tid + i * 256;
                if (idx < 1024) {
                    int r = idx >> 3, c = idx & 7;
                    uint32_t off = SWZ128(r * 128 + c * 16);
                    CP_ASYNC16(st + off, Abase + (size_t)r * (CKK * 2) + kb + c * 16);
                } else {
                    int j = idx - 1024;
                    int r = j >> 3, c = j & 7;
                    int n = n0 + r;
                    int h = (n >> 6) & 63, w = n & 63;
                    int y = h - 1 + ki, xw = w - 1 + kj;
                    bool valid = ((unsigned)y < 64u) && ((unsigned)xw < 64u);
                    int np = valid ? n + dn : 0;
                    uint32_t sz = valid ? 16u : 0u;
                    uint32_t off = SWZ128(r * 128 + c * 16);
                    CP_ASYNC16Z(st + 16384 + off,
                                Obase + (size_t)np * 512 + srcoff + c * 16, sz);
                }
            }
        }
        CP_COMMIT();
    };

    int lane = tid & 31, w = tid >> 5;
    int wm = w >> 1, wn = w & 1;
    int mW = wm * 32, nW = wn * 128;
    int gq = lane >> 3, rr = lane & 7;
    int rowin = (gq & 1) * 8 + rr;
    int kboff = (gq >> 1) * 16;

    float acc[2][16][4];
#pragma unroll
    for (int mt = 0; mt < 2; mt++)
#pragma unroll
        for (int j = 0; j < 16; j++)
#pragma unroll
            for (int q = 0; q < 4; q++) acc[mt][j][q] = 0.f;

    uint32_t aOff[2], aXor[2], bOff[8], bXor[8];
#pragma unroll
    for (int mt = 0; mt < 2; mt++) {
        int row = mW + mt * 16 + rowin;
        aOff[mt] = row * 128;
        aXor[mt] = (row & 7) << 4;
    }
#pragma unroll
    for (int nt = 0; nt < 8; nt++) {
        int row = nW + nt * 16 + rowin;
        bOff[nt] = row * 128;
        bXor[nt] = (row & 7) << 4;
    }

    load_stage(0, 0);
    load_stage(1, 1);
    load_stage(2, 2);

    for (int k = 0; k < NUM_KCH; k++) {
        int s = k % NSTAGE;
        uint32_t stA = sb + s * STAGE_SZ;
        uint32_t stB = stA + 16384;
        CP_WAIT2();
        __syncthreads();

#pragma unroll
        for (int ks = 0; ks < 4; ks++) {
            uint32_t kb = ks * 32 + kboff;
            uint32_t af[2][4];
#pragma unroll
            for (int mt = 0; mt < 2; mt++)
                LDSM4(af[mt][0], af[mt][1], af[mt][2], af[mt][3],
                      stA + aOff[mt] + (kb ^ aXor[mt]));
#pragma unroll
            for (int nt = 0; nt < 8; nt++) {
                uint32_t bf0, bf1, bf2, bf3;
                LDSM4(bf0, bf1, bf2, bf3, stB + bOff[nt] + (kb ^ bXor[nt]));
#pragma unroll
                for (int mt = 0; mt < 2; mt++) {
                    MMA16816F16(acc[mt][nt * 2], af[mt][0], af[mt][1], af[mt][2], af[mt][3],
                                bf0, bf2);
                    MMA16816F16(acc[mt][nt * 2 + 1], af[mt][0], af[mt][1], af[mt][2], af[mt][3],
                                bf1, bf3);
                }
            }
        }
        __syncthreads();
        if (k + 3 < NUM_KCH) load_stage(k + 3, s);
        else CP_COMMIT();
    }

    int qr = lane >> 2;
    int qc = (lane & 3) * 2;
#pragma unroll
    for (int mt = 0; mt < 2; mt++) {
        int row0 = m0 + mW + mt * 16 + qr;
        float bv0 = bias ? bias[row0] : 0.f;
        float bv1 = bias ? bias[row0 + 8] : 0.f;
        float s0 = 0.f, q0 = 0.f, s1 = 0.f, q1 = 0.f;
#pragma unroll
        for (int j = 0; j < 16; j++) {
            int col = n0 + nW + j * 8 + qc;
            float2 v0 = make_float2(acc[mt][j][0] + bv0, acc[mt][j][1] + bv0);
            float2 v1 = make_float2(acc[mt][j][2] + bv1, acc[mt][j][3] + bv1);
            s0 += v0.x + v0.y;
            q0 = fmaf(v0.x, v0.x, fmaf(v0.y, v0.y, q0));
            s1 += v1.x + v1.y;
            q1 = fmaf(v1.x, v1.x, fmaf(v1.y, v1.y, q1));
            *reinterpret_cast<float2*>(Cg + (size_t)row0 * NN + col) = v0;
            *reinterpret_cast<float2*>(Cg + (size_t)(row0 + 8) * NN + col) = v1;
        }
        s0 += __shfl_xor_sync(0xffffffff, s0, 1);
        s0 += __shfl_xor_sync(0xffffffff, s0, 2);
        q0 += __shfl_xor_sync(0xffffffff, q0, 1);
        q0 += __shfl_xor_sync(0xffffffff, q0, 2);
        s1 += __shfl_xor_sync(0xffffffff, s1, 1);
        s1 += __shfl_xor_sync(0xffffffff, s1, 2);
        q1 += __shfl_xor_sync(0xffffffff, q1, 1);
        q1 += __shfl_xor_sync(0xffffffff, q1, 2);
        if ((lane & 3) == 0) {
            atomicAdd(&bns[row0], s0);
            atomicAdd(&bnq[row0], q0);
            atomicAdd(&bns[row0 + 8], s1);
            atomicAdd(&bnq[row0 + 8], q1);
        }
    }
}

// ---------------- final: relu(bn2(out2) + x) in NCHW ------------------------
__global__ __launch_bounds__(256)
void k_final(const float* __restrict__ x, float* __restrict__ out) {
    int i = blockIdx.x * 256 + threadIdx.x;
    int hw = i & 4095;
    int o = (i >> 12) & 255;
    int b = i >> 20;
    float v = fmaf(g_out2[(size_t)o * NN + b * HWW + hw], g_scale2[o], g_shift2[o]) + x[i];
    out[i] = fmaxf(v, 0.f);
}

// ---------------- launch -----------------------------------------------------
extern "C" void kernel_launch(void* const* d_in, const int* in_sizes, int n_in,
                              void* d_out, int out_size) {
    const float* x     = (const float*)d_in[0];
    const float* off_w = (const float*)d_in[1];
    const float* off_b = (const float*)d_in[2];
    const float* dw    = (const float*)d_in[3];
    const float* db    = (const float*)d_in[4];
    const float* bn1_g = (const float*)d_in[5];
    const float* bn1_b = (const float*)d_in[6];
    const float* w2    = (const float*)d_in[7];
    const float* bn2_g = (const float*)d_in[8];
    const float* bn2_b = (const float*)d_in[9];
    float* out = (float*)d_out;

    cudaFuncSetAttribute(k_gemm_mma, cudaFuncAttributeMaxDynamicSharedMemorySize, GEMM_SMEM);
    cudaFuncSetAttribute(k_gemm_off, cudaFuncAttributeMaxDynamicSharedMemorySize, OFF_SMEM);

    k_zero<<<1, 256>>>();
    k_transpose_x<<<dim3(NN / 32, 4), 256>>>(x);
    k_wprep<<<dim3((OO * CKK + 255) / 256, 3), 256>>>(dw, w2, off_w);
    k_gemm_off<<<NN / 64, 256, OFF_SMEM>>>(off_b);
    k_im2col_deform<<<NN / 32, 256>>>();
    k_gemm_mma<<<dim3(2, 64), 256, GEMM_SMEM>>>(0, db, 0, 0);
    k_bnfin<<<1, 256>>>(bn1_g, bn1_b, 0);
    k_convert1<<<NN / 32, 256>>>();
    k_gemm_mma<<<dim3(2, 64), 256, GEMM_SMEM>>>(1, nullptr, 1, 1);
    k_bnfin<<<1, 256>>>(bn2_g, bn2_b, 1);
    k_final<<<(BB * OO * HWW + 255) / 256, 256>>>(x, out);
}